// round 2
// baseline (speedup 1.0000x reference)
#include <cuda_runtime.h>
#include <math.h>

// Problem constants
#define S_   1024
#define CA_  768
#define CS_  384
#define CZ_  64
#define H_   16
#define CH_  48     // head dim
#define C3_  144    // 3*CH

// ---------------------------------------------------------------------------
// Static scratch (device globals — no cudaMalloc allowed)
// ---------------------------------------------------------------------------
__device__ float g_b0[16 * 1024 * 1024];   // layer-0 bias/scores/P  (64 MiB)
__device__ float g_b1[16 * 1024 * 1024];   // layer-1 bias/scores/P  (64 MiB)
__device__ float g_shat[S_ * CS_];         // LN(s), no affine
__device__ float g_an[S_ * CA_];           // LN(a) per layer
__device__ float g_a2[S_ * CA_];           // adaln output (a2 / a3)
__device__ float g_q[S_ * CA_];
__device__ float g_kvg[S_ * 3 * CA_];
__device__ float g_o[S_ * CA_];            // sigmoid(g)*o, flat (B,S,CA) order
__device__ float g_amm[S_ * CA_];          // attn @ ao_w^T
__device__ float g_aout[S_ * CA_];         // gated attention output
__device__ float g_bb[S_ * 2 * CA_];       // silu(h1)*h2
__device__ float g_tmm[S_ * CA_];          // bb @ tr_b_w^T
__device__ float g_anew[S_ * CA_];         // a after layer 0
__device__ float g_wp[32 * 64];            // folded z-projection weights
__device__ float g_wpsum[32];
__device__ float g_wbias[32];

// ---------------------------------------------------------------------------
// Helpers
// ---------------------------------------------------------------------------
__device__ __forceinline__ float sigf(float x) { return 1.0f / (1.0f + expf(-x)); }

// block = 256 threads
__device__ __forceinline__ float blk_sum(float v, float* red) {
    int tid = threadIdx.x, lane = tid & 31;
    #pragma unroll
    for (int o = 16; o; o >>= 1) v += __shfl_xor_sync(0xffffffffu, v, o);
    if (lane == 0) red[tid >> 5] = v;
    __syncthreads();
    if (tid < 32) {
        float t = (tid < 8) ? red[tid] : 0.f;
        #pragma unroll
        for (int o = 4; o; o >>= 1) t += __shfl_xor_sync(0xffffffffu, t, o);
        if (tid == 0) red[0] = t;
    }
    __syncthreads();
    v = red[0];
    __syncthreads();
    return v;
}

// ---------------------------------------------------------------------------
// LayerNorm (no affine): one block per row, 256 threads, W <= 768
// ---------------------------------------------------------------------------
__global__ void __launch_bounds__(256) ln_kernel(const float* __restrict__ x,
                                                 float* __restrict__ y, int W) {
    __shared__ float red[32];
    long long row = blockIdx.x;
    const float* xr = x + row * W;
    float loc[3];
    int cnt = 0;
    float s = 0.f;
    for (int i = threadIdx.x; i < W; i += 256) { float v = xr[i]; loc[cnt++] = v; s += v; }
    float mean = blk_sum(s, red) / (float)W;
    float vs = 0.f;
    for (int j = 0; j < cnt; j++) { float d = loc[j] - mean; vs += d * d; }
    float var = blk_sum(vs, red) / (float)W;
    float rstd = rsqrtf(var + 1e-5f);
    float* yr = y + row * W;
    int j = 0;
    for (int i = threadIdx.x; i < W; i += 256) yr[i] = (loc[j++] - mean) * rstd;
}

// ---------------------------------------------------------------------------
// In-place softmax over rows of length 1024 (H*S rows)
// ---------------------------------------------------------------------------
__global__ void __launch_bounds__(256) softmax_kernel(float* __restrict__ p) {
    __shared__ float red[32];
    long long row = blockIdx.x;
    float* x = p + row * 1024;
    int tid = threadIdx.x, lane = tid & 31;
    float loc[4];
    float mx = -1e30f;
    #pragma unroll
    for (int j = 0; j < 4; j++) { loc[j] = x[tid + j * 256]; mx = fmaxf(mx, loc[j]); }
    #pragma unroll
    for (int o = 16; o; o >>= 1) mx = fmaxf(mx, __shfl_xor_sync(0xffffffffu, mx, o));
    if (lane == 0) red[tid >> 5] = mx;
    __syncthreads();
    if (tid < 32) {
        float t = (tid < 8) ? red[tid] : -1e30f;
        #pragma unroll
        for (int o = 4; o; o >>= 1) t = fmaxf(t, __shfl_xor_sync(0xffffffffu, t, o));
        if (tid == 0) red[0] = t;
    }
    __syncthreads();
    mx = red[0];
    __syncthreads();
    float sum = 0.f;
    #pragma unroll
    for (int j = 0; j < 4; j++) { loc[j] = expf(loc[j] - mx); sum += loc[j]; }
    float tot = blk_sum(sum, red);
    float inv = 1.0f / tot;
    #pragma unroll
    for (int j = 0; j < 4; j++) x[tid + j * 256] = loc[j] * inv;
}

// ---------------------------------------------------------------------------
// z projection prep: fold LN affine + head projection into a 32x64 GEMM
//   W'[lh,c] = pair_w[l,c] * bias_w[l,h,c]
//   wpsum[lh] = sum_c W'[lh,c]
//   wbias[lh] = sum_c pair_b[l,c]*bias_w[l,h,c] + bias_b[l,h]
// ---------------------------------------------------------------------------
__global__ void zprep_kernel(const float* __restrict__ pw, const float* __restrict__ pb,
                             const float* __restrict__ bw, const float* __restrict__ bb,
                             float* __restrict__ Wp, float* __restrict__ Wsum,
                             float* __restrict__ Wbias) {
    int lh = threadIdx.x;
    if (lh >= 32) return;
    int l = lh >> 4;
    float as = 0.f, bs = 0.f;
    for (int c = 0; c < 64; c++) {
        float w = bw[lh * 64 + c];
        float wp = pw[l * 64 + c] * w;
        Wp[lh * 64 + c] = wp;
        as += wp;
        bs += pb[l * 64 + c] * w;
    }
    Wsum[lh] = as;
    Wbias[lh] = bs + bb[lh];
}

// ---------------------------------------------------------------------------
// z projection: (1M x 64) @ (64 x 32) with per-row LN folded in.
// Writes both layers' flat bias arrays:  bflat_l[row*16 + h]
// Block: 128 rows x 32 cols, 256 threads (4x4 microtile on 8x32 thread grid)
// ---------------------------------------------------------------------------
__global__ void __launch_bounds__(256) zproj_kernel(const float* __restrict__ z,
                                                    const float* __restrict__ Wp,
                                                    const float* __restrict__ Wsum,
                                                    const float* __restrict__ Wbias,
                                                    float* __restrict__ b0,
                                                    float* __restrict__ b1) {
    __shared__ float zs[128 * 65];
    __shared__ float wsm[32 * 65];
    __shared__ float asm_[32], bsm[32];
    __shared__ float stat[128 * 2];
    int tid = threadIdx.x;
    long long base = (long long)blockIdx.x * 128 * 64;
    #pragma unroll
    for (int i = 0; i < 32; i++) {
        int idx = tid + i * 256;
        int r = idx >> 6, c = idx & 63;
        zs[r * 65 + c] = z[base + idx];
    }
    #pragma unroll
    for (int i = 0; i < 8; i++) {
        int idx = tid + i * 256;
        int lh = idx >> 6, c = idx & 63;
        wsm[lh * 65 + c] = Wp[idx];
    }
    if (tid < 32) { asm_[tid] = Wsum[tid]; bsm[tid] = Wbias[tid]; }
    __syncthreads();
    if (tid < 128) {
        float s = 0.f, s2 = 0.f;
        #pragma unroll 8
        for (int c = 0; c < 64; c++) { float v = zs[tid * 65 + c]; s += v; s2 += v * v; }
        float m = s * (1.f / 64.f);
        float var = s2 * (1.f / 64.f) - m * m;
        stat[tid * 2] = m;
        stat[tid * 2 + 1] = rsqrtf(var + 1e-5f);
    }
    __syncthreads();
    int tx = tid & 7, ty = tid >> 3;
    float acc[4][4] = {};
    #pragma unroll 8
    for (int k = 0; k < 64; k++) {
        float a[4], b[4];
        #pragma unroll
        for (int i = 0; i < 4; i++) a[i] = zs[(ty * 4 + i) * 65 + k];
        #pragma unroll
        for (int j = 0; j < 4; j++) b[j] = wsm[(tx * 4 + j) * 65 + k];
        #pragma unroll
        for (int i = 0; i < 4; i++)
            #pragma unroll
            for (int j = 0; j < 4; j++) acc[i][j] += a[i] * b[j];
    }
    long long rowg0 = (long long)blockIdx.x * 128;
    #pragma unroll
    for (int i = 0; i < 4; i++) {
        int rl = ty * 4 + i;
        long long rg = rowg0 + rl;
        float m = stat[rl * 2], rs = stat[rl * 2 + 1];
        #pragma unroll
        for (int j = 0; j < 4; j++) {
            int col = tx * 4 + j;
            float val = rs * (acc[i][j] - m * asm_[col]) + bsm[col];
            float* dst = (col < 16) ? b0 : b1;
            dst[rg * 16 + (col & 15)] = val;
        }
    }
}

// ---------------------------------------------------------------------------
// Generic fp32 tiled GEMM:  C[m,n] = sum_k A[m,k] * B[n,k]   (NT by default)
//   TA: A[m,k] stored at A[k*lda + m]     (used for P^T in attention-o)
//   TB: B[n,k] stored at B[k*ldb + n]     (used for V in attention-o)
//   DUAL: second B matrix, second accumulator (adaLN / SwiGLU)
// 64x64 tile, BK=16, 256 threads, 4x4 microtile. Requires M%64==0, K%16==0.
// ---------------------------------------------------------------------------
enum { EPI_PLAIN = 0, EPI_SCORES = 1, EPI_GSIG = 2, EPI_OUTGATE = 3,
       EPI_TRFIN = 4, EPI_ADALN = 5, EPI_GLU = 6 };

template <int EPI, bool TA, bool TB, bool DUAL>
__global__ void __launch_bounds__(256) gemm64(
    const float* __restrict__ A, const float* __restrict__ B1,
    const float* __restrict__ B2, const float* __restrict__ bias,
    const float* __restrict__ ascale, const float* __restrict__ aux,
    const float* __restrict__ aux2, float* __restrict__ Cp,
    int M, int N, int K, int lda, int ldb, int ldc, int aux_ld,
    long long sA, long long sB, long long sC, long long sAux, float alpha) {
    const int tid = threadIdx.x;
    const int tx = tid & 15, ty = tid >> 4;
    const int bm = blockIdx.y * 64, bn = blockIdx.x * 64;
    const int bz = blockIdx.z;
    A += bz * sA;
    B1 += bz * sB;
    if constexpr (DUAL) B2 += bz * sB;
    Cp += bz * sC;
    if (aux) aux += bz * sAux;

    __shared__ float As[64][17];
    __shared__ float Bs1[64][17];
    __shared__ float Bs2[DUAL ? 64 : 1][17];

    float acc1[4][4] = {};
    float acc2[4][4] = {};

    for (int k0 = 0; k0 < K; k0 += 16) {
        #pragma unroll
        for (int i = 0; i < 4; i++) {
            int idx = tid + i * 256;
            if constexpr (!TA) {
                int r = idx >> 4, kk = idx & 15;
                float v = A[(long long)(bm + r) * lda + (k0 + kk)];
                if (ascale) v *= ascale[k0 + kk];
                As[r][kk] = v;
            } else {
                int m = idx & 63, kk = idx >> 6;
                As[m][kk] = A[(long long)(k0 + kk) * lda + (bm + m)];
            }
        }
        #pragma unroll
        for (int i = 0; i < 4; i++) {
            int idx = tid + i * 256;
            if constexpr (!TB) {
                int n = idx >> 4, kk = idx & 15;
                int gn = bn + n;
                Bs1[n][kk] = (gn < N) ? B1[(long long)gn * ldb + (k0 + kk)] : 0.f;
                if constexpr (DUAL)
                    Bs2[n][kk] = (gn < N) ? B2[(long long)gn * ldb + (k0 + kk)] : 0.f;
            } else {
                int n = idx & 63, kk = idx >> 6;
                int gn = bn + n;
                Bs1[n][kk] = (gn < N) ? B1[(long long)(k0 + kk) * ldb + gn] : 0.f;
                if constexpr (DUAL)
                    Bs2[n][kk] = (gn < N) ? B2[(long long)(k0 + kk) * ldb + gn] : 0.f;
            }
        }
        __syncthreads();
        #pragma unroll
        for (int kk = 0; kk < 16; kk++) {
            float a[4], b[4], b2v[4];
            #pragma unroll
            for (int i = 0; i < 4; i++) a[i] = As[ty * 4 + i][kk];
            #pragma unroll
            for (int j = 0; j < 4; j++) b[j] = Bs1[tx * 4 + j][kk];
            if constexpr (DUAL) {
                #pragma unroll
                for (int j = 0; j < 4; j++) b2v[j] = Bs2[tx * 4 + j][kk];
            }
            #pragma unroll
            for (int i = 0; i < 4; i++)
                #pragma unroll
                for (int j = 0; j < 4; j++) {
                    acc1[i][j] += a[i] * b[j];
                    if constexpr (DUAL) acc2[i][j] += a[i] * b2v[j];
                }
        }
        __syncthreads();
    }

    #pragma unroll
    for (int i = 0; i < 4; i++) {
        int m = bm + ty * 4 + i;
        #pragma unroll
        for (int j = 0; j < 4; j++) {
            int n = bn + tx * 4 + j;
            if (n >= N) continue;
            long long cidx = (long long)m * ldc + n;
            float v = acc1[i][j];
            float out;
            if constexpr (EPI == EPI_PLAIN) {
                out = v + (bias ? bias[n] : 0.f);
            } else if constexpr (EPI == EPI_SCORES) {
                out = v * alpha + Cp[cidx];                       // in-place += bias
            } else if constexpr (EPI == EPI_GSIG) {
                out = sigf(aux[(long long)m * aux_ld + n]) * v;   // sigmoid(g) * o
            } else if constexpr (EPI == EPI_OUTGATE) {
                out = sigf(v + bias[n]) * aux[(long long)m * aux_ld + n];
            } else if constexpr (EPI == EPI_TRFIN) {
                out = aux2[(long long)m * aux_ld + n] +
                      sigf((v + bias[n]) * aux[(long long)m * aux_ld + n]);
            } else if constexpr (EPI == EPI_ADALN) {
                out = sigf((v + bias[n]) * aux[(long long)m * aux_ld + n] + acc2[i][j]);
            } else {  // EPI_GLU: silu(acc1) * acc2
                float s1 = v * sigf(v);
                out = s1 * acc2[i][j];
            }
            Cp[cidx] = out;
        }
    }
}

// ---------------------------------------------------------------------------
// Host orchestration
// ---------------------------------------------------------------------------
extern "C" void kernel_launch(void* const* d_in, const int* in_sizes, int n_in,
                              void* d_out, int out_size) {
    const float* A0        = (const float*)d_in[0];
    const float* Sm        = (const float*)d_in[1];
    const float* Z         = (const float*)d_in[2];
    const float* attn_sn_w = (const float*)d_in[3];
    const float* attn_pb_w = (const float*)d_in[4];
    const float* attn_pb_b = (const float*)d_in[5];
    const float* attn_pnb_w= (const float*)d_in[6];
    const float* pair_w    = (const float*)d_in[7];
    const float* pair_b    = (const float*)d_in[8];
    const float* q_w       = (const float*)d_in[9];
    const float* q_b       = (const float*)d_in[10];
    const float* kvg_w     = (const float*)d_in[11];
    const float* bias_w    = (const float*)d_in[12];
    const float* bias_b    = (const float*)d_in[13];
    const float* ao_w      = (const float*)d_in[14];
    const float* out_w     = (const float*)d_in[15];
    const float* out_b     = (const float*)d_in[16];
    const float* tr_sn_w   = (const float*)d_in[17];
    const float* tr_pb_w   = (const float*)d_in[18];
    const float* tr_pb_b   = (const float*)d_in[19];
    const float* tr_pnb_w  = (const float*)d_in[20];
    const float* tr_a_w    = (const float*)d_in[21];
    const float* tr_s_w    = (const float*)d_in[22];
    const float* tr_s_b    = (const float*)d_in[23];
    const float* tr_b_w    = (const float*)d_in[24];
    float* OUT = (float*)d_out;

    float *b0, *b1, *shat, *an, *a2, *qf, *kvg, *ob, *amm, *aout, *bbuf, *tmm, *anew;
    float *wp, *wpsum, *wbias;
    cudaGetSymbolAddress((void**)&b0, g_b0);
    cudaGetSymbolAddress((void**)&b1, g_b1);
    cudaGetSymbolAddress((void**)&shat, g_shat);
    cudaGetSymbolAddress((void**)&an, g_an);
    cudaGetSymbolAddress((void**)&a2, g_a2);
    cudaGetSymbolAddress((void**)&qf, g_q);
    cudaGetSymbolAddress((void**)&kvg, g_kvg);
    cudaGetSymbolAddress((void**)&ob, g_o);
    cudaGetSymbolAddress((void**)&amm, g_amm);
    cudaGetSymbolAddress((void**)&aout, g_aout);
    cudaGetSymbolAddress((void**)&bbuf, g_bb);
    cudaGetSymbolAddress((void**)&tmm, g_tmm);
    cudaGetSymbolAddress((void**)&anew, g_anew);
    cudaGetSymbolAddress((void**)&wp, g_wp);
    cudaGetSymbolAddress((void**)&wpsum, g_wpsum);
    cudaGetSymbolAddress((void**)&wbias, g_wbias);

    // s is layer-invariant: LN once
    ln_kernel<<<S_, 256>>>(Sm, shat, CS_);
    // z -> both layers' flat attention-bias arrays (reads z once)
    zprep_kernel<<<1, 32>>>(pair_w, pair_b, bias_w, bias_b, wp, wpsum, wbias);
    zproj_kernel<<<(S_ * S_) / 128, 256>>>(Z, wp, wpsum, wbias, b0, b1);

    for (int l = 0; l < 2; l++) {
        const float* ain = l ? anew : A0;
        float* aoutp = l ? OUT : anew;
        float* bf = l ? b1 : b0;
        long long lw = (long long)l;

        ln_kernel<<<S_, 256>>>(ain, an, CA_);

        // adaLN (attention branch): a2 = sigmoid((sn@pbW^T + pb_b)*an + sn@pnbW^T)
        gemm64<EPI_ADALN, false, false, true><<<dim3(12, 16, 1), 256>>>(
            shat, attn_pb_w + lw * CA_ * CS_, attn_pnb_w + lw * CA_ * CS_,
            attn_pb_b + lw * CA_, attn_sn_w + lw * CS_, an, nullptr,
            a2, S_, CA_, CS_, CS_, CS_, CA_, CA_, 0, 0, 0, 0, 1.f);

        // q = a2 @ q_w^T + q_b
        gemm64<EPI_PLAIN, false, false, false><<<dim3(12, 16, 1), 256>>>(
            a2, q_w + lw * CA_ * CA_, nullptr, q_b + lw * CA_, nullptr, nullptr, nullptr,
            qf, S_, CA_, CA_, CA_, CA_, CA_, 0, 0, 0, 0, 0, 1.f);

        // kvg = a2 @ kvg_w^T
        gemm64<EPI_PLAIN, false, false, false><<<dim3(36, 16, 1), 256>>>(
            a2, kvg_w + lw * 3 * CA_ * CA_, nullptr, nullptr, nullptr, nullptr, nullptr,
            kvg, S_, 3 * CA_, CA_, CA_, CA_, 3 * CA_, 0, 0, 0, 0, 0, 1.f);

        // scores[h,r,t] = dot(k[h,r], q[h,t]) / 48 + bflat[h,r,t]   (in place)
        gemm64<EPI_SCORES, false, false, false><<<dim3(16, 16, 16), 256>>>(
            kvg, qf, nullptr, nullptr, nullptr, nullptr, nullptr,
            bf, S_, S_, CH_, C3_, CH_, S_, 0,
            (long long)S_ * C3_, (long long)S_ * CH_, (long long)S_ * S_, 0, 1.f / 48.f);

        // softmax over last axis (t), rows = H*S
        softmax_kernel<<<H_ * S_, 256>>>(bf);

        // o[h,j,c] = sum_r P[h,r,j]*v[h,r,c];  fused: sigmoid(g[h,j,c]) * o
        gemm64<EPI_GSIG, true, true, false><<<dim3(1, 16, 16), 256>>>(
            bf, kvg + CH_, nullptr, nullptr, nullptr, kvg + 2 * CH_, nullptr,
            ob, S_, CH_, S_, S_, C3_, CH_, C3_,
            (long long)S_ * S_, (long long)S_ * C3_, (long long)S_ * CH_,
            (long long)S_ * C3_, 1.f);

        // attn_mm = (sig(g)*o) @ ao_w^T
        gemm64<EPI_PLAIN, false, false, false><<<dim3(12, 16, 1), 256>>>(
            ob, ao_w + lw * CA_ * CA_, nullptr, nullptr, nullptr, nullptr, nullptr,
            amm, S_, CA_, CA_, CA_, CA_, CA_, 0, 0, 0, 0, 0, 1.f);

        // attn_out = sigmoid(s @ out_w^T + out_b) * attn_mm
        gemm64<EPI_OUTGATE, false, false, false><<<dim3(12, 16, 1), 256>>>(
            Sm, out_w + lw * CA_ * CS_, nullptr, out_b + lw * CA_, nullptr, amm, nullptr,
            aout, S_, CA_, CS_, CS_, CS_, CA_, CA_, 0, 0, 0, 0, 1.f);

        // adaLN (transition branch) -> a3 (reuse a2)
        gemm64<EPI_ADALN, false, false, true><<<dim3(12, 16, 1), 256>>>(
            shat, tr_pb_w + lw * CA_ * CS_, tr_pnb_w + lw * CA_ * CS_,
            tr_pb_b + lw * CA_, tr_sn_w + lw * CS_, an, nullptr,
            a2, S_, CA_, CS_, CS_, CS_, CA_, CA_, 0, 0, 0, 0, 1.f);

        // bb = silu(a3 @ W1^T) * (a3 @ W2^T)   (tr_a_w split in half)
        gemm64<EPI_GLU, false, false, true><<<dim3(24, 16, 1), 256>>>(
            a2, tr_a_w + lw * 4 * CA_ * CA_, tr_a_w + lw * 4 * CA_ * CA_ + (long long)2 * CA_ * CA_,
            nullptr, nullptr, nullptr, nullptr,
            bbuf, S_, 2 * CA_, CA_, CA_, CA_, 2 * CA_, 0, 0, 0, 0, 0, 1.f);

        // tmm = bb @ tr_b_w^T
        gemm64<EPI_PLAIN, false, false, false><<<dim3(12, 16, 1), 256>>>(
            bbuf, tr_b_w + lw * CA_ * 2 * CA_, nullptr, nullptr, nullptr, nullptr, nullptr,
            tmm, S_, CA_, 2 * CA_, 2 * CA_, 2 * CA_, CA_, 0, 0, 0, 0, 0, 1.f);

        // a_next = attn_out + sigmoid((s @ tr_s_w^T + tr_s_b) * tmm)
        gemm64<EPI_TRFIN, false, false, false><<<dim3(12, 16, 1), 256>>>(
            Sm, tr_s_w + lw * CA_ * CS_, nullptr, tr_s_b + lw * CA_, nullptr, tmm, aout,
            aoutp, S_, CA_, CS_, CS_, CS_, CA_, CA_, 0, 0, 0, 0, 1.f);
    }
}

// round 3
// speedup vs baseline: 1.1047x; 1.1047x over previous
#include <cuda_runtime.h>
#include <math.h>
#include <stdint.h>

// Problem constants
#define S_   1024
#define CA_  768
#define CS_  384
#define CZ_  64
#define H_   16
#define CH_  48     // head dim
#define C3_  144    // 3*CH

// ---------------------------------------------------------------------------
// Static scratch (device globals — no cudaMalloc allowed)
// ---------------------------------------------------------------------------
__device__ float g_b0[16 * 1024 * 1024];   // layer-0 bias/scores/P  (64 MiB)
__device__ float g_b1[16 * 1024 * 1024];   // layer-1 bias/scores/P  (64 MiB)
__device__ float g_shat[S_ * CS_];         // LN(s), no affine
__device__ float g_an[S_ * CA_];           // LN(a) per layer
__device__ float g_a2[S_ * CA_];           // adaln output (a2 / a3)
__device__ float g_q[S_ * CA_];
__device__ float g_kvg[S_ * 3 * CA_];
__device__ float g_o[S_ * CA_];            // sigmoid(g)*o, flat (B,S,CA) order
__device__ float g_amm[S_ * CA_];          // attn @ ao_w^T
__device__ float g_aout[S_ * CA_];         // gated attention output
__device__ float g_bb[S_ * 2 * CA_];       // silu(h1)*h2
__device__ float g_tmm[S_ * CA_];          // bb @ tr_b_w^T
__device__ float g_anew[S_ * CA_];         // a after layer 0
__device__ float g_wp[32 * 64];            // folded z-projection weights
__device__ float g_wpsum[32];
__device__ float g_wbias[32];

// ---------------------------------------------------------------------------
// Helpers
// ---------------------------------------------------------------------------
__device__ __forceinline__ float sigf(float x) { return 1.0f / (1.0f + expf(-x)); }

__device__ __forceinline__ float tf32r(float x) {
    uint32_t u;
    asm("cvt.rna.tf32.f32 %0, %1;" : "=r"(u) : "f"(x));
    return __uint_as_float(u);
}

__device__ __forceinline__ void mma_tf32(float* d, const uint32_t* a,
                                         uint32_t b0, uint32_t b1) {
    asm volatile(
        "mma.sync.aligned.m16n8k8.row.col.f32.tf32.tf32.f32 "
        "{%0,%1,%2,%3}, {%4,%5,%6,%7}, {%8,%9}, {%0,%1,%2,%3};"
        : "+f"(d[0]), "+f"(d[1]), "+f"(d[2]), "+f"(d[3])
        : "r"(a[0]), "r"(a[1]), "r"(a[2]), "r"(a[3]), "r"(b0), "r"(b1));
}

// block = 256 threads
__device__ __forceinline__ float blk_sum(float v, float* red) {
    int tid = threadIdx.x, lane = tid & 31;
    #pragma unroll
    for (int o = 16; o; o >>= 1) v += __shfl_xor_sync(0xffffffffu, v, o);
    if (lane == 0) red[tid >> 5] = v;
    __syncthreads();
    if (tid < 32) {
        float t = (tid < 8) ? red[tid] : 0.f;
        #pragma unroll
        for (int o = 4; o; o >>= 1) t += __shfl_xor_sync(0xffffffffu, t, o);
        if (tid == 0) red[0] = t;
    }
    __syncthreads();
    v = red[0];
    __syncthreads();
    return v;
}

// ---------------------------------------------------------------------------
// LayerNorm (no affine): one block per row, 256 threads, W <= 768
// ---------------------------------------------------------------------------
__global__ void __launch_bounds__(256) ln_kernel(const float* __restrict__ x,
                                                 float* __restrict__ y, int W) {
    __shared__ float red[32];
    long long row = blockIdx.x;
    const float* xr = x + row * W;
    float loc[3];
    int cnt = 0;
    float s = 0.f;
    for (int i = threadIdx.x; i < W; i += 256) { float v = xr[i]; loc[cnt++] = v; s += v; }
    float mean = blk_sum(s, red) / (float)W;
    float vs = 0.f;
    for (int j = 0; j < cnt; j++) { float d = loc[j] - mean; vs += d * d; }
    float var = blk_sum(vs, red) / (float)W;
    float rstd = rsqrtf(var + 1e-5f);
    float* yr = y + row * W;
    int j = 0;
    for (int i = threadIdx.x; i < W; i += 256) yr[i] = (loc[j++] - mean) * rstd;
}

// ---------------------------------------------------------------------------
// In-place softmax over rows of length 1024 (H*S rows)
// ---------------------------------------------------------------------------
__global__ void __launch_bounds__(256) softmax_kernel(float* __restrict__ p) {
    __shared__ float red[32];
    long long row = blockIdx.x;
    float* x = p + row * 1024;
    int tid = threadIdx.x, lane = tid & 31;
    float loc[4];
    float mx = -1e30f;
    #pragma unroll
    for (int j = 0; j < 4; j++) { loc[j] = x[tid + j * 256]; mx = fmaxf(mx, loc[j]); }
    #pragma unroll
    for (int o = 16; o; o >>= 1) mx = fmaxf(mx, __shfl_xor_sync(0xffffffffu, mx, o));
    if (lane == 0) red[tid >> 5] = mx;
    __syncthreads();
    if (tid < 32) {
        float t = (tid < 8) ? red[tid] : -1e30f;
        #pragma unroll
        for (int o = 4; o; o >>= 1) t = fmaxf(t, __shfl_xor_sync(0xffffffffu, t, o));
        if (tid == 0) red[0] = t;
    }
    __syncthreads();
    mx = red[0];
    __syncthreads();
    float sum = 0.f;
    #pragma unroll
    for (int j = 0; j < 4; j++) { loc[j] = expf(loc[j] - mx); sum += loc[j]; }
    float tot = blk_sum(sum, red);
    float inv = 1.0f / tot;
    #pragma unroll
    for (int j = 0; j < 4; j++) x[tid + j * 256] = loc[j] * inv;
}

// ---------------------------------------------------------------------------
// z projection prep: fold LN affine + head projection into a 32x64 GEMM
// ---------------------------------------------------------------------------
__global__ void zprep_kernel(const float* __restrict__ pw, const float* __restrict__ pb,
                             const float* __restrict__ bw, const float* __restrict__ bb,
                             float* __restrict__ Wp, float* __restrict__ Wsum,
                             float* __restrict__ Wbias) {
    int lh = threadIdx.x;
    if (lh >= 32) return;
    int l = lh >> 4;
    float as = 0.f, bs = 0.f;
    for (int c = 0; c < 64; c++) {
        float w = bw[lh * 64 + c];
        float wp = pw[l * 64 + c] * w;
        Wp[lh * 64 + c] = wp;
        as += wp;
        bs += pb[l * 64 + c] * w;
    }
    Wsum[lh] = as;
    Wbias[lh] = bs + bb[lh];
}

// ---------------------------------------------------------------------------
// z projection: (1M x 64) @ (64 x 32) with per-row LN folded in.
// ---------------------------------------------------------------------------
__global__ void __launch_bounds__(256) zproj_kernel(const float* __restrict__ z,
                                                    const float* __restrict__ Wp,
                                                    const float* __restrict__ Wsum,
                                                    const float* __restrict__ Wbias,
                                                    float* __restrict__ b0,
                                                    float* __restrict__ b1) {
    __shared__ float zs[128 * 65];
    __shared__ float wsm[32 * 65];
    __shared__ float asm_[32], bsm[32];
    __shared__ float stat[128 * 2];
    int tid = threadIdx.x;
    long long base = (long long)blockIdx.x * 128 * 64;
    #pragma unroll
    for (int i = 0; i < 32; i++) {
        int idx = tid + i * 256;
        int r = idx >> 6, c = idx & 63;
        zs[r * 65 + c] = z[base + idx];
    }
    #pragma unroll
    for (int i = 0; i < 8; i++) {
        int idx = tid + i * 256;
        int lh = idx >> 6, c = idx & 63;
        wsm[lh * 65 + c] = Wp[idx];
    }
    if (tid < 32) { asm_[tid] = Wsum[tid]; bsm[tid] = Wbias[tid]; }
    __syncthreads();
    if (tid < 128) {
        float s = 0.f, s2 = 0.f;
        #pragma unroll 8
        for (int c = 0; c < 64; c++) { float v = zs[tid * 65 + c]; s += v; s2 += v * v; }
        float m = s * (1.f / 64.f);
        float var = s2 * (1.f / 64.f) - m * m;
        stat[tid * 2] = m;
        stat[tid * 2 + 1] = rsqrtf(var + 1e-5f);
    }
    __syncthreads();
    int tx = tid & 7, ty = tid >> 3;
    float acc[4][4] = {};
    #pragma unroll 8
    for (int k = 0; k < 64; k++) {
        float a[4], b[4];
        #pragma unroll
        for (int i = 0; i < 4; i++) a[i] = zs[(ty * 4 + i) * 65 + k];
        #pragma unroll
        for (int j = 0; j < 4; j++) b[j] = wsm[(tx * 4 + j) * 65 + k];
        #pragma unroll
        for (int i = 0; i < 4; i++)
            #pragma unroll
            for (int j = 0; j < 4; j++) acc[i][j] += a[i] * b[j];
    }
    long long rowg0 = (long long)blockIdx.x * 128;
    #pragma unroll
    for (int i = 0; i < 4; i++) {
        int rl = ty * 4 + i;
        long long rg = rowg0 + rl;
        float m = stat[rl * 2], rs = stat[rl * 2 + 1];
        #pragma unroll
        for (int j = 0; j < 4; j++) {
            int col = tx * 4 + j;
            float val = rs * (acc[i][j] - m * asm_[col]) + bsm[col];
            float* dst = (col < 16) ? b0 : b1;
            dst[rg * 16 + (col & 15)] = val;
        }
    }
}

// ---------------------------------------------------------------------------
// Tensor-core tf32 GEMM:  C[m,n] = sum_k A[m,k] * B[n,k]   (NT by default)
//   TA: A[m,k] stored at A[k*lda + m]     (P^T in attention-o)
//   TB: B[n,k] stored at B[k*ldb + n]     (V in attention-o)
//   DUAL: second B matrix, second accumulator (adaLN / SwiGLU)
// Block tile 128x64, BK=16, 256 threads (8 warps, 4x2), warp tile 32x32.
// mma.sync.m16n8k8 tf32->fp32. Requires M%128==0, K%16==0.
// ---------------------------------------------------------------------------
enum { EPI_PLAIN = 0, EPI_SCORES = 1, EPI_GSIG = 2, EPI_OUTGATE = 3,
       EPI_TRFIN = 4, EPI_ADALN = 5, EPI_GLU = 6 };

template <int EPI, bool TA, bool TB, bool DUAL>
__global__ void __launch_bounds__(256) gemm_tc(
    const float* __restrict__ A, const float* __restrict__ B1,
    const float* __restrict__ B2, const float* __restrict__ bias,
    const float* __restrict__ ascale, const float* __restrict__ aux,
    const float* __restrict__ aux2, float* __restrict__ Cp,
    int M, int N, int K, int lda, int ldb, int ldc, int aux_ld,
    long long sA, long long sB, long long sC, long long sAux, float alpha) {
    const int tid = threadIdx.x;
    const int lane = tid & 31, warp = tid >> 5;
    const int wm = warp >> 1, wn = warp & 1;       // 4 x 2 warp grid
    const int bm = blockIdx.y * 128, bn = blockIdx.x * 64;
    const int bz = blockIdx.z;
    A += bz * sA;
    B1 += bz * sB;
    if constexpr (DUAL) B2 += bz * sB;
    Cp += bz * sC;
    if (aux) aux += bz * sAux;

    __shared__ float As[128][20];
    __shared__ float Bs1[64][20];
    __shared__ float Bs2[DUAL ? 64 : 1][20];

    float acc1[2][4][4] = {};
    float acc2[2][4][4] = {};

    const int qr = lane >> 2, qc = lane & 3;       // quad row / col

    for (int k0 = 0; k0 < K; k0 += 16) {
        // ---- load A tile 128x16 (8 elems/thread), round to tf32 ----
        #pragma unroll
        for (int i = 0; i < 8; i++) {
            int idx = tid + i * 256;
            if constexpr (!TA) {
                int r = idx >> 4, kk = idx & 15;
                float v = A[(long long)(bm + r) * lda + (k0 + kk)];
                if (ascale) v *= ascale[k0 + kk];
                As[r][kk] = tf32r(v);
            } else {
                int m = idx & 127, kk = idx >> 7;
                As[m][kk] = tf32r(A[(long long)(k0 + kk) * lda + (bm + m)]);
            }
        }
        // ---- load B tile(s) 64x16 (4 elems/thread) ----
        #pragma unroll
        for (int i = 0; i < 4; i++) {
            int idx = tid + i * 256;
            if constexpr (!TB) {
                int n = idx >> 4, kk = idx & 15;
                int gn = bn + n;
                Bs1[n][kk] = (gn < N) ? tf32r(B1[(long long)gn * ldb + (k0 + kk)]) : 0.f;
                if constexpr (DUAL)
                    Bs2[n][kk] = (gn < N) ? tf32r(B2[(long long)gn * ldb + (k0 + kk)]) : 0.f;
            } else {
                int n = idx & 63, kk = idx >> 6;
                int gn = bn + n;
                Bs1[n][kk] = (gn < N) ? tf32r(B1[(long long)(k0 + kk) * ldb + gn]) : 0.f;
                if constexpr (DUAL)
                    Bs2[n][kk] = (gn < N) ? tf32r(B2[(long long)(k0 + kk) * ldb + gn]) : 0.f;
            }
        }
        __syncthreads();

        #pragma unroll
        for (int ks = 0; ks < 2; ks++) {
            const int kc = ks * 8;
            uint32_t af[2][4];
            #pragma unroll
            for (int i = 0; i < 2; i++) {
                int r = wm * 32 + i * 16 + qr;
                af[i][0] = __float_as_uint(As[r][kc + qc]);
                af[i][1] = __float_as_uint(As[r + 8][kc + qc]);
                af[i][2] = __float_as_uint(As[r][kc + 4 + qc]);
                af[i][3] = __float_as_uint(As[r + 8][kc + 4 + qc]);
            }
            #pragma unroll
            for (int j = 0; j < 4; j++) {
                int n = wn * 32 + j * 8 + qr;
                uint32_t b0 = __float_as_uint(Bs1[n][kc + qc]);
                uint32_t b1 = __float_as_uint(Bs1[n][kc + 4 + qc]);
                #pragma unroll
                for (int i = 0; i < 2; i++) mma_tf32(acc1[i][j], af[i], b0, b1);
                if constexpr (DUAL) {
                    uint32_t c0 = __float_as_uint(Bs2[n][kc + qc]);
                    uint32_t c1 = __float_as_uint(Bs2[n][kc + 4 + qc]);
                    #pragma unroll
                    for (int i = 0; i < 2; i++) mma_tf32(acc2[i][j], af[i], c0, c1);
                }
            }
        }
        __syncthreads();
    }

    // ---- epilogue: map m16n8 C layout back to (m,n) ----
    #pragma unroll
    for (int i = 0; i < 2; i++) {
        #pragma unroll
        for (int j = 0; j < 4; j++) {
            int m0 = bm + wm * 32 + i * 16 + qr;
            int n0 = bn + wn * 32 + j * 8 + 2 * qc;
            #pragma unroll
            for (int e = 0; e < 4; e++) {
                int m = m0 + ((e >= 2) ? 8 : 0);
                int n = n0 + (e & 1);
                if (n >= N) continue;
                long long cidx = (long long)m * ldc + n;
                float v = acc1[i][j][e];
                float out;
                if constexpr (EPI == EPI_PLAIN) {
                    out = v + (bias ? bias[n] : 0.f);
                } else if constexpr (EPI == EPI_SCORES) {
                    out = v * alpha + Cp[cidx];                       // in-place += bias
                } else if constexpr (EPI == EPI_GSIG) {
                    out = sigf(aux[(long long)m * aux_ld + n]) * v;   // sigmoid(g) * o
                } else if constexpr (EPI == EPI_OUTGATE) {
                    out = sigf(v + bias[n]) * aux[(long long)m * aux_ld + n];
                } else if constexpr (EPI == EPI_TRFIN) {
                    out = aux2[(long long)m * aux_ld + n] +
                          sigf((v + bias[n]) * aux[(long long)m * aux_ld + n]);
                } else if constexpr (EPI == EPI_ADALN) {
                    out = sigf((v + bias[n]) * aux[(long long)m * aux_ld + n] + acc2[i][j][e]);
                } else {  // EPI_GLU: silu(acc1) * acc2
                    out = v * sigf(v) * acc2[i][j][e];
                }
                Cp[cidx] = out;
            }
        }
    }
}

// ---------------------------------------------------------------------------
// Host orchestration
// ---------------------------------------------------------------------------
extern "C" void kernel_launch(void* const* d_in, const int* in_sizes, int n_in,
                              void* d_out, int out_size) {
    const float* A0        = (const float*)d_in[0];
    const float* Sm        = (const float*)d_in[1];
    const float* Z         = (const float*)d_in[2];
    const float* attn_sn_w = (const float*)d_in[3];
    const float* attn_pb_w = (const float*)d_in[4];
    const float* attn_pb_b = (const float*)d_in[5];
    const float* attn_pnb_w= (const float*)d_in[6];
    const float* pair_w    = (const float*)d_in[7];
    const float* pair_b    = (const float*)d_in[8];
    const float* q_w       = (const float*)d_in[9];
    const float* q_b       = (const float*)d_in[10];
    const float* kvg_w     = (const float*)d_in[11];
    const float* bias_w    = (const float*)d_in[12];
    const float* bias_b    = (const float*)d_in[13];
    const float* ao_w      = (const float*)d_in[14];
    const float* out_w     = (const float*)d_in[15];
    const float* out_b     = (const float*)d_in[16];
    const float* tr_sn_w   = (const float*)d_in[17];
    const float* tr_pb_w   = (const float*)d_in[18];
    const float* tr_pb_b   = (const float*)d_in[19];
    const float* tr_pnb_w  = (const float*)d_in[20];
    const float* tr_a_w    = (const float*)d_in[21];
    const float* tr_s_w    = (const float*)d_in[22];
    const float* tr_s_b    = (const float*)d_in[23];
    const float* tr_b_w    = (const float*)d_in[24];
    float* OUT = (float*)d_out;

    float *b0, *b1, *shat, *an, *a2, *qf, *kvg, *ob, *amm, *aout, *bbuf, *tmm, *anew;
    float *wp, *wpsum, *wbias;
    cudaGetSymbolAddress((void**)&b0, g_b0);
    cudaGetSymbolAddress((void**)&b1, g_b1);
    cudaGetSymbolAddress((void**)&shat, g_shat);
    cudaGetSymbolAddress((void**)&an, g_an);
    cudaGetSymbolAddress((void**)&a2, g_a2);
    cudaGetSymbolAddress((void**)&qf, g_q);
    cudaGetSymbolAddress((void**)&kvg, g_kvg);
    cudaGetSymbolAddress((void**)&ob, g_o);
    cudaGetSymbolAddress((void**)&amm, g_amm);
    cudaGetSymbolAddress((void**)&aout, g_aout);
    cudaGetSymbolAddress((void**)&bbuf, g_bb);
    cudaGetSymbolAddress((void**)&tmm, g_tmm);
    cudaGetSymbolAddress((void**)&anew, g_anew);
    cudaGetSymbolAddress((void**)&wp, g_wp);
    cudaGetSymbolAddress((void**)&wpsum, g_wpsum);
    cudaGetSymbolAddress((void**)&wbias, g_wbias);

    // s is layer-invariant: LN once
    ln_kernel<<<S_, 256>>>(Sm, shat, CS_);
    // z -> both layers' flat attention-bias arrays (reads z once)
    zprep_kernel<<<1, 32>>>(pair_w, pair_b, bias_w, bias_b, wp, wpsum, wbias);
    zproj_kernel<<<(S_ * S_) / 128, 256>>>(Z, wp, wpsum, wbias, b0, b1);

    for (int l = 0; l < 2; l++) {
        const float* ain = l ? anew : A0;
        float* aoutp = l ? OUT : anew;
        float* bf = l ? b1 : b0;
        long long lw = (long long)l;

        ln_kernel<<<S_, 256>>>(ain, an, CA_);

        // adaLN (attention branch): a2 = sigmoid((sn@pbW^T + pb_b)*an + sn@pnbW^T)
        gemm_tc<EPI_ADALN, false, false, true><<<dim3(12, 8, 1), 256>>>(
            shat, attn_pb_w + lw * CA_ * CS_, attn_pnb_w + lw * CA_ * CS_,
            attn_pb_b + lw * CA_, attn_sn_w + lw * CS_, an, nullptr,
            a2, S_, CA_, CS_, CS_, CS_, CA_, CA_, 0, 0, 0, 0, 1.f);

        // q = a2 @ q_w^T + q_b
        gemm_tc<EPI_PLAIN, false, false, false><<<dim3(12, 8, 1), 256>>>(
            a2, q_w + lw * CA_ * CA_, nullptr, q_b + lw * CA_, nullptr, nullptr, nullptr,
            qf, S_, CA_, CA_, CA_, CA_, CA_, 0, 0, 0, 0, 0, 1.f);

        // kvg = a2 @ kvg_w^T
        gemm_tc<EPI_PLAIN, false, false, false><<<dim3(36, 8, 1), 256>>>(
            a2, kvg_w + lw * 3 * CA_ * CA_, nullptr, nullptr, nullptr, nullptr, nullptr,
            kvg, S_, 3 * CA_, CA_, CA_, CA_, 3 * CA_, 0, 0, 0, 0, 0, 1.f);

        // scores[h,r,t] = dot(k[h,r], q[h,t]) / 48 + bflat[h,r,t]   (in place)
        gemm_tc<EPI_SCORES, false, false, false><<<dim3(16, 8, 16), 256>>>(
            kvg, qf, nullptr, nullptr, nullptr, nullptr, nullptr,
            bf, S_, S_, CH_, C3_, CH_, S_, 0,
            (long long)S_ * C3_, (long long)S_ * CH_, (long long)S_ * S_, 0, 1.f / 48.f);

        // softmax over last axis (t), rows = H*S
        softmax_kernel<<<H_ * S_, 256>>>(bf);

        // o[h,j,c] = sum_r P[h,r,j]*v[h,r,c];  fused: sigmoid(g[h,j,c]) * o
        gemm_tc<EPI_GSIG, true, true, false><<<dim3(1, 8, 16), 256>>>(
            bf, kvg + CH_, nullptr, nullptr, nullptr, kvg + 2 * CH_, nullptr,
            ob, S_, CH_, S_, S_, C3_, CH_, C3_,
            (long long)S_ * S_, (long long)S_ * C3_, (long long)S_ * CH_,
            (long long)S_ * C3_, 1.f);

        // attn_mm = (sig(g)*o) @ ao_w^T
        gemm_tc<EPI_PLAIN, false, false, false><<<dim3(12, 8, 1), 256>>>(
            ob, ao_w + lw * CA_ * CA_, nullptr, nullptr, nullptr, nullptr, nullptr,
            amm, S_, CA_, CA_, CA_, CA_, CA_, 0, 0, 0, 0, 0, 1.f);

        // attn_out = sigmoid(s @ out_w^T + out_b) * attn_mm
        gemm_tc<EPI_OUTGATE, false, false, false><<<dim3(12, 8, 1), 256>>>(
            Sm, out_w + lw * CA_ * CS_, nullptr, out_b + lw * CA_, nullptr, amm, nullptr,
            aout, S_, CA_, CS_, CS_, CS_, CA_, CA_, 0, 0, 0, 0, 1.f);

        // adaLN (transition branch) -> a3 (reuse a2)
        gemm_tc<EPI_ADALN, false, false, true><<<dim3(12, 8, 1), 256>>>(
            shat, tr_pb_w + lw * CA_ * CS_, tr_pnb_w + lw * CA_ * CS_,
            tr_pb_b + lw * CA_, tr_sn_w + lw * CS_, an, nullptr,
            a2, S_, CA_, CS_, CS_, CS_, CA_, CA_, 0, 0, 0, 0, 1.f);

        // bb = silu(a3 @ W1^T) * (a3 @ W2^T)   (tr_a_w split in half)
        gemm_tc<EPI_GLU, false, false, true><<<dim3(24, 8, 1), 256>>>(
            a2, tr_a_w + lw * 4 * CA_ * CA_, tr_a_w + lw * 4 * CA_ * CA_ + (long long)2 * CA_ * CA_,
            nullptr, nullptr, nullptr, nullptr,
            bbuf, S_, 2 * CA_, CA_, CA_, CA_, 2 * CA_, 0, 0, 0, 0, 0, 1.f);

        // tmm = bb @ tr_b_w^T
        gemm_tc<EPI_PLAIN, false, false, false><<<dim3(12, 8, 1), 256>>>(
            bbuf, tr_b_w + lw * CA_ * 2 * CA_, nullptr, nullptr, nullptr, nullptr, nullptr,
            tmm, S_, CA_, 2 * CA_, 2 * CA_, 2 * CA_, CA_, 0, 0, 0, 0, 0, 1.f);

        // a_next = attn_out + sigmoid((s @ tr_s_w^T + tr_s_b) * tmm)
        gemm_tc<EPI_TRFIN, false, false, false><<<dim3(12, 8, 1), 256>>>(
            Sm, tr_s_w + lw * CA_ * CS_, nullptr, tr_s_b + lw * CA_, nullptr, tmm, aout,
            aoutp, S_, CA_, CS_, CS_, CS_, CA_, CA_, 0, 0, 0, 0, 1.f);
    }
}

// round 4
// speedup vs baseline: 1.8477x; 1.6725x over previous
#include <cuda_runtime.h>
#include <cuda_bf16.h>
#include <math.h>
#include <stdint.h>

// Problem constants
#define S_   1024
#define CA_  768
#define CS_  384
#define CZ_  64
#define H_   16
#define CH_  48     // head dim
#define C3_  144    // 3*CH

// ---------------------------------------------------------------------------
// Static scratch (device globals — no cudaMalloc allowed)
// ---------------------------------------------------------------------------
__device__ float g_b0[16 * 1024 * 1024];   // layer-0 bias/scores/P  (64 MiB)
__device__ float g_b1[16 * 1024 * 1024];   // layer-1 bias/scores/P  (64 MiB)
__device__ float g_shat[S_ * CS_];         // LN(s), no affine
__device__ float g_an[S_ * CA_];           // LN(a) per layer
__device__ float g_a2[S_ * CA_];           // adaln output (a2 / a3)
__device__ float g_q[S_ * CA_];
__device__ float g_kvg[S_ * 3 * CA_];
__device__ float g_o[S_ * CA_];            // sigmoid(g)*o, flat (B,S,CA) order
__device__ float g_amm[S_ * CA_];          // attn @ ao_w^T
__device__ float g_aout[S_ * CA_];         // gated attention output
__device__ float g_bb[S_ * 2 * CA_];       // silu(h1)*h2
__device__ float g_tmm[S_ * CA_];          // bb @ tr_b_w^T
__device__ float g_anew[S_ * CA_];         // a after layer 0
__device__ float g_wp[32 * 64];            // folded z-projection weights
__device__ float g_wpsum[32];
__device__ float g_wbias[32];

// ---------------------------------------------------------------------------
// Helpers
// ---------------------------------------------------------------------------
__device__ __forceinline__ float sigf(float x) { return 1.0f / (1.0f + expf(-x)); }

__device__ __forceinline__ void mma_bf16(float* d, const uint32_t* a,
                                         uint32_t b0, uint32_t b1) {
    asm volatile(
        "mma.sync.aligned.m16n8k16.row.col.f32.bf16.bf16.f32 "
        "{%0,%1,%2,%3}, {%4,%5,%6,%7}, {%8,%9}, {%0,%1,%2,%3};"
        : "+f"(d[0]), "+f"(d[1]), "+f"(d[2]), "+f"(d[3])
        : "r"(a[0]), "r"(a[1]), "r"(a[2]), "r"(a[3]), "r"(b0), "r"(b1));
}

// block = 256 threads
__device__ __forceinline__ float blk_sum(float v, float* red) {
    int tid = threadIdx.x, lane = tid & 31;
    #pragma unroll
    for (int o = 16; o; o >>= 1) v += __shfl_xor_sync(0xffffffffu, v, o);
    if (lane == 0) red[tid >> 5] = v;
    __syncthreads();
    if (tid < 32) {
        float t = (tid < 8) ? red[tid] : 0.f;
        #pragma unroll
        for (int o = 4; o; o >>= 1) t += __shfl_xor_sync(0xffffffffu, t, o);
        if (tid == 0) red[0] = t;
    }
    __syncthreads();
    v = red[0];
    __syncthreads();
    return v;
}

// ---------------------------------------------------------------------------
// LayerNorm (no affine): one block per row, 256 threads, W <= 768
// ---------------------------------------------------------------------------
__global__ void __launch_bounds__(256) ln_kernel(const float* __restrict__ x,
                                                 float* __restrict__ y, int W) {
    __shared__ float red[32];
    long long row = blockIdx.x;
    const float* xr = x + row * W;
    float loc[3];
    int cnt = 0;
    float s = 0.f;
    for (int i = threadIdx.x; i < W; i += 256) { float v = xr[i]; loc[cnt++] = v; s += v; }
    float mean = blk_sum(s, red) / (float)W;
    float vs = 0.f;
    for (int j = 0; j < cnt; j++) { float d = loc[j] - mean; vs += d * d; }
    float var = blk_sum(vs, red) / (float)W;
    float rstd = rsqrtf(var + 1e-5f);
    float* yr = y + row * W;
    int j = 0;
    for (int i = threadIdx.x; i < W; i += 256) yr[i] = (loc[j++] - mean) * rstd;
}

// ---------------------------------------------------------------------------
// In-place softmax over rows of length 1024 (H*S rows), float4 vectorized
// ---------------------------------------------------------------------------
__global__ void __launch_bounds__(256) softmax_kernel(float* __restrict__ p) {
    __shared__ float red[32];
    long long row = blockIdx.x;
    float4* x = (float4*)(p + row * 1024);
    int tid = threadIdx.x, lane = tid & 31;
    float4 v = x[tid];
    float mx = fmaxf(fmaxf(v.x, v.y), fmaxf(v.z, v.w));
    #pragma unroll
    for (int o = 16; o; o >>= 1) mx = fmaxf(mx, __shfl_xor_sync(0xffffffffu, mx, o));
    if (lane == 0) red[tid >> 5] = mx;
    __syncthreads();
    if (tid < 32) {
        float t = (tid < 8) ? red[tid] : -1e30f;
        #pragma unroll
        for (int o = 4; o; o >>= 1) t = fmaxf(t, __shfl_xor_sync(0xffffffffu, t, o));
        if (tid == 0) red[0] = t;
    }
    __syncthreads();
    mx = red[0];
    __syncthreads();
    v.x = expf(v.x - mx); v.y = expf(v.y - mx);
    v.z = expf(v.z - mx); v.w = expf(v.w - mx);
    float sum = v.x + v.y + v.z + v.w;
    float tot = blk_sum(sum, red);
    float inv = 1.0f / tot;
    v.x *= inv; v.y *= inv; v.z *= inv; v.w *= inv;
    x[tid] = v;
}

// ---------------------------------------------------------------------------
// z projection prep: fold LN affine + head projection into a 32x64 GEMM
// ---------------------------------------------------------------------------
__global__ void zprep_kernel(const float* __restrict__ pw, const float* __restrict__ pb,
                             const float* __restrict__ bw, const float* __restrict__ bb,
                             float* __restrict__ Wp, float* __restrict__ Wsum,
                             float* __restrict__ Wbias) {
    int lh = threadIdx.x;
    if (lh >= 32) return;
    int l = lh >> 4;
    float as = 0.f, bs = 0.f;
    for (int c = 0; c < 64; c++) {
        float w = bw[lh * 64 + c];
        float wp = pw[l * 64 + c] * w;
        Wp[lh * 64 + c] = wp;
        as += wp;
        bs += pb[l * 64 + c] * w;
    }
    Wsum[lh] = as;
    Wbias[lh] = bs + bb[lh];
}

// ---------------------------------------------------------------------------
// z projection: (1M x 64) @ (64 x 32) with per-row LN folded in.
// ---------------------------------------------------------------------------
__global__ void __launch_bounds__(256) zproj_kernel(const float* __restrict__ z,
                                                    const float* __restrict__ Wp,
                                                    const float* __restrict__ Wsum,
                                                    const float* __restrict__ Wbias,
                                                    float* __restrict__ b0,
                                                    float* __restrict__ b1) {
    __shared__ float zs[128 * 65];
    __shared__ float wsm[32 * 65];
    __shared__ float asm_[32], bsm[32];
    __shared__ float stat[128 * 2];
    int tid = threadIdx.x;
    long long base = (long long)blockIdx.x * 128 * 64;
    #pragma unroll
    for (int i = 0; i < 8; i++) {
        int idx = tid + i * 256;              // float4 index
        int r = idx >> 4, c = (idx & 15) * 4;
        float4 v = *(const float4*)&z[base + (long long)idx * 4];
        zs[r * 65 + c] = v.x; zs[r * 65 + c + 1] = v.y;
        zs[r * 65 + c + 2] = v.z; zs[r * 65 + c + 3] = v.w;
    }
    #pragma unroll
    for (int i = 0; i < 8; i++) {
        int idx = tid + i * 256;
        int lh = idx >> 6, c = idx & 63;
        wsm[lh * 65 + c] = Wp[idx];
    }
    if (tid < 32) { asm_[tid] = Wsum[tid]; bsm[tid] = Wbias[tid]; }
    __syncthreads();
    if (tid < 128) {
        float s = 0.f, s2 = 0.f;
        #pragma unroll 8
        for (int c = 0; c < 64; c++) { float v = zs[tid * 65 + c]; s += v; s2 += v * v; }
        float m = s * (1.f / 64.f);
        float var = s2 * (1.f / 64.f) - m * m;
        stat[tid * 2] = m;
        stat[tid * 2 + 1] = rsqrtf(var + 1e-5f);
    }
    __syncthreads();
    int tx = tid & 7, ty = tid >> 3;
    float acc[4][4] = {};
    #pragma unroll 8
    for (int k = 0; k < 64; k++) {
        float a[4], b[4];
        #pragma unroll
        for (int i = 0; i < 4; i++) a[i] = zs[(ty * 4 + i) * 65 + k];
        #pragma unroll
        for (int j = 0; j < 4; j++) b[j] = wsm[(tx * 4 + j) * 65 + k];
        #pragma unroll
        for (int i = 0; i < 4; i++)
            #pragma unroll
            for (int j = 0; j < 4; j++) acc[i][j] += a[i] * b[j];
    }
    long long rowg0 = (long long)blockIdx.x * 128;
    #pragma unroll
    for (int i = 0; i < 4; i++) {
        int rl = ty * 4 + i;
        long long rg = rowg0 + rl;
        float m = stat[rl * 2], rs = stat[rl * 2 + 1];
        #pragma unroll
        for (int j = 0; j < 4; j++) {
            int col = tx * 4 + j;
            float val = rs * (acc[i][j] - m * asm_[col]) + bsm[col];
            float* dst = (col < 16) ? b0 : b1;
            dst[rg * 16 + (col & 15)] = val;
        }
    }
}

// ---------------------------------------------------------------------------
// Tensor-core bf16 GEMM:  C[m,n] = sum_k A[m,k] * B[n,k]   (NT by default)
//   TA: A[m,k] stored at A[k*lda + m]     (P^T in attention-o)
//   TB: B[n,k] stored at B[k*ldb + n]     (V in attention-o)
//   DUAL: second B matrix, second accumulator (adaLN / SwiGLU)
// Block tile 128x64, BK=32, 256 threads (8 warps, 4x2), warp tile 32x32.
// mma.sync.m16n8k16 bf16->fp32. Requires M%128==0, K even.
// smem rows padded to 40 bf16 (20 words) -> conflict-free frag loads.
// ---------------------------------------------------------------------------
enum { EPI_PLAIN = 0, EPI_SCORES = 1, EPI_GSIG = 2, EPI_OUTGATE = 3,
       EPI_TRFIN = 4, EPI_ADALN = 5, EPI_GLU = 6 };

#define PITCH 40   // bf16 elements per smem row (20 x 32-bit words)

template <int EPI, bool TA, bool TB, bool DUAL>
__global__ void __launch_bounds__(256) gemm_tc(
    const float* __restrict__ A, const float* __restrict__ B1,
    const float* __restrict__ B2, const float* __restrict__ bias,
    const float* __restrict__ ascale, const float* __restrict__ aux,
    const float* __restrict__ aux2, float* __restrict__ Cp,
    int M, int N, int K, int lda, int ldb, int ldc, int aux_ld,
    long long sA, long long sB, long long sC, long long sAux, float alpha) {
    const int tid = threadIdx.x;
    const int lane = tid & 31, warp = tid >> 5;
    const int wm = warp >> 1, wn = warp & 1;       // 4 x 2 warp grid
    const int bm = blockIdx.y * 128, bn = blockIdx.x * 64;
    const int bz = blockIdx.z;
    A += bz * sA;
    B1 += bz * sB;
    if constexpr (DUAL) B2 += bz * sB;
    Cp += bz * sC;
    if (aux) aux += bz * sAux;

    __shared__ __nv_bfloat16 As[128][PITCH];
    __shared__ __nv_bfloat16 Bs1[64][PITCH];
    __shared__ __nv_bfloat16 Bs2[DUAL ? 64 : 1][PITCH];

    float acc1[2][4][4] = {};
    float acc2[2][4][4] = {};

    const int qr = lane >> 2, qc = lane & 3;       // quad row / col

    for (int k0 = 0; k0 < K; k0 += 32) {
        // ---- load A tile 128x32 ----
        if constexpr (!TA) {
            #pragma unroll
            for (int i = 0; i < 8; i++) {
                int idx = tid + i * 256;            // float2 pair index
                int r = idx >> 4, kp = idx & 15;
                int kk = k0 + kp * 2;
                float2 v = make_float2(0.f, 0.f);
                if (kk < K) v = *(const float2*)&A[(long long)(bm + r) * lda + kk];
                if (ascale) { v.x *= ascale[kk]; v.y *= ascale[kk + 1]; }
                *(__nv_bfloat162*)&As[r][kp * 2] = __floats2bfloat162_rn(v.x, v.y);
            }
        } else {
            #pragma unroll
            for (int i = 0; i < 16; i++) {
                int idx = tid + i * 256;
                int m = idx & 127, kk = idx >> 7;
                float v = (k0 + kk < K) ? A[(long long)(k0 + kk) * lda + (bm + m)] : 0.f;
                As[m][kk] = __float2bfloat16_rn(v);
            }
        }
        // ---- load B tile(s) 64x32 ----
        if constexpr (!TB) {
            #pragma unroll
            for (int i = 0; i < 4; i++) {
                int idx = tid + i * 256;
                int n = idx >> 4, kp = idx & 15;
                int kk = k0 + kp * 2;
                int gn = bn + n;
                float2 v = make_float2(0.f, 0.f);
                if (gn < N && kk < K) v = *(const float2*)&B1[(long long)gn * ldb + kk];
                *(__nv_bfloat162*)&Bs1[n][kp * 2] = __floats2bfloat162_rn(v.x, v.y);
                if constexpr (DUAL) {
                    float2 w = make_float2(0.f, 0.f);
                    if (gn < N && kk < K) w = *(const float2*)&B2[(long long)gn * ldb + kk];
                    *(__nv_bfloat162*)&Bs2[n][kp * 2] = __floats2bfloat162_rn(w.x, w.y);
                }
            }
        } else {
            #pragma unroll
            for (int i = 0; i < 8; i++) {
                int idx = tid + i * 256;
                int n = idx & 63, kk = idx >> 6;
                int gn = bn + n;
                float v = (gn < N && k0 + kk < K) ? B1[(long long)(k0 + kk) * ldb + gn] : 0.f;
                Bs1[n][kk] = __float2bfloat16_rn(v);
            }
        }
        __syncthreads();

        #pragma unroll
        for (int ks = 0; ks < 2; ks++) {
            uint32_t af[2][4];
            #pragma unroll
            for (int i = 0; i < 2; i++) {
                int r = wm * 32 + i * 16 + qr;
                const uint32_t* arow  = (const uint32_t*)&As[r][0];
                const uint32_t* arow8 = (const uint32_t*)&As[r + 8][0];
                af[i][0] = arow[ks * 8 + qc];
                af[i][1] = arow8[ks * 8 + qc];
                af[i][2] = arow[ks * 8 + 4 + qc];
                af[i][3] = arow8[ks * 8 + 4 + qc];
            }
            #pragma unroll
            for (int j = 0; j < 4; j++) {
                int n = wn * 32 + j * 8 + qr;
                const uint32_t* brow = (const uint32_t*)&Bs1[n][0];
                uint32_t b0 = brow[ks * 8 + qc];
                uint32_t b1 = brow[ks * 8 + 4 + qc];
                #pragma unroll
                for (int i = 0; i < 2; i++) mma_bf16(acc1[i][j], af[i], b0, b1);
                if constexpr (DUAL) {
                    const uint32_t* brow2 = (const uint32_t*)&Bs2[n][0];
                    uint32_t c0 = brow2[ks * 8 + qc];
                    uint32_t c1 = brow2[ks * 8 + 4 + qc];
                    #pragma unroll
                    for (int i = 0; i < 2; i++) mma_bf16(acc2[i][j], af[i], c0, c1);
                }
            }
        }
        __syncthreads();
    }

    // ---- epilogue: map m16n8 C layout back to (m,n) ----
    #pragma unroll
    for (int i = 0; i < 2; i++) {
        #pragma unroll
        for (int j = 0; j < 4; j++) {
            int m0 = bm + wm * 32 + i * 16 + qr;
            int n0 = bn + wn * 32 + j * 8 + 2 * qc;
            #pragma unroll
            for (int e = 0; e < 4; e++) {
                int m = m0 + ((e >= 2) ? 8 : 0);
                int n = n0 + (e & 1);
                if (n >= N) continue;
                long long cidx = (long long)m * ldc + n;
                float v = acc1[i][j][e];
                float out;
                if constexpr (EPI == EPI_PLAIN) {
                    out = v + (bias ? bias[n] : 0.f);
                } else if constexpr (EPI == EPI_SCORES) {
                    out = v * alpha + Cp[cidx];                       // in-place += bias
                } else if constexpr (EPI == EPI_GSIG) {
                    out = sigf(aux[(long long)m * aux_ld + n]) * v;   // sigmoid(g) * o
                } else if constexpr (EPI == EPI_OUTGATE) {
                    out = sigf(v + bias[n]) * aux[(long long)m * aux_ld + n];
                } else if constexpr (EPI == EPI_TRFIN) {
                    out = aux2[(long long)m * aux_ld + n] +
                          sigf((v + bias[n]) * aux[(long long)m * aux_ld + n]);
                } else if constexpr (EPI == EPI_ADALN) {
                    out = sigf((v + bias[n]) * aux[(long long)m * aux_ld + n] + acc2[i][j][e]);
                } else {  // EPI_GLU: silu(acc1) * acc2
                    out = v * sigf(v) * acc2[i][j][e];
                }
                Cp[cidx] = out;
            }
        }
    }
}

// ---------------------------------------------------------------------------
// Host orchestration
// ---------------------------------------------------------------------------
extern "C" void kernel_launch(void* const* d_in, const int* in_sizes, int n_in,
                              void* d_out, int out_size) {
    const float* A0        = (const float*)d_in[0];
    const float* Sm        = (const float*)d_in[1];
    const float* Z         = (const float*)d_in[2];
    const float* attn_sn_w = (const float*)d_in[3];
    const float* attn_pb_w = (const float*)d_in[4];
    const float* attn_pb_b = (const float*)d_in[5];
    const float* attn_pnb_w= (const float*)d_in[6];
    const float* pair_w    = (const float*)d_in[7];
    const float* pair_b    = (const float*)d_in[8];
    const float* q_w       = (const float*)d_in[9];
    const float* q_b       = (const float*)d_in[10];
    const float* kvg_w     = (const float*)d_in[11];
    const float* bias_w    = (const float*)d_in[12];
    const float* bias_b    = (const float*)d_in[13];
    const float* ao_w      = (const float*)d_in[14];
    const float* out_w     = (const float*)d_in[15];
    const float* out_b     = (const float*)d_in[16];
    const float* tr_sn_w   = (const float*)d_in[17];
    const float* tr_pb_w   = (const float*)d_in[18];
    const float* tr_pb_b   = (const float*)d_in[19];
    const float* tr_pnb_w  = (const float*)d_in[20];
    const float* tr_a_w    = (const float*)d_in[21];
    const float* tr_s_w    = (const float*)d_in[22];
    const float* tr_s_b    = (const float*)d_in[23];
    const float* tr_b_w    = (const float*)d_in[24];
    float* OUT = (float*)d_out;

    float *b0, *b1, *shat, *an, *a2, *qf, *kvg, *ob, *amm, *aout, *bbuf, *tmm, *anew;
    float *wp, *wpsum, *wbias;
    cudaGetSymbolAddress((void**)&b0, g_b0);
    cudaGetSymbolAddress((void**)&b1, g_b1);
    cudaGetSymbolAddress((void**)&shat, g_shat);
    cudaGetSymbolAddress((void**)&an, g_an);
    cudaGetSymbolAddress((void**)&a2, g_a2);
    cudaGetSymbolAddress((void**)&qf, g_q);
    cudaGetSymbolAddress((void**)&kvg, g_kvg);
    cudaGetSymbolAddress((void**)&ob, g_o);
    cudaGetSymbolAddress((void**)&amm, g_amm);
    cudaGetSymbolAddress((void**)&aout, g_aout);
    cudaGetSymbolAddress((void**)&bbuf, g_bb);
    cudaGetSymbolAddress((void**)&tmm, g_tmm);
    cudaGetSymbolAddress((void**)&anew, g_anew);
    cudaGetSymbolAddress((void**)&wp, g_wp);
    cudaGetSymbolAddress((void**)&wpsum, g_wpsum);
    cudaGetSymbolAddress((void**)&wbias, g_wbias);

    // s is layer-invariant: LN once
    ln_kernel<<<S_, 256>>>(Sm, shat, CS_);
    // z -> both layers' flat attention-bias arrays (reads z once)
    zprep_kernel<<<1, 32>>>(pair_w, pair_b, bias_w, bias_b, wp, wpsum, wbias);
    zproj_kernel<<<(S_ * S_) / 128, 256>>>(Z, wp, wpsum, wbias, b0, b1);

    for (int l = 0; l < 2; l++) {
        const float* ain = l ? anew : A0;
        float* aoutp = l ? OUT : anew;
        float* bf = l ? b1 : b0;
        long long lw = (long long)l;

        ln_kernel<<<S_, 256>>>(ain, an, CA_);

        // adaLN (attention branch): a2 = sigmoid((sn@pbW^T + pb_b)*an + sn@pnbW^T)
        gemm_tc<EPI_ADALN, false, false, true><<<dim3(12, 8, 1), 256>>>(
            shat, attn_pb_w + lw * CA_ * CS_, attn_pnb_w + lw * CA_ * CS_,
            attn_pb_b + lw * CA_, attn_sn_w + lw * CS_, an, nullptr,
            a2, S_, CA_, CS_, CS_, CS_, CA_, CA_, 0, 0, 0, 0, 1.f);

        // q = a2 @ q_w^T + q_b
        gemm_tc<EPI_PLAIN, false, false, false><<<dim3(12, 8, 1), 256>>>(
            a2, q_w + lw * CA_ * CA_, nullptr, q_b + lw * CA_, nullptr, nullptr, nullptr,
            qf, S_, CA_, CA_, CA_, CA_, CA_, 0, 0, 0, 0, 0, 1.f);

        // kvg = a2 @ kvg_w^T
        gemm_tc<EPI_PLAIN, false, false, false><<<dim3(36, 8, 1), 256>>>(
            a2, kvg_w + lw * 3 * CA_ * CA_, nullptr, nullptr, nullptr, nullptr, nullptr,
            kvg, S_, 3 * CA_, CA_, CA_, CA_, 3 * CA_, 0, 0, 0, 0, 0, 1.f);

        // scores[h,r,t] = dot(k[h,r], q[h,t]) / 48 + bflat[h,r,t]   (in place)
        gemm_tc<EPI_SCORES, false, false, false><<<dim3(16, 8, 16), 256>>>(
            kvg, qf, nullptr, nullptr, nullptr, nullptr, nullptr,
            bf, S_, S_, CH_, C3_, CH_, S_, 0,
            (long long)S_ * C3_, (long long)S_ * CH_, (long long)S_ * S_, 0, 1.f / 48.f);

        // softmax over last axis (t), rows = H*S
        softmax_kernel<<<H_ * S_, 256>>>(bf);

        // o[h,j,c] = sum_r P[h,r,j]*v[h,r,c];  fused: sigmoid(g[h,j,c]) * o
        gemm_tc<EPI_GSIG, true, true, false><<<dim3(1, 8, 16), 256>>>(
            bf, kvg + CH_, nullptr, nullptr, nullptr, kvg + 2 * CH_, nullptr,
            ob, S_, CH_, S_, S_, C3_, CH_, C3_,
            (long long)S_ * S_, (long long)S_ * C3_, (long long)S_ * CH_,
            (long long)S_ * C3_, 1.f);

        // attn_mm = (sig(g)*o) @ ao_w^T
        gemm_tc<EPI_PLAIN, false, false, false><<<dim3(12, 8, 1), 256>>>(
            ob, ao_w + lw * CA_ * CA_, nullptr, nullptr, nullptr, nullptr, nullptr,
            amm, S_, CA_, CA_, CA_, CA_, CA_, 0, 0, 0, 0, 0, 1.f);

        // attn_out = sigmoid(s @ out_w^T + out_b) * attn_mm
        gemm_tc<EPI_OUTGATE, false, false, false><<<dim3(12, 8, 1), 256>>>(
            Sm, out_w + lw * CA_ * CS_, nullptr, out_b + lw * CA_, nullptr, amm, nullptr,
            aout, S_, CA_, CS_, CS_, CS_, CA_, CA_, 0, 0, 0, 0, 1.f);

        // adaLN (transition branch) -> a3 (reuse a2)
        gemm_tc<EPI_ADALN, false, false, true><<<dim3(12, 8, 1), 256>>>(
            shat, tr_pb_w + lw * CA_ * CS_, tr_pnb_w + lw * CA_ * CS_,
            tr_pb_b + lw * CA_, tr_sn_w + lw * CS_, an, nullptr,
            a2, S_, CA_, CS_, CS_, CS_, CA_, CA_, 0, 0, 0, 0, 1.f);

        // bb = silu(a3 @ W1^T) * (a3 @ W2^T)   (tr_a_w split in half)
        gemm_tc<EPI_GLU, false, false, true><<<dim3(24, 8, 1), 256>>>(
            a2, tr_a_w + lw * 4 * CA_ * CA_, tr_a_w + lw * 4 * CA_ * CA_ + (long long)2 * CA_ * CA_,
            nullptr, nullptr, nullptr, nullptr,
            bbuf, S_, 2 * CA_, CA_, CA_, CA_, 2 * CA_, 0, 0, 0, 0, 0, 1.f);

        // tmm = bb @ tr_b_w^T
        gemm_tc<EPI_PLAIN, false, false, false><<<dim3(12, 8, 1), 256>>>(
            bbuf, tr_b_w + lw * CA_ * 2 * CA_, nullptr, nullptr, nullptr, nullptr, nullptr,
            tmm, S_, CA_, 2 * CA_, 2 * CA_, 2 * CA_, CA_, 0, 0, 0, 0, 0, 1.f);

        // a_next = attn_out + sigmoid((s @ tr_s_w^T + tr_s_b) * tmm)
        gemm_tc<EPI_TRFIN, false, false, false><<<dim3(12, 8, 1), 256>>>(
            Sm, tr_s_w + lw * CA_ * CS_, nullptr, tr_s_b + lw * CA_, nullptr, tmm, aout,
            aoutp, S_, CA_, CS_, CS_, CS_, CA_, CA_, 0, 0, 0, 0, 1.f);
    }
}

// round 5
// speedup vs baseline: 2.4182x; 1.3087x over previous
#include <cuda_runtime.h>
#include <cuda_bf16.h>
#include <math.h>
#include <stdint.h>

// Problem constants
#define S_   1024
#define CA_  768
#define CS_  384
#define CZ_  64
#define H_   16
#define CH_  48     // head dim
#define C3_  144    // 3*CH

// ---------------------------------------------------------------------------
// Static scratch (device globals — no cudaMalloc allowed)
// ---------------------------------------------------------------------------
__device__ float g_b0[16 * 1024 * 1024];   // layer-0 bias/scores (64 MiB)
__device__ float g_b1[16 * 1024 * 1024];   // layer-1 bias/scores (64 MiB)
__device__ float g_an[S_ * CA_];           // LN(a) per layer (fp32 aux)
__device__ float g_amm[S_ * CA_];          // attn @ ao_w^T
__device__ float g_aout[S_ * CA_];         // gated attention output
__device__ float g_tmm[S_ * CA_];          // bb @ tr_b_w^T
__device__ float g_anew[S_ * CA_];         // a after layer 0
__device__ float g_wbias[32];

__device__ __align__(16) __nv_bfloat16 g_wbf[16908288];   // all weights + s, bf16
__device__ __align__(16) __nv_bfloat16 g_shatb[S_ * CS_];
__device__ __align__(16) __nv_bfloat16 g_a2b[S_ * CA_];
__device__ __align__(16) __nv_bfloat16 g_qb[S_ * CA_];
__device__ __align__(16) __nv_bfloat16 g_kvgb[S_ * 3 * CA_];
__device__ __align__(16) __nv_bfloat16 g_obb[S_ * CA_];
__device__ __align__(16) __nv_bfloat16 g_bbb[S_ * 2 * CA_];
__device__ __align__(16) __nv_bfloat16 g_pbf[H_ * S_ * S_];  // softmax P (32 MiB)
__device__ __align__(16) __nv_bfloat16 g_wpbf[32 * 64];      // folded z-proj weights

// ---------------------------------------------------------------------------
// Helpers
// ---------------------------------------------------------------------------
__device__ __forceinline__ float sigf(float x) { return 1.0f / (1.0f + expf(-x)); }

__device__ __forceinline__ void mma_bf16(float* d, const uint32_t* a,
                                         uint32_t b0, uint32_t b1) {
    asm volatile(
        "mma.sync.aligned.m16n8k16.row.col.f32.bf16.bf16.f32 "
        "{%0,%1,%2,%3}, {%4,%5,%6,%7}, {%8,%9}, {%0,%1,%2,%3};"
        : "+f"(d[0]), "+f"(d[1]), "+f"(d[2]), "+f"(d[3])
        : "r"(a[0]), "r"(a[1]), "r"(a[2]), "r"(a[3]), "r"(b0), "r"(b1));
}

__device__ __forceinline__ void cp16(uint32_t smem, const void* g, int sbytes) {
    asm volatile("cp.async.cg.shared.global [%0], [%1], 16, %2;\n"
                 :: "r"(smem), "l"(g), "r"(sbytes));
}
#define CP_COMMIT() asm volatile("cp.async.commit_group;\n" ::)

__device__ __forceinline__ float toF(float v) { return v; }
__device__ __forceinline__ float toF(__nv_bfloat16 v) { return __bfloat162float(v); }
__device__ __forceinline__ void storeOut(float v, float* p) { *p = v; }
__device__ __forceinline__ void storeOut(float v, __nv_bfloat16* p) { *p = __float2bfloat16_rn(v); }

// block = 256 threads
__device__ __forceinline__ float blk_sum(float v, float* red) {
    int tid = threadIdx.x, lane = tid & 31;
    #pragma unroll
    for (int o = 16; o; o >>= 1) v += __shfl_xor_sync(0xffffffffu, v, o);
    if (lane == 0) red[tid >> 5] = v;
    __syncthreads();
    if (tid < 32) {
        float t = (tid < 8) ? red[tid] : 0.f;
        #pragma unroll
        for (int o = 4; o; o >>= 1) t += __shfl_xor_sync(0xffffffffu, t, o);
        if (tid == 0) red[0] = t;
    }
    __syncthreads();
    v = red[0];
    __syncthreads();
    return v;
}

// ---------------------------------------------------------------------------
// Weight/act conversion fp32 -> bf16 (optionally scaling columns by scl[c])
// ---------------------------------------------------------------------------
struct CvtArgs {
    const float* src[24];
    const float* scl[24];
    __nv_bfloat16* dst[24];
    int len[24];
    int smod;
    int nseg;
};

__global__ void __launch_bounds__(256) cvt_kernel(CvtArgs a) {
    int s = blockIdx.y;
    if (s >= a.nseg) return;
    const float* src = a.src[s];
    const float* scl = a.scl[s];
    __nv_bfloat16* dst = a.dst[s];
    int n = a.len[s];
    for (long long i = (long long)(blockIdx.x * 256 + threadIdx.x) * 2; i < n;
         i += (long long)gridDim.x * 512) {
        float2 v = *(const float2*)&src[i];
        if (scl) { int c = (int)(i % a.smod); v.x *= scl[c]; v.y *= scl[c + 1]; }
        *(__nv_bfloat162*)&dst[i] = __floats2bfloat162_rn(v.x, v.y);
    }
}

// ---------------------------------------------------------------------------
// LayerNorm (no affine): one block per row, 256 threads, W <= 768
// ---------------------------------------------------------------------------
template <typename OutT>
__global__ void __launch_bounds__(256) ln_kernel(const float* __restrict__ x,
                                                 OutT* __restrict__ y, int W) {
    __shared__ float red[32];
    long long row = blockIdx.x;
    const float* xr = x + row * W;
    float loc[3];
    int cnt = 0;
    float s = 0.f;
    for (int i = threadIdx.x; i < W; i += 256) { float v = xr[i]; loc[cnt++] = v; s += v; }
    float mean = blk_sum(s, red) / (float)W;
    float vs = 0.f;
    for (int j = 0; j < cnt; j++) { float d = loc[j] - mean; vs += d * d; }
    float var = blk_sum(vs, red) / (float)W;
    float rstd = rsqrtf(var + 1e-5f);
    OutT* yr = y + row * W;
    int j = 0;
    for (int i = threadIdx.x; i < W; i += 256) storeOut((loc[j++] - mean) * rstd, &yr[i]);
}

// ---------------------------------------------------------------------------
// In-place-read softmax: fp32 scores -> bf16 P.  Rows of 1024, H*S rows.
// ---------------------------------------------------------------------------
__global__ void __launch_bounds__(256) softmax_kernel(const float* __restrict__ sc,
                                                      __nv_bfloat16* __restrict__ P) {
    __shared__ float red[32];
    long long row = blockIdx.x;
    const float4* x = (const float4*)(sc + row * 1024);
    int tid = threadIdx.x, lane = tid & 31;
    float4 v = x[tid];
    float mx = fmaxf(fmaxf(v.x, v.y), fmaxf(v.z, v.w));
    #pragma unroll
    for (int o = 16; o; o >>= 1) mx = fmaxf(mx, __shfl_xor_sync(0xffffffffu, mx, o));
    if (lane == 0) red[tid >> 5] = mx;
    __syncthreads();
    if (tid < 32) {
        float t = (tid < 8) ? red[tid] : -1e30f;
        #pragma unroll
        for (int o = 4; o; o >>= 1) t = fmaxf(t, __shfl_xor_sync(0xffffffffu, t, o));
        if (tid == 0) red[0] = t;
    }
    __syncthreads();
    mx = red[0];
    __syncthreads();
    v.x = expf(v.x - mx); v.y = expf(v.y - mx);
    v.z = expf(v.z - mx); v.w = expf(v.w - mx);
    float tot = blk_sum(v.x + v.y + v.z + v.w, red);
    float inv = 1.0f / tot;
    __nv_bfloat162* o2 = (__nv_bfloat162*)(P + row * 1024);
    o2[tid * 2]     = __floats2bfloat162_rn(v.x * inv, v.y * inv);
    o2[tid * 2 + 1] = __floats2bfloat162_rn(v.z * inv, v.w * inv);
}

// ---------------------------------------------------------------------------
// z projection prep: Wp[lh,c] = bf16(pair_w[l,c]*bias_w[l,h,c]);
// Wbias[lh] = sum_c pair_b[l,c]*bias_w[l,h,c] + bias_b[l,h]
// ---------------------------------------------------------------------------
__global__ void zprep_kernel(const float* __restrict__ pw, const float* __restrict__ pb,
                             const float* __restrict__ bw, const float* __restrict__ bb,
                             __nv_bfloat16* __restrict__ Wp, float* __restrict__ Wbias) {
    int lh = threadIdx.x;
    if (lh >= 32) return;
    int l = lh >> 4;
    float bs = 0.f;
    for (int c = 0; c < 64; c++) {
        float w = bw[lh * 64 + c];
        Wp[lh * 64 + c] = __float2bfloat16_rn(pw[l * 64 + c] * w);
        bs += pb[l * 64 + c] * w;
    }
    Wbias[lh] = bs + bb[lh];
}

// ---------------------------------------------------------------------------
// z projection on tensor cores: per block: 128 z-rows LN'd (fp32 stats) ->
// bf16, mma (128x32x64) with Wp, + Wbias -> both layers' flat bias arrays.
// ---------------------------------------------------------------------------
__global__ void __launch_bounds__(256) zproj_kernel(const float* __restrict__ z,
                                                    const __nv_bfloat16* __restrict__ Wp,
                                                    const float* __restrict__ Wbias,
                                                    float* __restrict__ b0,
                                                    float* __restrict__ b1) {
    __shared__ __nv_bfloat16 zb[128][72];
    __shared__ __nv_bfloat16 wsm[32][72];
    __shared__ float bsm[32];
    int tid = threadIdx.x;
    int row = tid >> 1, half = tid & 1;
    long long base = (long long)blockIdx.x * 8192 + (long long)row * 64 + half * 32;
    float v[32];
    #pragma unroll
    for (int i = 0; i < 8; i++) {
        float4 t = *(const float4*)&z[base + i * 4];
        v[i * 4] = t.x; v[i * 4 + 1] = t.y; v[i * 4 + 2] = t.z; v[i * 4 + 3] = t.w;
    }
    float s = 0.f, s2 = 0.f;
    #pragma unroll
    for (int i = 0; i < 32; i++) { s += v[i]; s2 += v[i] * v[i]; }
    s  += __shfl_xor_sync(0xffffffffu, s, 1);
    s2 += __shfl_xor_sync(0xffffffffu, s2, 1);
    float m = s * (1.f / 64.f);
    float rs = rsqrtf(s2 * (1.f / 64.f) - m * m + 1e-5f);
    #pragma unroll
    for (int i = 0; i < 16; i++) {
        *(__nv_bfloat162*)&zb[row][half * 32 + 2 * i] =
            __floats2bfloat162_rn((v[2 * i] - m) * rs, (v[2 * i + 1] - m) * rs);
    }
    #pragma unroll
    for (int i = 0; i < 8; i++) {
        int idx = tid + i * 256;
        wsm[idx >> 6][idx & 63] = Wp[idx];
    }
    if (tid < 32) bsm[tid] = Wbias[tid];
    __syncthreads();

    int w = tid >> 5, lane = tid & 31, qr = lane >> 2, qc = lane & 3;
    float acc[4][4] = {};
    const uint32_t* zw = (const uint32_t*)&zb[0][0];    // word pitch 36
    const uint32_t* ww = (const uint32_t*)&wsm[0][0];
    #pragma unroll
    for (int kc = 0; kc < 4; kc++) {
        uint32_t af[4];
        int r = w * 16 + qr;
        af[0] = zw[r * 36 + kc * 8 + qc];
        af[1] = zw[(r + 8) * 36 + kc * 8 + qc];
        af[2] = zw[r * 36 + kc * 8 + 4 + qc];
        af[3] = zw[(r + 8) * 36 + kc * 8 + 4 + qc];
        #pragma unroll
        for (int j = 0; j < 4; j++) {
            int n = j * 8 + qr;
            mma_bf16(acc[j], af, ww[n * 36 + kc * 8 + qc], ww[n * 36 + kc * 8 + 4 + qc]);
        }
    }
    long long rg0 = (long long)blockIdx.x * 128;
    #pragma unroll
    for (int j = 0; j < 4; j++) {
        #pragma unroll
        for (int e = 0; e < 4; e++) {
            int mm = w * 16 + qr + ((e >= 2) ? 8 : 0);
            int n = j * 8 + 2 * qc + (e & 1);
            float val = acc[j][e] + bsm[n];
            float* dst = (n < 16) ? b0 : b1;
            dst[(rg0 + mm) * 16 + (n & 15)] = val;
        }
    }
}

// ---------------------------------------------------------------------------
// Tensor-core bf16 GEMM:  C[m,n] = sum_k A[m,k] * B[n,k]   (NT by default)
// All operands bf16 in global.  NT path: cp.async multi-stage pipeline.
// TA/TB (legacy, PV only): register-double-buffered synchronous loads.
// Block tile 128x64, BK=32, 256 threads (8 warps, 4x2), warp tile 32x32.
// Requires M%128==0, N%64==0 on async path; K%8==0.
// ---------------------------------------------------------------------------
enum { EPI_PLAIN = 0, EPI_SCORES = 1, EPI_GSIG = 2, EPI_OUTGATE = 3,
       EPI_TRFIN = 4, EPI_ADALN = 5, EPI_GLU = 6 };

template <int EPI, bool TA, bool TB, bool DUAL, typename OutT, typename AuxT>
__global__ void __launch_bounds__(256) gemm_tc(
    const __nv_bfloat16* __restrict__ A, const __nv_bfloat16* __restrict__ B1,
    const __nv_bfloat16* __restrict__ B2, const float* __restrict__ bias,
    const AuxT* __restrict__ aux, const float* __restrict__ aux2,
    OutT* __restrict__ Cp, const float* __restrict__ CpIn,
    int M, int N, int K, int lda, int ldb, int ldc, int aux_ld,
    long long sA, long long sB, long long sC, long long sAux, float alpha) {
    constexpr int NST = DUAL ? 2 : 3;
    const int tid = threadIdx.x;
    const int lane = tid & 31, warp = tid >> 5;
    const int wm = warp >> 1, wn = warp & 1;       // 4 x 2 warp grid
    const int bm = blockIdx.y * 128, bn = blockIdx.x * 64;
    const int bz = blockIdx.z;
    A += bz * sA;
    B1 += bz * sB;
    if constexpr (DUAL) B2 += bz * sB;
    Cp += bz * sC;
    if (CpIn) CpIn += bz * sC;
    if (aux) aux += bz * sAux;

    __shared__ __nv_bfloat16 As[NST][128][40];
    __shared__ __nv_bfloat16 Bs1[NST][64][40];
    __shared__ __nv_bfloat16 Bs2[DUAL ? NST : 1][64][40];

    float acc1[2][4][4] = {};
    float acc2[2][4][4] = {};
    const int qr = lane >> 2, qc = lane & 3;
    const int nk = (K + 31) / 32;

    // fragment-MMA over one stage
    auto do_mma = [&](int st) {
        #pragma unroll
        for (int ks = 0; ks < 2; ks++) {
            uint32_t af[2][4];
            #pragma unroll
            for (int i = 0; i < 2; i++) {
                int r = wm * 32 + i * 16 + qr;
                const uint32_t* arow  = (const uint32_t*)&As[st][r][0];
                const uint32_t* arow8 = (const uint32_t*)&As[st][r + 8][0];
                af[i][0] = arow[ks * 8 + qc];
                af[i][1] = arow8[ks * 8 + qc];
                af[i][2] = arow[ks * 8 + 4 + qc];
                af[i][3] = arow8[ks * 8 + 4 + qc];
            }
            #pragma unroll
            for (int j = 0; j < 4; j++) {
                int n = wn * 32 + j * 8 + qr;
                const uint32_t* brow = (const uint32_t*)&Bs1[st][n][0];
                uint32_t b0 = brow[ks * 8 + qc];
                uint32_t b1 = brow[ks * 8 + 4 + qc];
                #pragma unroll
                for (int i = 0; i < 2; i++) mma_bf16(acc1[i][j], af[i], b0, b1);
                if constexpr (DUAL) {
                    const uint32_t* brow2 = (const uint32_t*)&Bs2[st][n][0];
                    uint32_t c0 = brow2[ks * 8 + qc];
                    uint32_t c1 = brow2[ks * 8 + 4 + qc];
                    #pragma unroll
                    for (int i = 0; i < 2; i++) mma_bf16(acc2[i][j], af[i], c0, c1);
                }
            }
        }
    };

    if constexpr (!TA && !TB) {
        // ---------------- async pipelined path ----------------
        uint32_t aBase = (uint32_t)__cvta_generic_to_shared(&As[0][0][0]);
        uint32_t bBase = (uint32_t)__cvta_generic_to_shared(&Bs1[0][0][0]);
        uint32_t b2Base = 0;
        if constexpr (DUAL) b2Base = (uint32_t)__cvta_generic_to_shared(&Bs2[0][0][0]);

        auto issue = [&](int st, int k0) {
            #pragma unroll
            for (int i = 0; i < 2; i++) {
                int id = tid + i * 256;
                int r = id >> 2, cp4 = id & 3;
                int kk = k0 + cp4 * 8;
                const __nv_bfloat16* src = A + (long long)(bm + r) * lda + kk;
                int sb = (kk < K) ? 16 : 0;
                if (!sb) src = A;
                cp16(aBase + st * 128 * 80 + r * 80 + cp4 * 16, src, sb);
            }
            {
                int r = tid >> 2, cp4 = tid & 3;
                int kk = k0 + cp4 * 8;
                int sb = (kk < K) ? 16 : 0;
                const __nv_bfloat16* src = B1 + (long long)(bn + r) * ldb + kk;
                if (!sb) src = B1;
                cp16(bBase + st * 64 * 80 + r * 80 + cp4 * 16, src, sb);
                if constexpr (DUAL) {
                    const __nv_bfloat16* src2 = B2 + (long long)(bn + r) * ldb + kk;
                    if (!sb) src2 = B2;
                    cp16(b2Base + st * 64 * 80 + r * 80 + cp4 * 16, src2, sb);
                }
            }
        };

        #pragma unroll
        for (int p = 0; p < NST - 1; p++) {
            if (p < nk) issue(p, p * 32);
            CP_COMMIT();
        }
        for (int ic = 0; ic < nk; ic++) {
            int pn = ic + NST - 1;
            if (pn < nk) issue(pn % NST, pn * 32);
            CP_COMMIT();
            if constexpr (NST == 3) asm volatile("cp.async.wait_group 2;\n" ::);
            else                    asm volatile("cp.async.wait_group 1;\n" ::);
            __syncthreads();
            do_mma(ic % NST);
            __syncthreads();
        }
    } else {
        // ---------------- legacy path with register double buffer ----------
        __nv_bfloat16 ra[16], rb[8];
        const __nv_bfloat16 z0 = __float2bfloat16(0.f);
        auto loadA = [&](int k0) {
            #pragma unroll
            for (int i = 0; i < 16; i++) {
                int idx = tid + i * 256;
                int mm = idx & 127, kk = idx >> 7;
                if constexpr (TA)
                    ra[i] = (k0 + kk < K) ? A[(long long)(k0 + kk) * lda + (bm + mm)] : z0;
                else
                    ra[i] = (k0 + kk < K) ? A[(long long)(bm + mm) * lda + (k0 + kk)] : z0;
            }
        };
        auto loadB = [&](int k0) {
            #pragma unroll
            for (int i = 0; i < 8; i++) {
                int idx = tid + i * 256;
                int n = idx & 63, kk = idx >> 6;
                int gn = bn + n;
                if constexpr (TB)
                    rb[i] = (gn < N && k0 + kk < K) ? B1[(long long)(k0 + kk) * ldb + gn] : z0;
                else
                    rb[i] = (gn < N && k0 + kk < K) ? B1[(long long)gn * ldb + (k0 + kk)] : z0;
            }
        };
        loadA(0); loadB(0);
        for (int ic = 0; ic < nk; ic++) {
            #pragma unroll
            for (int i = 0; i < 16; i++) {
                int idx = tid + i * 256;
                As[0][idx & 127][idx >> 7] = ra[i];
            }
            #pragma unroll
            for (int i = 0; i < 8; i++) {
                int idx = tid + i * 256;
                Bs1[0][idx & 63][idx >> 6] = rb[i];
            }
            __syncthreads();
            if (ic + 1 < nk) { loadA((ic + 1) * 32); loadB((ic + 1) * 32); }
            do_mma(0);
            __syncthreads();
        }
    }

    // ---- epilogue: map m16n8 C layout back to (m,n) ----
    #pragma unroll
    for (int i = 0; i < 2; i++) {
        #pragma unroll
        for (int j = 0; j < 4; j++) {
            int m0 = bm + wm * 32 + i * 16 + qr;
            int n0 = bn + wn * 32 + j * 8 + 2 * qc;
            #pragma unroll
            for (int e = 0; e < 4; e++) {
                int m = m0 + ((e >= 2) ? 8 : 0);
                int n = n0 + (e & 1);
                if (n >= N) continue;
                long long cidx = (long long)m * ldc + n;
                float v = acc1[i][j][e];
                float out;
                if constexpr (EPI == EPI_PLAIN) {
                    out = v + (bias ? bias[n] : 0.f);
                } else if constexpr (EPI == EPI_SCORES) {
                    out = v * alpha + CpIn[cidx];                     // += bias (in place)
                } else if constexpr (EPI == EPI_GSIG) {
                    out = sigf(toF(aux[(long long)m * aux_ld + n])) * v;
                } else if constexpr (EPI == EPI_OUTGATE) {
                    out = sigf(v + bias[n]) * toF(aux[(long long)m * aux_ld + n]);
                } else if constexpr (EPI == EPI_TRFIN) {
                    out = aux2[(long long)m * aux_ld + n] +
                          sigf((v + bias[n]) * toF(aux[(long long)m * aux_ld + n]));
                } else if constexpr (EPI == EPI_ADALN) {
                    out = sigf((v + bias[n]) * toF(aux[(long long)m * aux_ld + n]) + acc2[i][j][e]);
                } else {  // EPI_GLU
                    out = v * sigf(v) * acc2[i][j][e];
                }
                storeOut(out, &Cp[cidx]);
            }
        }
    }
}

// ---------------------------------------------------------------------------
// Host orchestration
// ---------------------------------------------------------------------------
extern "C" void kernel_launch(void* const* d_in, const int* in_sizes, int n_in,
                              void* d_out, int out_size) {
    const float* A0        = (const float*)d_in[0];
    const float* Sm        = (const float*)d_in[1];
    const float* Z         = (const float*)d_in[2];
    const float* attn_sn_w = (const float*)d_in[3];
    const float* attn_pb_w = (const float*)d_in[4];
    const float* attn_pb_b = (const float*)d_in[5];
    const float* attn_pnb_w= (const float*)d_in[6];
    const float* pair_w    = (const float*)d_in[7];
    const float* pair_b    = (const float*)d_in[8];
    const float* q_w       = (const float*)d_in[9];
    const float* q_b       = (const float*)d_in[10];
    const float* kvg_w     = (const float*)d_in[11];
    const float* bias_w    = (const float*)d_in[12];
    const float* bias_b    = (const float*)d_in[13];
    const float* ao_w      = (const float*)d_in[14];
    const float* out_w     = (const float*)d_in[15];
    const float* out_b     = (const float*)d_in[16];
    const float* tr_sn_w   = (const float*)d_in[17];
    const float* tr_pb_w   = (const float*)d_in[18];
    const float* tr_pb_b   = (const float*)d_in[19];
    const float* tr_pnb_w  = (const float*)d_in[20];
    const float* tr_a_w    = (const float*)d_in[21];
    const float* tr_s_w    = (const float*)d_in[22];
    const float* tr_s_b    = (const float*)d_in[23];
    const float* tr_b_w    = (const float*)d_in[24];
    float* OUT = (float*)d_out;

    float *b0, *b1, *an, *amm, *aout, *tmm, *anew, *wbias;
    __nv_bfloat16 *wbf, *shatb, *a2b, *qb, *kvgb, *obb, *bbb, *pbf, *wpbf;
    cudaGetSymbolAddress((void**)&b0, g_b0);
    cudaGetSymbolAddress((void**)&b1, g_b1);
    cudaGetSymbolAddress((void**)&an, g_an);
    cudaGetSymbolAddress((void**)&amm, g_amm);
    cudaGetSymbolAddress((void**)&aout, g_aout);
    cudaGetSymbolAddress((void**)&tmm, g_tmm);
    cudaGetSymbolAddress((void**)&anew, g_anew);
    cudaGetSymbolAddress((void**)&wbias, g_wbias);
    cudaGetSymbolAddress((void**)&wbf, g_wbf);
    cudaGetSymbolAddress((void**)&shatb, g_shatb);
    cudaGetSymbolAddress((void**)&a2b, g_a2b);
    cudaGetSymbolAddress((void**)&qb, g_qb);
    cudaGetSymbolAddress((void**)&kvgb, g_kvgb);
    cudaGetSymbolAddress((void**)&obb, g_obb);
    cudaGetSymbolAddress((void**)&bbb, g_bbb);
    cudaGetSymbolAddress((void**)&pbf, g_pbf);
    cudaGetSymbolAddress((void**)&wpbf, g_wpbf);

    // ---- build conversion table + record weight offsets ----
    CvtArgs ca;
    long long off = 0;
    int ns = 0;
    long long wo_pb[2], wo_pnb[2], wo_q[2], wo_kvg[2], wo_ao[2], wo_out[2];
    long long wo_trpb[2], wo_trpnb[2], wo_tra[2], wo_trs[2], wo_trb[2], wo_s;
    auto seg = [&](const float* s, int len, const float* sc) -> long long {
        ca.src[ns] = s; ca.scl[ns] = sc; ca.dst[ns] = wbf + off; ca.len[ns] = len;
        long long o = off; off += len; ns++; return o;
    };
    for (int l = 0; l < 2; l++) {
        wo_pb[l]    = seg(attn_pb_w  + (long long)l * CA_ * CS_, CA_ * CS_, attn_sn_w + l * CS_);
        wo_pnb[l]   = seg(attn_pnb_w + (long long)l * CA_ * CS_, CA_ * CS_, attn_sn_w + l * CS_);
        wo_q[l]     = seg(q_w   + (long long)l * CA_ * CA_, CA_ * CA_, nullptr);
        wo_kvg[l]   = seg(kvg_w + (long long)l * 3 * CA_ * CA_, 3 * CA_ * CA_, nullptr);
        wo_ao[l]    = seg(ao_w  + (long long)l * CA_ * CA_, CA_ * CA_, nullptr);
        wo_out[l]   = seg(out_w + (long long)l * CA_ * CS_, CA_ * CS_, nullptr);
        wo_trpb[l]  = seg(tr_pb_w  + (long long)l * CA_ * CS_, CA_ * CS_, tr_sn_w + l * CS_);
        wo_trpnb[l] = seg(tr_pnb_w + (long long)l * CA_ * CS_, CA_ * CS_, tr_sn_w + l * CS_);
        wo_tra[l]   = seg(tr_a_w + (long long)l * 4 * CA_ * CA_, 4 * CA_ * CA_, nullptr);
        wo_trs[l]   = seg(tr_s_w + (long long)l * CA_ * CS_, CA_ * CS_, nullptr);
        wo_trb[l]   = seg(tr_b_w + (long long)l * 2 * CA_ * CA_, 2 * CA_ * CA_, nullptr);
    }
    wo_s = seg(Sm, S_ * CS_, nullptr);
    ca.smod = CS_;
    ca.nseg = ns;

    cvt_kernel<<<dim3(128, ns), 256>>>(ca);
    ln_kernel<__nv_bfloat16><<<S_, 256>>>(Sm, shatb, CS_);
    zprep_kernel<<<1, 32>>>(pair_w, pair_b, bias_w, bias_b, wpbf, wbias);
    zproj_kernel<<<(S_ * S_) / 128, 256>>>(Z, wpbf, wbias, b0, b1);

    const __nv_bfloat16* s_bf = wbf + wo_s;

    for (int l = 0; l < 2; l++) {
        const float* ain = l ? anew : A0;
        float* aoutp = l ? OUT : anew;
        float* bf = l ? b1 : b0;

        ln_kernel<float><<<S_, 256>>>(ain, an, CA_);

        // adaLN (attention): a2 = sigmoid((sn@pbW^T + pb_b)*an + sn@pnbW^T)
        gemm_tc<EPI_ADALN, false, false, true, __nv_bfloat16, float><<<dim3(12, 8, 1), 256>>>(
            shatb, wbf + wo_pb[l], wbf + wo_pnb[l], attn_pb_b + (long long)l * CA_,
            an, nullptr, a2b, nullptr,
            S_, CA_, CS_, CS_, CS_, CA_, CA_, 0, 0, 0, 0, 1.f);

        // q = a2 @ q_w^T + q_b
        gemm_tc<EPI_PLAIN, false, false, false, __nv_bfloat16, float><<<dim3(12, 8, 1), 256>>>(
            a2b, wbf + wo_q[l], nullptr, q_b + (long long)l * CA_,
            nullptr, nullptr, qb, nullptr,
            S_, CA_, CA_, CA_, CA_, CA_, 0, 0, 0, 0, 0, 1.f);

        // kvg = a2 @ kvg_w^T
        gemm_tc<EPI_PLAIN, false, false, false, __nv_bfloat16, float><<<dim3(36, 8, 1), 256>>>(
            a2b, wbf + wo_kvg[l], nullptr, nullptr,
            nullptr, nullptr, kvgb, nullptr,
            S_, 3 * CA_, CA_, CA_, CA_, 3 * CA_, 0, 0, 0, 0, 0, 1.f);

        // scores[h,r,t] = dot(k[h,r], q[h,t]) / 48 + bias[h,r,t]   (in place)
        gemm_tc<EPI_SCORES, false, false, false, float, float><<<dim3(16, 8, 16), 256>>>(
            kvgb, qb, nullptr, nullptr, nullptr, nullptr, bf, bf,
            S_, S_, CH_, C3_, CH_, S_, 0,
            (long long)S_ * C3_, (long long)S_ * CH_, (long long)S_ * S_, 0, 1.f / 48.f);

        // softmax over last axis -> bf16 P
        softmax_kernel<<<H_ * S_, 256>>>(bf, pbf);

        // o[h,j,c] = sum_r P[h,r,j]*v[h,r,c];  fused sigmoid(g)*o
        gemm_tc<EPI_GSIG, true, true, false, __nv_bfloat16, __nv_bfloat16><<<dim3(1, 8, 16), 256>>>(
            pbf, kvgb + CH_, nullptr, nullptr, kvgb + 2 * CH_, nullptr, obb, nullptr,
            S_, CH_, S_, S_, C3_, CH_, C3_,
            (long long)S_ * S_, (long long)S_ * C3_, (long long)S_ * CH_,
            (long long)S_ * C3_, 1.f);

        // attn_mm = (sig(g)*o) @ ao_w^T
        gemm_tc<EPI_PLAIN, false, false, false, float, float><<<dim3(12, 8, 1), 256>>>(
            obb, wbf + wo_ao[l], nullptr, nullptr, nullptr, nullptr, amm, nullptr,
            S_, CA_, CA_, CA_, CA_, CA_, 0, 0, 0, 0, 0, 1.f);

        // attn_out = sigmoid(s @ out_w^T + out_b) * attn_mm
        gemm_tc<EPI_OUTGATE, false, false, false, float, float><<<dim3(12, 8, 1), 256>>>(
            s_bf, wbf + wo_out[l], nullptr, out_b + (long long)l * CA_,
            amm, nullptr, aout, nullptr,
            S_, CA_, CS_, CS_, CS_, CA_, CA_, 0, 0, 0, 0, 1.f);

        // adaLN (transition) -> a3
        gemm_tc<EPI_ADALN, false, false, true, __nv_bfloat16, float><<<dim3(12, 8, 1), 256>>>(
            shatb, wbf + wo_trpb[l], wbf + wo_trpnb[l], tr_pb_b + (long long)l * CA_,
            an, nullptr, a2b, nullptr,
            S_, CA_, CS_, CS_, CS_, CA_, CA_, 0, 0, 0, 0, 1.f);

        // bb = silu(a3 @ W1^T) * (a3 @ W2^T)
        gemm_tc<EPI_GLU, false, false, true, __nv_bfloat16, float><<<dim3(24, 8, 1), 256>>>(
            a2b, wbf + wo_tra[l], wbf + wo_tra[l] + (long long)2 * CA_ * CA_, nullptr,
            nullptr, nullptr, bbb, nullptr,
            S_, 2 * CA_, CA_, CA_, CA_, 2 * CA_, 0, 0, 0, 0, 0, 1.f);

        // tmm = bb @ tr_b_w^T
        gemm_tc<EPI_PLAIN, false, false, false, float, float><<<dim3(12, 8, 1), 256>>>(
            bbb, wbf + wo_trb[l], nullptr, nullptr, nullptr, nullptr, tmm, nullptr,
            S_, CA_, 2 * CA_, 2 * CA_, 2 * CA_, CA_, 0, 0, 0, 0, 0, 1.f);

        // a_next = attn_out + sigmoid((s @ tr_s_w^T + tr_s_b) * tmm)
        gemm_tc<EPI_TRFIN, false, false, false, float, float><<<dim3(12, 8, 1), 256>>>(
            s_bf, wbf + wo_trs[l], nullptr, tr_s_b + (long long)l * CA_,
            tmm, aout, aoutp, nullptr,
            S_, CA_, CS_, CS_, CS_, CA_, CA_, 0, 0, 0, 0, 1.f);
    }
}

// round 7
// speedup vs baseline: 4.0081x; 1.6575x over previous
#include <cuda_runtime.h>
#include <cuda_bf16.h>
#include <math.h>
#include <stdint.h>

// Problem constants
#define S_   1024
#define CA_  768
#define CS_  384
#define CZ_  64
#define H_   16
#define CH_  48     // head dim
#define C3_  144    // 3*CH
#define S2_  (S_ * S_)

// ---------------------------------------------------------------------------
// Static scratch (device globals — no cudaMalloc allowed)
// ---------------------------------------------------------------------------
__device__ float g_an[S_ * CA_];           // LN(a) per layer (fp32 aux)
__device__ float g_amm[S_ * CA_];          // attn @ ao_w^T
__device__ float g_aout[S_ * CA_];         // gated attention output
__device__ float g_tmm[S_ * CA_];          // bb @ tr_b_w^T
__device__ float g_anew[S_ * CA_];         // a after layer 0
__device__ float g_wbias[32];
__device__ float g_rinv[H_ * S_];          // reciprocal softmax row sums

__device__ __align__(16) __nv_bfloat16 g_bb0[H_ * S2_];   // layer-0 bias [h][i][j] (32MB)
__device__ __align__(16) __nv_bfloat16 g_bb1[H_ * S2_];   // layer-1 bias (32MB)
__device__ __align__(16) __nv_bfloat16 g_wbf[16908288];   // all weights + s, bf16
__device__ __align__(16) __nv_bfloat16 g_shatb[S_ * CS_];
__device__ __align__(16) __nv_bfloat16 g_a2b[S_ * CA_];
__device__ __align__(16) __nv_bfloat16 g_qb[S_ * CA_];
__device__ __align__(16) __nv_bfloat16 g_kvgb[S_ * 3 * CA_];
__device__ __align__(16) __nv_bfloat16 g_obb[S_ * CA_];
__device__ __align__(16) __nv_bfloat16 g_bbb[S_ * 2 * CA_];
__device__ __align__(16) __nv_bfloat16 g_pbf[H_ * S2_];   // unnormalized P (32 MiB)
__device__ __align__(16) __nv_bfloat16 g_wpbf[32 * 64];   // folded z-proj weights

// ---------------------------------------------------------------------------
// Helpers
// ---------------------------------------------------------------------------
__device__ __forceinline__ float sigf(float x) { return 1.0f / (1.0f + expf(-x)); }

__device__ __forceinline__ void mma_bf16(float* d, const uint32_t* a,
                                         uint32_t b0, uint32_t b1) {
    asm volatile(
        "mma.sync.aligned.m16n8k16.row.col.f32.bf16.bf16.f32 "
        "{%0,%1,%2,%3}, {%4,%5,%6,%7}, {%8,%9}, {%0,%1,%2,%3};"
        : "+f"(d[0]), "+f"(d[1]), "+f"(d[2]), "+f"(d[3])
        : "r"(a[0]), "r"(a[1]), "r"(a[2]), "r"(a[3]), "r"(b0), "r"(b1));
}

__device__ __forceinline__ void cp16(uint32_t smem, const void* g, int sbytes) {
    asm volatile("cp.async.cg.shared.global [%0], [%1], 16, %2;\n"
                 :: "r"(smem), "l"(g), "r"(sbytes));
}
#define CP_COMMIT() asm volatile("cp.async.commit_group;\n" ::)

__device__ __forceinline__ float toF(float v) { return v; }
__device__ __forceinline__ float toF(__nv_bfloat16 v) { return __bfloat162float(v); }
__device__ __forceinline__ void storeOut(float v, float* p) { *p = v; }
__device__ __forceinline__ void storeOut(float v, __nv_bfloat16* p) { *p = __float2bfloat16_rn(v); }

// block = 256 threads
__device__ __forceinline__ float blk_sum(float v, float* red) {
    int tid = threadIdx.x, lane = tid & 31;
    #pragma unroll
    for (int o = 16; o; o >>= 1) v += __shfl_xor_sync(0xffffffffu, v, o);
    if (lane == 0) red[tid >> 5] = v;
    __syncthreads();
    if (tid < 32) {
        float t = (tid < 8) ? red[tid] : 0.f;
        #pragma unroll
        for (int o = 4; o; o >>= 1) t += __shfl_xor_sync(0xffffffffu, t, o);
        if (tid == 0) red[0] = t;
    }
    __syncthreads();
    v = red[0];
    __syncthreads();
    return v;
}

// ---------------------------------------------------------------------------
// Weight/act conversion fp32 -> bf16 (optionally scaling columns by scl[c])
// ---------------------------------------------------------------------------
struct CvtArgs {
    const float* src[24];
    const float* scl[24];
    __nv_bfloat16* dst[24];
    int len[24];
    int smod;
    int nseg;
};

__global__ void __launch_bounds__(256) cvt_kernel(CvtArgs a) {
    int s = blockIdx.y;
    if (s >= a.nseg) return;
    const float* src = a.src[s];
    const float* scl = a.scl[s];
    __nv_bfloat16* dst = a.dst[s];
    int n = a.len[s];
    for (long long i = (long long)(blockIdx.x * 256 + threadIdx.x) * 2; i < n;
         i += (long long)gridDim.x * 512) {
        float2 v = *(const float2*)&src[i];
        if (scl) { int c = (int)(i % a.smod); v.x *= scl[c]; v.y *= scl[c + 1]; }
        *(__nv_bfloat162*)&dst[i] = __floats2bfloat162_rn(v.x, v.y);
    }
}

// ---------------------------------------------------------------------------
// LayerNorm (no affine): one block per row, 256 threads, W <= 768
// ---------------------------------------------------------------------------
template <typename OutT>
__global__ void __launch_bounds__(256) ln_kernel(const float* __restrict__ x,
                                                 OutT* __restrict__ y, int W) {
    __shared__ float red[32];
    long long row = blockIdx.x;
    const float* xr = x + row * W;
    float loc[3];
    int cnt = 0;
    float s = 0.f;
    for (int i = threadIdx.x; i < W; i += 256) { float v = xr[i]; loc[cnt++] = v; s += v; }
    float mean = blk_sum(s, red) / (float)W;
    float vs = 0.f;
    for (int j = 0; j < cnt; j++) { float d = loc[j] - mean; vs += d * d; }
    float var = blk_sum(vs, red) / (float)W;
    float rstd = rsqrtf(var + 1e-5f);
    OutT* yr = y + row * W;
    int j = 0;
    for (int i = threadIdx.x; i < W; i += 256) storeOut((loc[j++] - mean) * rstd, &yr[i]);
}

// ---------------------------------------------------------------------------
// z projection prep: Wp[lh,c] = bf16(pair_w[l,c]*bias_w[l,h,c]);
// Wbias[lh] = sum_c pair_b[l,c]*bias_w[l,h,c] + bias_b[l,h]
// ---------------------------------------------------------------------------
__global__ void zprep_kernel(const float* __restrict__ pw, const float* __restrict__ pb,
                             const float* __restrict__ bw, const float* __restrict__ bb,
                             __nv_bfloat16* __restrict__ Wp, float* __restrict__ Wbias) {
    int lh = threadIdx.x;
    if (lh >= 32) return;
    int l = lh >> 4;
    float bs = 0.f;
    for (int c = 0; c < 64; c++) {
        float w = bw[lh * 64 + c];
        Wp[lh * 64 + c] = __float2bfloat16_rn(pw[l * 64 + c] * w);
        bs += pb[l * 64 + c] * w;
    }
    Wbias[lh] = bs + bb[lh];
}

// ---------------------------------------------------------------------------
// z projection: coalesced load -> bf16 smem -> per-row LN -> mma (128x32x64)
// -> bf16 bias output in [h][i*S+j] layout (coalesced per-head stores).
// ---------------------------------------------------------------------------
__global__ void __launch_bounds__(256) zproj_kernel(const float* __restrict__ z,
                                                    const __nv_bfloat16* __restrict__ Wp,
                                                    const float* __restrict__ Wbias,
                                                    __nv_bfloat16* __restrict__ b0,
                                                    __nv_bfloat16* __restrict__ b1) {
    __shared__ __nv_bfloat16 zb[128][72];
    __shared__ __nv_bfloat16 wsm[32][72];
    __shared__ __nv_bfloat16 sOut[32][136];
    __shared__ float bsm[32];
    int tid = threadIdx.x;
    long long base = (long long)blockIdx.x * 8192;

    // coalesced load z -> bf16 smem
    #pragma unroll
    for (int i = 0; i < 8; i++) {
        int idx = tid + i * 256;               // float4 units (2048 total)
        float4 t = *(const float4*)&z[base + (long long)idx * 4];
        int r = idx >> 4, c = (idx & 15) * 4;
        *(__nv_bfloat162*)&zb[r][c]     = __floats2bfloat162_rn(t.x, t.y);
        *(__nv_bfloat162*)&zb[r][c + 2] = __floats2bfloat162_rn(t.z, t.w);
    }
    #pragma unroll
    for (int i = 0; i < 8; i++) {
        int idx = tid + i * 256;
        wsm[idx >> 6][idx & 63] = Wp[idx];
    }
    if (tid < 32) bsm[tid] = Wbias[tid];
    __syncthreads();

    // per-row LN: thread pair per row (half = 32 elems each)
    {
        int row = tid >> 1, half = tid & 1;
        float vv[32];
        float s = 0.f, s2 = 0.f;
        #pragma unroll
        for (int i = 0; i < 32; i++) {
            float v = toF(zb[row][half * 32 + i]);
            vv[i] = v; s += v; s2 += v * v;
        }
        s  += __shfl_xor_sync(0xffffffffu, s, 1);
        s2 += __shfl_xor_sync(0xffffffffu, s2, 1);
        float m = s * (1.f / 64.f);
        float rs = rsqrtf(s2 * (1.f / 64.f) - m * m + 1e-5f);
        #pragma unroll
        for (int i = 0; i < 16; i++)
            *(__nv_bfloat162*)&zb[row][half * 32 + 2 * i] =
                __floats2bfloat162_rn((vv[2 * i] - m) * rs, (vv[2 * i + 1] - m) * rs);
    }
    __syncthreads();

    int w = tid >> 5, lane = tid & 31, qr = lane >> 2, qc = lane & 3;
    float acc[4][4] = {};
    const uint32_t* zw = (const uint32_t*)&zb[0][0];    // word pitch 36
    const uint32_t* ww = (const uint32_t*)&wsm[0][0];
    #pragma unroll
    for (int kc = 0; kc < 4; kc++) {
        uint32_t af[4];
        int r = w * 16 + qr;
        af[0] = zw[r * 36 + kc * 8 + qc];
        af[1] = zw[(r + 8) * 36 + kc * 8 + qc];
        af[2] = zw[r * 36 + kc * 8 + 4 + qc];
        af[3] = zw[(r + 8) * 36 + kc * 8 + 4 + qc];
        #pragma unroll
        for (int j = 0; j < 4; j++) {
            int n = j * 8 + qr;
            mma_bf16(acc[j], af, ww[n * 36 + kc * 8 + qc], ww[n * 36 + kc * 8 + 4 + qc]);
        }
    }
    // stage to sOut[n][m]
    #pragma unroll
    for (int j = 0; j < 4; j++) {
        #pragma unroll
        for (int e = 0; e < 4; e++) {
            int mm = w * 16 + qr + ((e >= 2) ? 8 : 0);
            int n = j * 8 + 2 * qc + (e & 1);
            sOut[n][mm] = __float2bfloat16_rn(acc[j][e] + bsm[n]);
        }
    }
    __syncthreads();
    // coalesced write: per lh a contiguous run of 128 bf16 at rg0
    long long rg0 = (long long)blockIdx.x * 128;
    #pragma unroll
    for (int it = 0; it < 2; it++) {
        int lh = tid >> 3, part = (tid & 7) + it * 8;
        uint4 v = *(const uint4*)&sOut[lh][part * 8];
        __nv_bfloat16* dst = ((lh < 16) ? b0 : b1) +
                             (long long)(lh & 15) * S2_ + rg0 + part * 8;
        *(uint4*)dst = v;
    }
}

// ---------------------------------------------------------------------------
// Fused scores+softmax: per block = (head, 128 k-rows r) x all 1024 t.
// P[h,r,t] = exp(q[h,t]·k[h,r]/48 + bias[h,r,t])  (unnormalized, bf16)
// rinv[h,r] = 1/sum_t P.   Dynamic smem 64KB.
// ---------------------------------------------------------------------------
__global__ void __launch_bounds__(256) attn_sm_kernel(
    const __nv_bfloat16* __restrict__ kvg,   // [H][S][144] (flat reinterpret)
    const __nv_bfloat16* __restrict__ q,     // [H][S][48]
    const __nv_bfloat16* __restrict__ bias,  // [H][S][S]
    __nv_bfloat16* __restrict__ P,           // [H][S][S]
    float* __restrict__ rinv) {
    const int h = blockIdx.y;
    const int bm = blockIdx.x * 128;
    const int tid = threadIdx.x, lane = tid & 31, warp = tid >> 5;
    const int wm = warp >> 1, wn = warp & 1;
    const int qr = lane >> 2, qc = lane & 3;

    extern __shared__ char smraw[];
    __nv_bfloat16* Ks  = (__nv_bfloat16*)smraw;            // [128][56]
    __nv_bfloat16* Qs  = Ks + 128 * 56;                    // [2][64][56]
    __nv_bfloat16* Bsm = Qs + 2 * 64 * 56;                 // [2][128][72]
    __shared__ float rs[128];

    // K tile (sync, once): row r -> kvg[h][bm+r][0..48)
    const __nv_bfloat16* kbase = kvg + (long long)h * S_ * C3_;
    for (int id = tid; id < 128 * 24; id += 256) {  // bf16x2 units
        int r = id / 24, c2 = id % 24;
        *(__nv_bfloat162*)&Ks[r * 56 + c2 * 2] =
            *(const __nv_bfloat162*)&kbase[(long long)(bm + r) * C3_ + c2 * 2];
    }
    if (tid < 128) rs[tid] = 0.f;

    const __nv_bfloat16* qbase = q + (long long)h * S_ * CH_;
    const __nv_bfloat16* bbase = bias + (long long)h * S2_;
    __nv_bfloat16* pbase = P + (long long)h * S2_;
    uint32_t qS = (uint32_t)__cvta_generic_to_shared(Qs);
    uint32_t bS = (uint32_t)__cvta_generic_to_shared(Bsm);

    auto issue = [&](int st, int tc) {
        if (tid < 192) {
            int t = tid / 3, seg = tid % 3;
            cp16(qS + st * 64 * 112 + t * 112 + seg * 16,
                 qbase + (long long)(tc * 64 + t) * CH_ + seg * 8, 16);
        }
        #pragma unroll
        for (int i = 0; i < 4; i++) {
            int id = tid + i * 256;
            int r = id >> 3, seg = id & 7;
            cp16(bS + st * 128 * 144 + r * 144 + seg * 16,
                 bbase + (long long)(bm + r) * S_ + tc * 64 + seg * 8, 16);
        }
    };

    float rowacc[2][2] = {};
    issue(0, 0);
    CP_COMMIT();

    for (int tc = 0; tc < 16; tc++) {
        if (tc + 1 < 16) issue((tc + 1) & 1, tc + 1);
        CP_COMMIT();
        asm volatile("cp.async.wait_group 1;\n" ::);
        __syncthreads();
        int st = tc & 1;
        float acc[2][4][4] = {};
        #pragma unroll
        for (int ks = 0; ks < 3; ks++) {
            uint32_t af[2][4];
            #pragma unroll
            for (int i = 0; i < 2; i++) {
                int r = wm * 32 + i * 16 + qr;
                const uint32_t* a0 = (const uint32_t*)&Ks[r * 56];
                const uint32_t* a8 = (const uint32_t*)&Ks[(r + 8) * 56];
                af[i][0] = a0[ks * 8 + qc];
                af[i][1] = a8[ks * 8 + qc];
                af[i][2] = a0[ks * 8 + 4 + qc];
                af[i][3] = a8[ks * 8 + 4 + qc];
            }
            #pragma unroll
            for (int j = 0; j < 4; j++) {
                int n = wn * 32 + j * 8 + qr;
                const uint32_t* br = (const uint32_t*)&Qs[st * 64 * 56 + n * 56];
                uint32_t b0 = br[ks * 8 + qc];
                uint32_t b1 = br[ks * 8 + 4 + qc];
                #pragma unroll
                for (int i = 0; i < 2; i++) mma_bf16(acc[i][j], af[i], b0, b1);
            }
        }
        // epilogue: exp(acc/48 + bias) -> P, accumulate rowsum
        #pragma unroll
        for (int i = 0; i < 2; i++) {
            #pragma unroll
            for (int eh = 0; eh < 2; eh++) {
                int ml = wm * 32 + i * 16 + qr + eh * 8;
                const __nv_bfloat16* brow = &Bsm[st * 128 * 72 + ml * 72];
                long long prow = (long long)(bm + ml) * S_ + tc * 64;
                float part = 0.f;
                #pragma unroll
                for (int j = 0; j < 4; j++) {
                    int nl = wn * 32 + j * 8 + 2 * qc;
                    __nv_bfloat162 bb = *(const __nv_bfloat162*)&brow[nl];
                    float v0 = acc[i][j][eh * 2 + 0] * (1.f / 48.f) + toF(bb.x);
                    float v1 = acc[i][j][eh * 2 + 1] * (1.f / 48.f) + toF(bb.y);
                    float e0 = __expf(v0), e1 = __expf(v1);
                    *(__nv_bfloat162*)&pbase[prow + nl] = __floats2bfloat162_rn(e0, e1);
                    part += e0 + e1;
                }
                rowacc[i][eh] += part;
            }
        }
        __syncthreads();
    }
    // reduce row sums: over qc lanes, then across the two wn warps via smem atomics
    #pragma unroll
    for (int i = 0; i < 2; i++) {
        #pragma unroll
        for (int eh = 0; eh < 2; eh++) {
            float v = rowacc[i][eh];
            v += __shfl_xor_sync(0xffffffffu, v, 1);
            v += __shfl_xor_sync(0xffffffffu, v, 2);
            if (qc == 0) atomicAdd(&rs[wm * 32 + i * 16 + qr + eh * 8], v);
        }
    }
    __syncthreads();
    if (tid < 128) rinv[h * S_ + bm + tid] = 1.0f / rs[tid];
}

// ---------------------------------------------------------------------------
// Tensor-core bf16 GEMM:  C[m,n] = sum_k A[m,k] * B[n,k]   (NT by default)
// NT path: cp.async multi-stage pipeline.  TA/TB (PV only): sync loads with
// register double buffer; optional per-k scale on B (kscale).
// ---------------------------------------------------------------------------
enum { EPI_PLAIN = 0, EPI_GSIG = 2, EPI_OUTGATE = 3,
       EPI_TRFIN = 4, EPI_ADALN = 5, EPI_GLU = 6 };

template <int EPI, bool TA, bool TB, bool DUAL, typename OutT, typename AuxT>
__global__ void __launch_bounds__(256) gemm_tc(
    const __nv_bfloat16* __restrict__ A, const __nv_bfloat16* __restrict__ B1,
    const __nv_bfloat16* __restrict__ B2, const float* __restrict__ bias,
    const AuxT* __restrict__ aux, const float* __restrict__ aux2,
    OutT* __restrict__ Cp, const float* __restrict__ kscale,
    int M, int N, int K, int lda, int ldb, int ldc, int aux_ld,
    long long sA, long long sB, long long sC, long long sAux, long long sKs) {
    constexpr int NST = DUAL ? 2 : 3;
    const int tid = threadIdx.x;
    const int lane = tid & 31, warp = tid >> 5;
    const int wm = warp >> 1, wn = warp & 1;       // 4 x 2 warp grid
    const int bm = blockIdx.y * 128, bn = blockIdx.x * 64;
    const int bz = blockIdx.z;
    A += bz * sA;
    B1 += bz * sB;
    if constexpr (DUAL) B2 += bz * sB;
    Cp += bz * sC;
    if (aux) aux += bz * sAux;
    if (kscale) kscale += bz * sKs;

    __shared__ __nv_bfloat16 As[NST][128][40];
    __shared__ __nv_bfloat16 Bs1[NST][64][40];
    __shared__ __nv_bfloat16 Bs2[DUAL ? NST : 1][64][40];

    float acc1[2][4][4] = {};
    float acc2[2][4][4] = {};
    const int qr = lane >> 2, qc = lane & 3;
    const int nk = (K + 31) / 32;

    auto do_mma = [&](int st) {
        #pragma unroll
        for (int ks = 0; ks < 2; ks++) {
            uint32_t af[2][4];
            #pragma unroll
            for (int i = 0; i < 2; i++) {
                int r = wm * 32 + i * 16 + qr;
                const uint32_t* arow  = (const uint32_t*)&As[st][r][0];
                const uint32_t* arow8 = (const uint32_t*)&As[st][r + 8][0];
                af[i][0] = arow[ks * 8 + qc];
                af[i][1] = arow8[ks * 8 + qc];
                af[i][2] = arow[ks * 8 + 4 + qc];
                af[i][3] = arow8[ks * 8 + 4 + qc];
            }
            #pragma unroll
            for (int j = 0; j < 4; j++) {
                int n = wn * 32 + j * 8 + qr;
                const uint32_t* brow = (const uint32_t*)&Bs1[st][n][0];
                uint32_t b0 = brow[ks * 8 + qc];
                uint32_t b1 = brow[ks * 8 + 4 + qc];
                #pragma unroll
                for (int i = 0; i < 2; i++) mma_bf16(acc1[i][j], af[i], b0, b1);
                if constexpr (DUAL) {
                    const uint32_t* brow2 = (const uint32_t*)&Bs2[st][n][0];
                    uint32_t c0 = brow2[ks * 8 + qc];
                    uint32_t c1 = brow2[ks * 8 + 4 + qc];
                    #pragma unroll
                    for (int i = 0; i < 2; i++) mma_bf16(acc2[i][j], af[i], c0, c1);
                }
            }
        }
    };

    if constexpr (!TA && !TB) {
        uint32_t aBase = (uint32_t)__cvta_generic_to_shared(&As[0][0][0]);
        uint32_t bBase = (uint32_t)__cvta_generic_to_shared(&Bs1[0][0][0]);
        uint32_t b2Base = 0;
        if constexpr (DUAL) b2Base = (uint32_t)__cvta_generic_to_shared(&Bs2[0][0][0]);

        auto issue = [&](int st, int k0) {
            #pragma unroll
            for (int i = 0; i < 2; i++) {
                int id = tid + i * 256;
                int r = id >> 2, cp4 = id & 3;
                int kk = k0 + cp4 * 8;
                const __nv_bfloat16* src = A + (long long)(bm + r) * lda + kk;
                int sb = (kk < K) ? 16 : 0;
                if (!sb) src = A;
                cp16(aBase + st * 128 * 80 + r * 80 + cp4 * 16, src, sb);
            }
            {
                int r = tid >> 2, cp4 = tid & 3;
                int kk = k0 + cp4 * 8;
                int sb = (kk < K) ? 16 : 0;
                const __nv_bfloat16* src = B1 + (long long)(bn + r) * ldb + kk;
                if (!sb) src = B1;
                cp16(bBase + st * 64 * 80 + r * 80 + cp4 * 16, src, sb);
                if constexpr (DUAL) {
                    const __nv_bfloat16* src2 = B2 + (long long)(bn + r) * ldb + kk;
                    if (!sb) src2 = B2;
                    cp16(b2Base + st * 64 * 80 + r * 80 + cp4 * 16, src2, sb);
                }
            }
        };

        #pragma unroll
        for (int p = 0; p < NST - 1; p++) {
            if (p < nk) issue(p, p * 32);
            CP_COMMIT();
        }
        for (int ic = 0; ic < nk; ic++) {
            int pn = ic + NST - 1;
            if (pn < nk) issue(pn % NST, pn * 32);
            CP_COMMIT();
            if constexpr (NST == 3) asm volatile("cp.async.wait_group 2;\n" ::);
            else                    asm volatile("cp.async.wait_group 1;\n" ::);
            __syncthreads();
            do_mma(ic % NST);
            __syncthreads();
        }
    } else {
        __nv_bfloat16 ra[16], rb[8];
        const __nv_bfloat16 z0 = __float2bfloat16(0.f);
        auto loadA = [&](int k0) {
            #pragma unroll
            for (int i = 0; i < 16; i++) {
                int idx = tid + i * 256;
                int mm = idx & 127, kk = idx >> 7;
                if constexpr (TA)
                    ra[i] = (k0 + kk < K) ? A[(long long)(k0 + kk) * lda + (bm + mm)] : z0;
                else
                    ra[i] = (k0 + kk < K) ? A[(long long)(bm + mm) * lda + (k0 + kk)] : z0;
            }
        };
        auto loadB = [&](int k0) {
            #pragma unroll
            for (int i = 0; i < 8; i++) {
                int idx = tid + i * 256;
                int n = idx & 63, kk = idx >> 6;
                int gn = bn + n;
                bool ok = (gn < N && k0 + kk < K);
                __nv_bfloat16 raw;
                if constexpr (TB)
                    raw = ok ? B1[(long long)(k0 + kk) * ldb + gn] : z0;
                else
                    raw = ok ? B1[(long long)gn * ldb + (k0 + kk)] : z0;
                if (kscale && ok)
                    raw = __float2bfloat16_rn(toF(raw) * kscale[k0 + kk]);
                rb[i] = raw;
            }
        };
        loadA(0); loadB(0);
        for (int ic = 0; ic < nk; ic++) {
            #pragma unroll
            for (int i = 0; i < 16; i++) {
                int idx = tid + i * 256;
                As[0][idx & 127][idx >> 7] = ra[i];
            }
            #pragma unroll
            for (int i = 0; i < 8; i++) {
                int idx = tid + i * 256;
                Bs1[0][idx & 63][idx >> 6] = rb[i];
            }
            __syncthreads();
            if (ic + 1 < nk) { loadA((ic + 1) * 32); loadB((ic + 1) * 32); }
            do_mma(0);
            __syncthreads();
        }
    }

    // ---- epilogue ----
    #pragma unroll
    for (int i = 0; i < 2; i++) {
        #pragma unroll
        for (int j = 0; j < 4; j++) {
            int m0 = bm + wm * 32 + i * 16 + qr;
            int n0 = bn + wn * 32 + j * 8 + 2 * qc;
            #pragma unroll
            for (int e = 0; e < 4; e++) {
                int m = m0 + ((e >= 2) ? 8 : 0);
                int n = n0 + (e & 1);
                if (n >= N) continue;
                long long cidx = (long long)m * ldc + n;
                float v = acc1[i][j][e];
                float out;
                if constexpr (EPI == EPI_PLAIN) {
                    out = v + (bias ? bias[n] : 0.f);
                } else if constexpr (EPI == EPI_GSIG) {
                    out = sigf(toF(aux[(long long)m * aux_ld + n])) * v;
                } else if constexpr (EPI == EPI_OUTGATE) {
                    out = sigf(v + bias[n]) * toF(aux[(long long)m * aux_ld + n]);
                } else if constexpr (EPI == EPI_TRFIN) {
                    out = aux2[(long long)m * aux_ld + n] +
                          sigf((v + bias[n]) * toF(aux[(long long)m * aux_ld + n]));
                } else if constexpr (EPI == EPI_ADALN) {
                    out = sigf((v + bias[n]) * toF(aux[(long long)m * aux_ld + n]) + acc2[i][j][e]);
                } else {  // EPI_GLU
                    out = v * sigf(v) * acc2[i][j][e];
                }
                storeOut(out, &Cp[cidx]);
            }
        }
    }
}

// ---------------------------------------------------------------------------
// Host orchestration
// ---------------------------------------------------------------------------
extern "C" void kernel_launch(void* const* d_in, const int* in_sizes, int n_in,
                              void* d_out, int out_size) {
    const float* A0        = (const float*)d_in[0];
    const float* Sm        = (const float*)d_in[1];
    const float* Z         = (const float*)d_in[2];
    const float* attn_sn_w = (const float*)d_in[3];
    const float* attn_pb_w = (const float*)d_in[4];
    const float* attn_pb_b = (const float*)d_in[5];
    const float* attn_pnb_w= (const float*)d_in[6];
    const float* pair_w    = (const float*)d_in[7];
    const float* pair_b    = (const float*)d_in[8];
    const float* q_w       = (const float*)d_in[9];
    const float* q_b       = (const float*)d_in[10];
    const float* kvg_w     = (const float*)d_in[11];
    const float* bias_w    = (const float*)d_in[12];
    const float* bias_b    = (const float*)d_in[13];
    const float* ao_w      = (const float*)d_in[14];
    const float* out_w     = (const float*)d_in[15];
    const float* out_b     = (const float*)d_in[16];
    const float* tr_sn_w   = (const float*)d_in[17];
    const float* tr_pb_w   = (const float*)d_in[18];
    const float* tr_pb_b   = (const float*)d_in[19];
    const float* tr_pnb_w  = (const float*)d_in[20];
    const float* tr_a_w    = (const float*)d_in[21];
    const float* tr_s_w    = (const float*)d_in[22];
    const float* tr_s_b    = (const float*)d_in[23];
    const float* tr_b_w    = (const float*)d_in[24];
    float* OUT = (float*)d_out;

    float *an, *amm, *aout, *tmm, *anew, *wbias, *rinv;
    __nv_bfloat16 *bb0, *bb1, *wbf, *shatb, *a2b, *qb, *kvgb, *obb, *bbb, *pbf, *wpbf;
    cudaGetSymbolAddress((void**)&an, g_an);
    cudaGetSymbolAddress((void**)&amm, g_amm);
    cudaGetSymbolAddress((void**)&aout, g_aout);
    cudaGetSymbolAddress((void**)&tmm, g_tmm);
    cudaGetSymbolAddress((void**)&anew, g_anew);
    cudaGetSymbolAddress((void**)&wbias, g_wbias);
    cudaGetSymbolAddress((void**)&rinv, g_rinv);
    cudaGetSymbolAddress((void**)&bb0, g_bb0);
    cudaGetSymbolAddress((void**)&bb1, g_bb1);
    cudaGetSymbolAddress((void**)&wbf, g_wbf);
    cudaGetSymbolAddress((void**)&shatb, g_shatb);
    cudaGetSymbolAddress((void**)&a2b, g_a2b);
    cudaGetSymbolAddress((void**)&qb, g_qb);
    cudaGetSymbolAddress((void**)&kvgb, g_kvgb);
    cudaGetSymbolAddress((void**)&obb, g_obb);
    cudaGetSymbolAddress((void**)&bbb, g_bbb);
    cudaGetSymbolAddress((void**)&pbf, g_pbf);
    cudaGetSymbolAddress((void**)&wpbf, g_wpbf);

    cudaFuncSetAttribute(attn_sm_kernel, cudaFuncAttributeMaxDynamicSharedMemorySize, 65536);

    // ---- build conversion table + record weight offsets ----
    CvtArgs ca;
    long long off = 0;
    int ns = 0;
    long long wo_pb[2], wo_pnb[2], wo_q[2], wo_kvg[2], wo_ao[2], wo_out[2];
    long long wo_trpb[2], wo_trpnb[2], wo_tra[2], wo_trs[2], wo_trb[2], wo_s;
    auto seg = [&](const float* s, int len, const float* sc) -> long long {
        ca.src[ns] = s; ca.scl[ns] = sc; ca.dst[ns] = wbf + off; ca.len[ns] = len;
        long long o = off; off += len; ns++; return o;
    };
    for (int l = 0; l < 2; l++) {
        wo_pb[l]    = seg(attn_pb_w  + (long long)l * CA_ * CS_, CA_ * CS_, attn_sn_w + l * CS_);
        wo_pnb[l]   = seg(attn_pnb_w + (long long)l * CA_ * CS_, CA_ * CS_, attn_sn_w + l * CS_);
        wo_q[l]     = seg(q_w   + (long long)l * CA_ * CA_, CA_ * CA_, nullptr);
        wo_kvg[l]   = seg(kvg_w + (long long)l * 3 * CA_ * CA_, 3 * CA_ * CA_, nullptr);
        wo_ao[l]    = seg(ao_w  + (long long)l * CA_ * CA_, CA_ * CA_, nullptr);
        wo_out[l]   = seg(out_w + (long long)l * CA_ * CS_, CA_ * CS_, nullptr);
        wo_trpb[l]  = seg(tr_pb_w  + (long long)l * CA_ * CS_, CA_ * CS_, tr_sn_w + l * CS_);
        wo_trpnb[l] = seg(tr_pnb_w + (long long)l * CA_ * CS_, CA_ * CS_, tr_sn_w + l * CS_);
        wo_tra[l]   = seg(tr_a_w + (long long)l * 4 * CA_ * CA_, 4 * CA_ * CA_, nullptr);
        wo_trs[l]   = seg(tr_s_w + (long long)l * CA_ * CS_, CA_ * CS_, nullptr);
        wo_trb[l]   = seg(tr_b_w + (long long)l * 2 * CA_ * CA_, 2 * CA_ * CA_, nullptr);
    }
    wo_s = seg(Sm, S_ * CS_, nullptr);
    ca.smod = CS_;
    ca.nseg = ns;

    cvt_kernel<<<dim3(128, ns), 256>>>(ca);
    ln_kernel<__nv_bfloat16><<<S_, 256>>>(Sm, shatb, CS_);
    zprep_kernel<<<1, 32>>>(pair_w, pair_b, bias_w, bias_b, wpbf, wbias);
    zproj_kernel<<<(S_ * S_) / 128, 256>>>(Z, wpbf, wbias, bb0, bb1);

    const __nv_bfloat16* s_bf = wbf + wo_s;

    for (int l = 0; l < 2; l++) {
        const float* ain = l ? anew : A0;
        float* aoutp = l ? OUT : anew;
        const __nv_bfloat16* bbl = l ? bb1 : bb0;

        ln_kernel<float><<<S_, 256>>>(ain, an, CA_);

        // adaLN (attention): a2 = sigmoid((sn@pbW^T + pb_b)*an + sn@pnbW^T)
        gemm_tc<EPI_ADALN, false, false, true, __nv_bfloat16, float><<<dim3(12, 8, 1), 256>>>(
            shatb, wbf + wo_pb[l], wbf + wo_pnb[l], attn_pb_b + (long long)l * CA_,
            an, nullptr, a2b, nullptr,
            S_, CA_, CS_, CS_, CS_, CA_, CA_, 0, 0, 0, 0, 0);

        // q = a2 @ q_w^T + q_b
        gemm_tc<EPI_PLAIN, false, false, false, __nv_bfloat16, float><<<dim3(12, 8, 1), 256>>>(
            a2b, wbf + wo_q[l], nullptr, q_b + (long long)l * CA_,
            nullptr, nullptr, qb, nullptr,
            S_, CA_, CA_, CA_, CA_, CA_, 0, 0, 0, 0, 0, 0);

        // kvg = a2 @ kvg_w^T
        gemm_tc<EPI_PLAIN, false, false, false, __nv_bfloat16, float><<<dim3(36, 8, 1), 256>>>(
            a2b, wbf + wo_kvg[l], nullptr, nullptr,
            nullptr, nullptr, kvgb, nullptr,
            S_, 3 * CA_, CA_, CA_, CA_, 3 * CA_, 0, 0, 0, 0, 0, 0);

        // fused scores + softmax (unnormalized P + reciprocal row sums)
        attn_sm_kernel<<<dim3(8, 16), 256, 65536>>>(kvgb, qb, bbl, pbf, rinv);

        // o[h,j,c] = sum_r P[h,r,j]*rinv[h,r]*v[h,r,c];  fused sigmoid(g)*o
        // B1 = V (kvg col offset CH_), aux = g (col offset 2*CH_)
        gemm_tc<EPI_GSIG, true, true, false, __nv_bfloat16, __nv_bfloat16><<<dim3(1, 8, 16), 256>>>(
            pbf, kvgb + CH_, nullptr, nullptr, kvgb + 2 * CH_, nullptr, obb, rinv,
            S_, CH_, S_, S_, C3_, CH_, C3_,
            (long long)S_ * S_, (long long)S_ * C3_, (long long)S_ * CH_,
            (long long)S_ * C3_, S_);

        // attn_mm = (sig(g)*o) @ ao_w^T
        gemm_tc<EPI_PLAIN, false, false, false, float, float><<<dim3(12, 8, 1), 256>>>(
            obb, wbf + wo_ao[l], nullptr, nullptr, nullptr, nullptr, amm, nullptr,
            S_, CA_, CA_, CA_, CA_, CA_, 0, 0, 0, 0, 0, 0);

        // attn_out = sigmoid(s @ out_w^T + out_b) * attn_mm
        gemm_tc<EPI_OUTGATE, false, false, false, float, float><<<dim3(12, 8, 1), 256>>>(
            s_bf, wbf + wo_out[l], nullptr, out_b + (long long)l * CA_,
            amm, nullptr, aout, nullptr,
            S_, CA_, CS_, CS_, CS_, CA_, CA_, 0, 0, 0, 0, 0);

        // adaLN (transition) -> a3
        gemm_tc<EPI_ADALN, false, false, true, __nv_bfloat16, float><<<dim3(12, 8, 1), 256>>>(
            shatb, wbf + wo_trpb[l], wbf + wo_trpnb[l], tr_pb_b + (long long)l * CA_,
            an, nullptr, a2b, nullptr,
            S_, CA_, CS_, CS_, CS_, CA_, CA_, 0, 0, 0, 0, 0);

        // bb = silu(a3 @ W1^T) * (a3 @ W2^T)
        gemm_tc<EPI_GLU, false, false, true, __nv_bfloat16, float><<<dim3(24, 8, 1), 256>>>(
            a2b, wbf + wo_tra[l], wbf + wo_tra[l] + (long long)2 * CA_ * CA_, nullptr,
            nullptr, nullptr, bbb, nullptr,
            S_, 2 * CA_, CA_, CA_, CA_, 2 * CA_, 0, 0, 0, 0, 0, 0);

        // tmm = bb @ tr_b_w^T
        gemm_tc<EPI_PLAIN, false, false, false, float, float><<<dim3(12, 8, 1), 256>>>(
            bbb, wbf + wo_trb[l], nullptr, nullptr, nullptr, nullptr, tmm, nullptr,
            S_, CA_, 2 * CA_, 2 * CA_, 2 * CA_, CA_, 0, 0, 0, 0, 0, 0);

        // a_next = attn_out + sigmoid((s @ tr_s_w^T + tr_s_b) * tmm)
        gemm_tc<EPI_TRFIN, false, false, false, float, float><<<dim3(12, 8, 1), 256>>>(
            s_bf, wbf + wo_trs[l], nullptr, tr_s_b + (long long)l * CA_,
            tmm, aout, aoutp, nullptr,
            S_, CA_, CS_, CS_, CS_, CA_, CA_, 0, 0, 0, 0, 0);
    }
}

// round 10
// speedup vs baseline: 4.5149x; 1.1264x over previous
#include <cuda_runtime.h>
#include <cuda_bf16.h>
#include <math.h>
#include <stdint.h>

// Problem constants
#define S_   1024
#define CA_  768
#define CS_  384
#define CZ_  64
#define H_   16
#define CH_  48     // head dim
#define C3_  144    // 3*CH
#define S2_  (S_ * S_)

// ---------------------------------------------------------------------------
// Static scratch (device globals — no cudaMalloc allowed)
// ---------------------------------------------------------------------------
__device__ float g_an[S_ * CA_];           // LN(a) per layer (fp32 aux)
__device__ float g_amm[S_ * CA_];          // attn @ ao_w^T
__device__ float g_aout[S_ * CA_];         // gated attention output
__device__ float g_tmm[S_ * CA_];          // bb @ tr_b_w^T
__device__ float g_anew[S_ * CA_];         // a after layer 0
__device__ float g_wbias[32];
__device__ float g_rinv[H_ * S_];          // reciprocal softmax row sums

__device__ __align__(16) __nv_bfloat16 g_bb0[H_ * S2_];   // layer-0 bias [h][i][j]
__device__ __align__(16) __nv_bfloat16 g_bb1[H_ * S2_];   // layer-1 bias
__device__ __align__(16) __nv_bfloat16 g_wbf[16908288];   // all weights + s, bf16
__device__ __align__(16) __nv_bfloat16 g_shatb[S_ * CS_];
__device__ __align__(16) __nv_bfloat16 g_a2b[S_ * CA_];
__device__ __align__(16) __nv_bfloat16 g_qb[S_ * CA_];
__device__ __align__(16) __nv_bfloat16 g_kvgb[S_ * 3 * CA_];
__device__ __align__(16) __nv_bfloat16 g_obb[S_ * CA_];
__device__ __align__(16) __nv_bfloat16 g_bbb[S_ * 2 * CA_];
__device__ __align__(16) __nv_bfloat16 g_pbf[H_ * S2_];   // Pt (transposed, unnormalized)
__device__ __align__(16) __nv_bfloat16 g_vtb[H_ * CH_ * S_ + 64 * S_];  // Vt scaled (+pad)
__device__ __align__(16) __nv_bfloat16 g_wpbf[32 * 64];   // folded z-proj weights

// ---------------------------------------------------------------------------
// Helpers
// ---------------------------------------------------------------------------
__device__ __forceinline__ float sigf(float x) { return 1.0f / (1.0f + expf(-x)); }

__device__ __forceinline__ void mma_bf16(float* d, const uint32_t* a,
                                         uint32_t b0, uint32_t b1) {
    asm volatile(
        "mma.sync.aligned.m16n8k16.row.col.f32.bf16.bf16.f32 "
        "{%0,%1,%2,%3}, {%4,%5,%6,%7}, {%8,%9}, {%0,%1,%2,%3};"
        : "+f"(d[0]), "+f"(d[1]), "+f"(d[2]), "+f"(d[3])
        : "r"(a[0]), "r"(a[1]), "r"(a[2]), "r"(a[3]), "r"(b0), "r"(b1));
}

__device__ __forceinline__ void cp16(uint32_t smem, const void* g, int sbytes) {
    asm volatile("cp.async.cg.shared.global [%0], [%1], 16, %2;\n"
                 :: "r"(smem), "l"(g), "r"(sbytes));
}
#define CP_COMMIT() asm volatile("cp.async.commit_group;\n" ::)

__device__ __forceinline__ float toF(float v) { return v; }
__device__ __forceinline__ float toF(__nv_bfloat16 v) { return __bfloat162float(v); }
__device__ __forceinline__ void storeOut(float v, float* p) { *p = v; }
__device__ __forceinline__ void storeOut(float v, __nv_bfloat16* p) { *p = __float2bfloat16_rn(v); }

// ---------------------------------------------------------------------------
// Weight/act conversion fp32 -> bf16 (optionally scaling columns by scl[c])
// ---------------------------------------------------------------------------
struct CvtArgs {
    const float* src[24];
    const float* scl[24];
    __nv_bfloat16* dst[24];
    int len[24];
    int smod;
    int nseg;
};

__global__ void __launch_bounds__(256) cvt_kernel(CvtArgs a) {
    int s = blockIdx.y;
    if (s >= a.nseg) return;
    const float* src = a.src[s];
    const float* scl = a.scl[s];
    __nv_bfloat16* dst = a.dst[s];
    int n = a.len[s];
    for (long long i = (long long)(blockIdx.x * 256 + threadIdx.x) * 2; i < n;
         i += (long long)gridDim.x * 512) {
        float2 v = *(const float2*)&src[i];
        if (scl) { int c = (int)(i % a.smod); v.x *= scl[c]; v.y *= scl[c + 1]; }
        *(__nv_bfloat162*)&dst[i] = __floats2bfloat162_rn(v.x, v.y);
    }
}

// ---------------------------------------------------------------------------
// LayerNorm (no affine): one WARP per row, 8 rows/block. W % 128 == 0, W<=768.
// ---------------------------------------------------------------------------
template <typename OutT>
__global__ void __launch_bounds__(256) ln_kernel(const float* __restrict__ x,
                                                 OutT* __restrict__ y, int W) {
    int warp = threadIdx.x >> 5, lane = threadIdx.x & 31;
    long long row = (long long)blockIdx.x * 8 + warp;
    const float4* xr = (const float4*)(x + row * W);
    int npl = W >> 7;                       // float4 per lane (<=6)
    float4 v[6];
    float s = 0.f;
    #pragma unroll 6
    for (int i = 0; i < npl; i++) {
        v[i] = xr[lane + i * 32];
        s += v[i].x + v[i].y + v[i].z + v[i].w;
    }
    #pragma unroll
    for (int o = 16; o; o >>= 1) s += __shfl_xor_sync(0xffffffffu, s, o);
    float mean = s / (float)W;
    float vs = 0.f;
    #pragma unroll 6
    for (int i = 0; i < npl; i++) {
        float a = v[i].x - mean, b = v[i].y - mean, c = v[i].z - mean, d = v[i].w - mean;
        vs += a * a + b * b + c * c + d * d;
    }
    #pragma unroll
    for (int o = 16; o; o >>= 1) vs += __shfl_xor_sync(0xffffffffu, vs, o);
    float rstd = rsqrtf(vs / (float)W + 1e-5f);
    #pragma unroll 6
    for (int i = 0; i < npl; i++) {
        float a = (v[i].x - mean) * rstd, b = (v[i].y - mean) * rstd;
        float c = (v[i].z - mean) * rstd, d = (v[i].w - mean) * rstd;
        if constexpr (sizeof(OutT) == 4) {
            ((float4*)(y + row * W))[lane + i * 32] = make_float4(a, b, c, d);
        } else {
            uint2 u;
            u.x = __float_as_uint(0.f);  // placeholder, overwritten below
            __nv_bfloat162 p0 = __floats2bfloat162_rn(a, b);
            __nv_bfloat162 p1 = __floats2bfloat162_rn(c, d);
            memcpy(&u.x, &p0, 4);
            memcpy(&u.y, &p1, 4);
            ((uint2*)(y + row * W))[lane + i * 32] = u;
        }
    }
}

// ---------------------------------------------------------------------------
// z projection prep
// ---------------------------------------------------------------------------
__global__ void zprep_kernel(const float* __restrict__ pw, const float* __restrict__ pb,
                             const float* __restrict__ bw, const float* __restrict__ bb,
                             __nv_bfloat16* __restrict__ Wp, float* __restrict__ Wbias) {
    int lh = threadIdx.x;
    if (lh >= 32) return;
    int l = lh >> 4;
    float bs = 0.f;
    for (int c = 0; c < 64; c++) {
        float w = bw[lh * 64 + c];
        Wp[lh * 64 + c] = __float2bfloat16_rn(pw[l * 64 + c] * w);
        bs += pb[l * 64 + c] * w;
    }
    Wbias[lh] = bs + bb[lh];
}

// ---------------------------------------------------------------------------
// z projection: coalesced load -> bf16 smem -> vectorized per-row LN ->
// mma (128x32x64) -> bf16 bias output [h][i*S+j] with coalesced stores.
// ---------------------------------------------------------------------------
__global__ void __launch_bounds__(256) zproj_kernel(const float* __restrict__ z,
                                                    const __nv_bfloat16* __restrict__ Wp,
                                                    const float* __restrict__ Wbias,
                                                    __nv_bfloat16* __restrict__ b0,
                                                    __nv_bfloat16* __restrict__ b1) {
    __shared__ __nv_bfloat16 zb[128][72];
    __shared__ __nv_bfloat16 wsm[32][72];
    __shared__ __nv_bfloat16 sOut[32][136];
    __shared__ float bsm[32];
    int tid = threadIdx.x;
    long long base = (long long)blockIdx.x * 8192;

    #pragma unroll
    for (int i = 0; i < 8; i++) {
        int idx = tid + i * 256;
        float4 t = *(const float4*)&z[base + (long long)idx * 4];
        int r = idx >> 4, c = (idx & 15) * 4;
        *(__nv_bfloat162*)&zb[r][c]     = __floats2bfloat162_rn(t.x, t.y);
        *(__nv_bfloat162*)&zb[r][c + 2] = __floats2bfloat162_rn(t.z, t.w);
    }
    #pragma unroll
    for (int i = 0; i < 8; i++) {
        int idx = tid + i * 256;
        wsm[idx >> 6][idx & 63] = Wp[idx];
    }
    if (tid < 32) bsm[tid] = Wbias[tid];
    __syncthreads();

    // per-row LN, vectorized: thread pair per row, 32 elems each (4 uint4)
    {
        int row = tid >> 1, half = tid & 1;
        uint4* zr = (uint4*)&zb[row][half * 32];
        uint4 u[4];
        float vv[32];
        float s = 0.f, s2 = 0.f;
        #pragma unroll
        for (int i = 0; i < 4; i++) {
            u[i] = zr[i];
            const __nv_bfloat162* p = (const __nv_bfloat162*)&u[i];
            #pragma unroll
            for (int w = 0; w < 4; w++) {
                float2 f = __bfloat1622float2(p[w]);
                vv[i * 8 + w * 2] = f.x; vv[i * 8 + w * 2 + 1] = f.y;
                s += f.x + f.y; s2 += f.x * f.x + f.y * f.y;
            }
        }
        s  += __shfl_xor_sync(0xffffffffu, s, 1);
        s2 += __shfl_xor_sync(0xffffffffu, s2, 1);
        float m = s * (1.f / 64.f);
        float rs = rsqrtf(s2 * (1.f / 64.f) - m * m + 1e-5f);
        #pragma unroll
        for (int i = 0; i < 4; i++) {
            __nv_bfloat162* p = (__nv_bfloat162*)&u[i];
            #pragma unroll
            for (int w = 0; w < 4; w++)
                p[w] = __floats2bfloat162_rn((vv[i * 8 + w * 2] - m) * rs,
                                             (vv[i * 8 + w * 2 + 1] - m) * rs);
            zr[i] = u[i];
        }
    }
    __syncthreads();

    int w = tid >> 5, lane = tid & 31, qr = lane >> 2, qc = lane & 3;
    float acc[4][4] = {};
    const uint32_t* zw = (const uint32_t*)&zb[0][0];    // word pitch 36
    const uint32_t* ww = (const uint32_t*)&wsm[0][0];
    #pragma unroll
    for (int kc = 0; kc < 4; kc++) {
        uint32_t af[4];
        int r = w * 16 + qr;
        af[0] = zw[r * 36 + kc * 8 + qc];
        af[1] = zw[(r + 8) * 36 + kc * 8 + qc];
        af[2] = zw[r * 36 + kc * 8 + 4 + qc];
        af[3] = zw[(r + 8) * 36 + kc * 8 + 4 + qc];
        #pragma unroll
        for (int j = 0; j < 4; j++) {
            int n = j * 8 + qr;
            mma_bf16(acc[j], af, ww[n * 36 + kc * 8 + qc], ww[n * 36 + kc * 8 + 4 + qc]);
        }
    }
    #pragma unroll
    for (int j = 0; j < 4; j++) {
        #pragma unroll
        for (int e = 0; e < 4; e++) {
            int mm = w * 16 + qr + ((e >= 2) ? 8 : 0);
            int n = j * 8 + 2 * qc + (e & 1);
            sOut[n][mm] = __float2bfloat16_rn(acc[j][e] + bsm[n]);
        }
    }
    __syncthreads();
    long long rg0 = (long long)blockIdx.x * 128;
    #pragma unroll
    for (int it = 0; it < 2; it++) {
        int lh = tid >> 3, part = (tid & 7) + it * 8;
        uint4 v = *(const uint4*)&sOut[lh][part * 8];
        __nv_bfloat16* dst = ((lh < 16) ? b0 : b1) +
                             (long long)(lh & 15) * S2_ + rg0 + part * 8;
        *(uint4*)dst = v;
    }
}

// ---------------------------------------------------------------------------
// Fused scores+softmax: per block = (head, 128 k-rows r) x all 1024 t.
// Writes TRANSPOSED unnormalized P:  Pt[h][t][r] = exp(q[h,t]·k[h,r]/48 + bias)
// rinv[h,r] = 1/sum_t.  Dynamic smem 82944B.
// ---------------------------------------------------------------------------
__global__ void __launch_bounds__(256) attn_sm_kernel(
    const __nv_bfloat16* __restrict__ kvg,
    const __nv_bfloat16* __restrict__ q,
    const __nv_bfloat16* __restrict__ bias,
    __nv_bfloat16* __restrict__ Pt,          // [H][t][r]
    float* __restrict__ rinv) {
    const int h = blockIdx.y;
    const int bm = blockIdx.x * 128;
    const int tid = threadIdx.x, lane = tid & 31, warp = tid >> 5;
    const int wm = warp >> 1, wn = warp & 1;
    const int qr = lane >> 2, qc = lane & 3;

    extern __shared__ char smraw[];
    __nv_bfloat16* Ks  = (__nv_bfloat16*)smraw;            // [128][56]
    __nv_bfloat16* Qs  = Ks + 128 * 56;                    // [2][64][56]
    __nv_bfloat16* Bsm = Qs + 2 * 64 * 56;                 // [2][128][72]
    __nv_bfloat16* sP  = Bsm + 2 * 128 * 72;               // [64][136]
    __shared__ float rs[128];

    const __nv_bfloat16* kbase = kvg + (long long)h * S_ * C3_;
    for (int id = tid; id < 128 * 24; id += 256) {
        int r = id / 24, c2 = id % 24;
        *(__nv_bfloat162*)&Ks[r * 56 + c2 * 2] =
            *(const __nv_bfloat162*)&kbase[(long long)(bm + r) * C3_ + c2 * 2];
    }
    if (tid < 128) rs[tid] = 0.f;

    const __nv_bfloat16* qbase = q + (long long)h * S_ * CH_;
    const __nv_bfloat16* bbase = bias + (long long)h * S2_;
    __nv_bfloat16* ptbase = Pt + (long long)h * S2_;
    uint32_t qS = (uint32_t)__cvta_generic_to_shared(Qs);
    uint32_t bS = (uint32_t)__cvta_generic_to_shared(Bsm);

    auto issue = [&](int st, int tc) {
        if (tid < 192) {
            int t = tid / 3, seg = tid % 3;
            cp16(qS + st * 64 * 112 + t * 112 + seg * 16,
                 qbase + (long long)(tc * 64 + t) * CH_ + seg * 8, 16);
        }
        #pragma unroll
        for (int i = 0; i < 4; i++) {
            int id = tid + i * 256;
            int r = id >> 3, seg = id & 7;
            cp16(bS + st * 128 * 144 + r * 144 + seg * 16,
                 bbase + (long long)(bm + r) * S_ + tc * 64 + seg * 8, 16);
        }
    };

    float rowacc[2][2] = {};
    issue(0, 0);
    CP_COMMIT();

    for (int tc = 0; tc < 16; tc++) {
        asm volatile("cp.async.wait_group 0;\n" ::);
        __syncthreads();
        if (tc + 1 < 16) issue((tc + 1) & 1, tc + 1);
        CP_COMMIT();
        int st = tc & 1;
        float acc[2][4][4] = {};
        #pragma unroll
        for (int ks = 0; ks < 3; ks++) {
            uint32_t af[2][4];
            #pragma unroll
            for (int i = 0; i < 2; i++) {
                int r = wm * 32 + i * 16 + qr;
                const uint32_t* a0 = (const uint32_t*)&Ks[r * 56];
                const uint32_t* a8 = (const uint32_t*)&Ks[(r + 8) * 56];
                af[i][0] = a0[ks * 8 + qc];
                af[i][1] = a8[ks * 8 + qc];
                af[i][2] = a0[ks * 8 + 4 + qc];
                af[i][3] = a8[ks * 8 + 4 + qc];
            }
            #pragma unroll
            for (int j = 0; j < 4; j++) {
                int n = wn * 32 + j * 8 + qr;
                const uint32_t* br = (const uint32_t*)&Qs[st * 64 * 56 + n * 56];
                uint32_t b0 = br[ks * 8 + qc];
                uint32_t b1 = br[ks * 8 + 4 + qc];
                #pragma unroll
                for (int i = 0; i < 2; i++) mma_bf16(acc[i][j], af[i], b0, b1);
            }
        }
        // epilogue: exp(acc/48 + bias) -> staged transposed sP[t][r], rowacc
        #pragma unroll
        for (int i = 0; i < 2; i++) {
            #pragma unroll
            for (int eh = 0; eh < 2; eh++) {
                int ml = wm * 32 + i * 16 + qr + eh * 8;
                const __nv_bfloat16* brow = &Bsm[st * 128 * 72 + ml * 72];
                float part = 0.f;
                #pragma unroll
                for (int j = 0; j < 4; j++) {
                    int nl = wn * 32 + j * 8 + 2 * qc;
                    __nv_bfloat162 bb = *(const __nv_bfloat162*)&brow[nl];
                    float v0 = acc[i][j][eh * 2 + 0] * (1.f / 48.f) + toF(bb.x);
                    float v1 = acc[i][j][eh * 2 + 1] * (1.f / 48.f) + toF(bb.y);
                    float e0 = __expf(v0), e1 = __expf(v1);
                    sP[nl * 136 + ml]       = __float2bfloat16_rn(e0);
                    sP[(nl + 1) * 136 + ml] = __float2bfloat16_rn(e1);
                    part += e0 + e1;
                }
                rowacc[i][eh] += part;
            }
        }
        __syncthreads();
        // coalesced transposed store: Pt rows t = tc*64 + trow, cols [bm, bm+128)
        #pragma unroll
        for (int it = 0; it < 4; it++) {
            int id = tid + it * 256;
            int trow = id >> 4, chunk = id & 15;
            uint4 v = *(const uint4*)&sP[trow * 136 + chunk * 8];
            *(uint4*)&ptbase[(long long)(tc * 64 + trow) * S_ + bm + chunk * 8] = v;
        }
    }
    #pragma unroll
    for (int i = 0; i < 2; i++) {
        #pragma unroll
        for (int eh = 0; eh < 2; eh++) {
            float v = rowacc[i][eh];
            v += __shfl_xor_sync(0xffffffffu, v, 1);
            v += __shfl_xor_sync(0xffffffffu, v, 2);
            if (qc == 0) atomicAdd(&rs[wm * 32 + i * 16 + qr + eh * 8], v);
        }
    }
    __syncthreads();
    if (tid < 128) rinv[h * S_ + bm + tid] = 1.0f / rs[tid];
}

// ---------------------------------------------------------------------------
// Vt[h][c][r] = v[h][r][c] * rinv[h][r]  (transpose + scale, bf16)
// ---------------------------------------------------------------------------
__global__ void __launch_bounds__(256) vt_kernel(const __nv_bfloat16* __restrict__ kvg,
                                                 const float* __restrict__ rinv,
                                                 __nv_bfloat16* __restrict__ vt) {
    __shared__ __nv_bfloat16 sv[48][136];
    int h = blockIdx.y, bm = blockIdx.x * 128, tid = threadIdx.x;
    const __nv_bfloat16* vbase = kvg + (long long)h * S_ * C3_ + CH_;
    for (int id = tid; id < 128 * 24; id += 256) {
        int r = id / 24, c2 = id % 24;
        __nv_bfloat162 v = *(const __nv_bfloat162*)&vbase[(long long)(bm + r) * C3_ + 2 * c2];
        float sc = rinv[h * S_ + bm + r];
        sv[2 * c2][r]     = __float2bfloat16_rn(toF(v.x) * sc);
        sv[2 * c2 + 1][r] = __float2bfloat16_rn(toF(v.y) * sc);
    }
    __syncthreads();
    for (int id = tid; id < 48 * 16; id += 256) {
        int c = id >> 4, chunk = id & 15;
        *(uint4*)&vt[(long long)h * CH_ * S_ + (long long)c * S_ + bm + chunk * 8] =
            *(const uint4*)&sv[c][chunk * 8];
    }
}

// ---------------------------------------------------------------------------
// Tensor-core bf16 GEMM (NT):  C[m,n] = sum_k A[m,k] * B[n,k]
// cp.async multi-stage ring, ONE sync per k-chunk.
// Block tile 128x64, BK=32, 256 threads (8 warps, 4x2), warp tile 32x32.
// M%128==0. N<64 allowed only if B buffer is padded (reads rows [N,64)).
// ---------------------------------------------------------------------------
enum { EPI_PLAIN = 0, EPI_GSIG = 2, EPI_OUTGATE = 3,
       EPI_TRFIN = 4, EPI_ADALN = 5, EPI_GLU = 6 };

template <int EPI, bool DUAL, typename OutT, typename AuxT>
__global__ void __launch_bounds__(256) gemm_tc(
    const __nv_bfloat16* __restrict__ A, const __nv_bfloat16* __restrict__ B1,
    const __nv_bfloat16* __restrict__ B2, const float* __restrict__ bias,
    const AuxT* __restrict__ aux, const float* __restrict__ aux2,
    OutT* __restrict__ Cp,
    int M, int N, int K, int lda, int ldb, int ldc, int aux_ld,
    long long sA, long long sB, long long sC, long long sAux) {
    constexpr int NST = DUAL ? 2 : 3;
    const int tid = threadIdx.x;
    const int lane = tid & 31, warp = tid >> 5;
    const int wm = warp >> 1, wn = warp & 1;
    const int bm = blockIdx.y * 128, bn = blockIdx.x * 64;
    const int bz = blockIdx.z;
    A += bz * sA;
    B1 += bz * sB;
    if constexpr (DUAL) B2 += bz * sB;
    Cp += bz * sC;
    if (aux) aux += bz * sAux;

    __shared__ __nv_bfloat16 As[NST][128][40];
    __shared__ __nv_bfloat16 Bs1[NST][64][40];
    __shared__ __nv_bfloat16 Bs2[DUAL ? NST : 1][64][40];

    float acc1[2][4][4] = {};
    float acc2[2][4][4] = {};
    const int qr = lane >> 2, qc = lane & 3;
    const int nk = (K + 31) / 32;

    auto do_mma = [&](int st) {
        #pragma unroll
        for (int ks = 0; ks < 2; ks++) {
            uint32_t af[2][4];
            #pragma unroll
            for (int i = 0; i < 2; i++) {
                int r = wm * 32 + i * 16 + qr;
                const uint32_t* arow  = (const uint32_t*)&As[st][r][0];
                const uint32_t* arow8 = (const uint32_t*)&As[st][r + 8][0];
                af[i][0] = arow[ks * 8 + qc];
                af[i][1] = arow8[ks * 8 + qc];
                af[i][2] = arow[ks * 8 + 4 + qc];
                af[i][3] = arow8[ks * 8 + 4 + qc];
            }
            #pragma unroll
            for (int j = 0; j < 4; j++) {
                int n = wn * 32 + j * 8 + qr;
                const uint32_t* brow = (const uint32_t*)&Bs1[st][n][0];
                uint32_t b0 = brow[ks * 8 + qc];
                uint32_t b1 = brow[ks * 8 + 4 + qc];
                #pragma unroll
                for (int i = 0; i < 2; i++) mma_bf16(acc1[i][j], af[i], b0, b1);
                if constexpr (DUAL) {
                    const uint32_t* brow2 = (const uint32_t*)&Bs2[st][n][0];
                    uint32_t c0 = brow2[ks * 8 + qc];
                    uint32_t c1 = brow2[ks * 8 + 4 + qc];
                    #pragma unroll
                    for (int i = 0; i < 2; i++) mma_bf16(acc2[i][j], af[i], c0, c1);
                }
            }
        }
    };

    uint32_t aBase = (uint32_t)__cvta_generic_to_shared(&As[0][0][0]);
    uint32_t bBase = (uint32_t)__cvta_generic_to_shared(&Bs1[0][0][0]);
    uint32_t b2Base = 0;
    if constexpr (DUAL) b2Base = (uint32_t)__cvta_generic_to_shared(&Bs2[0][0][0]);

    auto issue = [&](int st, int k0) {
        #pragma unroll
        for (int i = 0; i < 2; i++) {
            int id = tid + i * 256;
            int r = id >> 2, cp4 = id & 3;
            int kk = k0 + cp4 * 8;
            const __nv_bfloat16* src = A + (long long)(bm + r) * lda + kk;
            int sb = (kk < K) ? 16 : 0;
            if (!sb) src = A;
            cp16(aBase + st * 128 * 80 + r * 80 + cp4 * 16, src, sb);
        }
        {
            int r = tid >> 2, cp4 = tid & 3;
            int kk = k0 + cp4 * 8;
            int sb = (kk < K) ? 16 : 0;
            const __nv_bfloat16* src = B1 + (long long)(bn + r) * ldb + kk;
            if (!sb) src = B1;
            cp16(bBase + st * 64 * 80 + r * 80 + cp4 * 16, src, sb);
            if constexpr (DUAL) {
                const __nv_bfloat16* src2 = B2 + (long long)(bn + r) * ldb + kk;
                if (!sb) src2 = B2;
                cp16(b2Base + st * 64 * 80 + r * 80 + cp4 * 16, src2, sb);
            }
        }
    };

    #pragma unroll
    for (int p = 0; p < NST - 1; p++) {
        if (p < nk) issue(p, p * 32);
        CP_COMMIT();
    }
    for (int ic = 0; ic < nk; ic++) {
        if constexpr (NST == 3) asm volatile("cp.async.wait_group 1;\n" ::);
        else                    asm volatile("cp.async.wait_group 0;\n" ::);
        __syncthreads();
        int pn = ic + NST - 1;
        if (pn < nk) issue(pn % NST, pn * 32);
        CP_COMMIT();
        do_mma(ic % NST);
    }

    // ---- epilogue ----
    #pragma unroll
    for (int i = 0; i < 2; i++) {
        #pragma unroll
        for (int j = 0; j < 4; j++) {
            int m0 = bm + wm * 32 + i * 16 + qr;
            int n0 = bn + wn * 32 + j * 8 + 2 * qc;
            #pragma unroll
            for (int e = 0; e < 4; e++) {
                int m = m0 + ((e >= 2) ? 8 : 0);
                int n = n0 + (e & 1);
                if (n >= N) continue;
                long long cidx = (long long)m * ldc + n;
                float v = acc1[i][j][e];
                float out;
                if constexpr (EPI == EPI_PLAIN) {
                    out = v + (bias ? bias[n] : 0.f);
                } else if constexpr (EPI == EPI_GSIG) {
                    out = sigf(toF(aux[(long long)m * aux_ld + n])) * v;
                } else if constexpr (EPI == EPI_OUTGATE) {
                    out = sigf(v + bias[n]) * toF(aux[(long long)m * aux_ld + n]);
                } else if constexpr (EPI == EPI_TRFIN) {
                    out = aux2[(long long)m * aux_ld + n] +
                          sigf((v + bias[n]) * toF(aux[(long long)m * aux_ld + n]));
                } else if constexpr (EPI == EPI_ADALN) {
                    out = sigf((v + bias[n]) * toF(aux[(long long)m * aux_ld + n]) + acc2[i][j][e]);
                } else {  // EPI_GLU
                    out = v * sigf(v) * acc2[i][j][e];
                }
                storeOut(out, &Cp[cidx]);
            }
        }
    }
}

// ---------------------------------------------------------------------------
// Host orchestration
// ---------------------------------------------------------------------------
extern "C" void kernel_launch(void* const* d_in, const int* in_sizes, int n_in,
                              void* d_out, int out_size) {
    const float* A0        = (const float*)d_in[0];
    const float* Sm        = (const float*)d_in[1];
    const float* Z         = (const float*)d_in[2];
    const float* attn_sn_w = (const float*)d_in[3];
    const float* attn_pb_w = (const float*)d_in[4];
    const float* attn_pb_b = (const float*)d_in[5];
    const float* attn_pnb_w= (const float*)d_in[6];
    const float* pair_w    = (const float*)d_in[7];
    const float* pair_b    = (const float*)d_in[8];
    const float* q_w       = (const float*)d_in[9];
    const float* q_b       = (const float*)d_in[10];
    const float* kvg_w     = (const float*)d_in[11];
    const float* bias_w    = (const float*)d_in[12];
    const float* bias_b    = (const float*)d_in[13];
    const float* ao_w      = (const float*)d_in[14];
    const float* out_w     = (const float*)d_in[15];
    const float* out_b     = (const float*)d_in[16];
    const float* tr_sn_w   = (const float*)d_in[17];
    const float* tr_pb_w   = (const float*)d_in[18];
    const float* tr_pb_b   = (const float*)d_in[19];
    const float* tr_pnb_w  = (const float*)d_in[20];
    const float* tr_a_w    = (const float*)d_in[21];
    const float* tr_s_w    = (const float*)d_in[22];
    const float* tr_s_b    = (const float*)d_in[23];
    const float* tr_b_w    = (const float*)d_in[24];
    float* OUT = (float*)d_out;

    float *an, *amm, *aout, *tmm, *anew, *wbias, *rinv;
    __nv_bfloat16 *bb0, *bb1, *wbf, *shatb, *a2b, *qb, *kvgb, *obb, *bbb, *pbf, *vtb, *wpbf;
    cudaGetSymbolAddress((void**)&an, g_an);
    cudaGetSymbolAddress((void**)&amm, g_amm);
    cudaGetSymbolAddress((void**)&aout, g_aout);
    cudaGetSymbolAddress((void**)&tmm, g_tmm);
    cudaGetSymbolAddress((void**)&anew, g_anew);
    cudaGetSymbolAddress((void**)&wbias, g_wbias);
    cudaGetSymbolAddress((void**)&rinv, g_rinv);
    cudaGetSymbolAddress((void**)&bb0, g_bb0);
    cudaGetSymbolAddress((void**)&bb1, g_bb1);
    cudaGetSymbolAddress((void**)&wbf, g_wbf);
    cudaGetSymbolAddress((void**)&shatb, g_shatb);
    cudaGetSymbolAddress((void**)&a2b, g_a2b);
    cudaGetSymbolAddress((void**)&qb, g_qb);
    cudaGetSymbolAddress((void**)&kvgb, g_kvgb);
    cudaGetSymbolAddress((void**)&obb, g_obb);
    cudaGetSymbolAddress((void**)&bbb, g_bbb);
    cudaGetSymbolAddress((void**)&pbf, g_pbf);
    cudaGetSymbolAddress((void**)&vtb, g_vtb);
    cudaGetSymbolAddress((void**)&wpbf, g_wpbf);

    cudaFuncSetAttribute(attn_sm_kernel, cudaFuncAttributeMaxDynamicSharedMemorySize, 82944);

    // ---- build conversion table + record weight offsets ----
    CvtArgs ca;
    long long off = 0;
    int ns = 0;
    long long wo_pb[2], wo_pnb[2], wo_q[2], wo_kvg[2], wo_ao[2], wo_out[2];
    long long wo_trpb[2], wo_trpnb[2], wo_tra[2], wo_trs[2], wo_trb[2], wo_s;
    auto seg = [&](const float* s, int len, const float* sc) -> long long {
        ca.src[ns] = s; ca.scl[ns] = sc; ca.dst[ns] = wbf + off; ca.len[ns] = len;
        long long o = off; off += len; ns++; return o;
    };
    for (int l = 0; l < 2; l++) {
        wo_pb[l]    = seg(attn_pb_w  + (long long)l * CA_ * CS_, CA_ * CS_, attn_sn_w + l * CS_);
        wo_pnb[l]   = seg(attn_pnb_w + (long long)l * CA_ * CS_, CA_ * CS_, attn_sn_w + l * CS_);
        wo_q[l]     = seg(q_w   + (long long)l * CA_ * CA_, CA_ * CA_, nullptr);
        wo_kvg[l]   = seg(kvg_w + (long long)l * 3 * CA_ * CA_, 3 * CA_ * CA_, nullptr);
        wo_ao[l]    = seg(ao_w  + (long long)l * CA_ * CA_, CA_ * CA_, nullptr);
        wo_out[l]   = seg(out_w + (long long)l * CA_ * CS_, CA_ * CS_, nullptr);
        wo_trpb[l]  = seg(tr_pb_w  + (long long)l * CA_ * CS_, CA_ * CS_, tr_sn_w + l * CS_);
        wo_trpnb[l] = seg(tr_pnb_w + (long long)l * CA_ * CS_, CA_ * CS_, tr_sn_w + l * CS_);
        wo_tra[l]   = seg(tr_a_w + (long long)l * 4 * CA_ * CA_, 4 * CA_ * CA_, nullptr);
        wo_trs[l]   = seg(tr_s_w + (long long)l * CA_ * CS_, CA_ * CS_, nullptr);
        wo_trb[l]   = seg(tr_b_w + (long long)l * 2 * CA_ * CA_, 2 * CA_ * CA_, nullptr);
    }
    wo_s = seg(Sm, S_ * CS_, nullptr);
    ca.smod = CS_;
    ca.nseg = ns;

    cvt_kernel<<<dim3(128, ns), 256>>>(ca);
    ln_kernel<__nv_bfloat16><<<S_ / 8, 256>>>(Sm, shatb, CS_);
    zprep_kernel<<<1, 32>>>(pair_w, pair_b, bias_w, bias_b, wpbf, wbias);
    zproj_kernel<<<(S_ * S_) / 128, 256>>>(Z, wpbf, wbias, bb0, bb1);

    const __nv_bfloat16* s_bf = wbf + wo_s;

    for (int l = 0; l < 2; l++) {
        const float* ain = l ? anew : A0;
        float* aoutp = l ? OUT : anew;
        const __nv_bfloat16* bbl = l ? bb1 : bb0;

        ln_kernel<float><<<S_ / 8, 256>>>(ain, an, CA_);

        // adaLN (attention): a2 = sigmoid((sn@pbW^T + pb_b)*an + sn@pnbW^T)
        gemm_tc<EPI_ADALN, true, __nv_bfloat16, float><<<dim3(12, 8, 1), 256>>>(
            shatb, wbf + wo_pb[l], wbf + wo_pnb[l], attn_pb_b + (long long)l * CA_,
            an, nullptr, a2b,
            S_, CA_, CS_, CS_, CS_, CA_, CA_, 0, 0, 0, 0);

        // q = a2 @ q_w^T + q_b
        gemm_tc<EPI_PLAIN, false, __nv_bfloat16, float><<<dim3(12, 8, 1), 256>>>(
            a2b, wbf + wo_q[l], nullptr, q_b + (long long)l * CA_,
            nullptr, nullptr, qb,
            S_, CA_, CA_, CA_, CA_, CA_, 0, 0, 0, 0, 0);

        // kvg = a2 @ kvg_w^T
        gemm_tc<EPI_PLAIN, false, __nv_bfloat16, float><<<dim3(36, 8, 1), 256>>>(
            a2b, wbf + wo_kvg[l], nullptr, nullptr,
            nullptr, nullptr, kvgb,
            S_, 3 * CA_, CA_, CA_, CA_, 3 * CA_, 0, 0, 0, 0, 0);

        // fused scores + softmax -> transposed unnormalized Pt + rinv
        attn_sm_kernel<<<dim3(8, 16), 256, 82944>>>(kvgb, qb, bbl, pbf, rinv);

        // Vt = V * rinv (transpose + scale)
        vt_kernel<<<dim3(8, 16), 256>>>(kvgb, rinv, vtb);

        // o[t,c] = sum_r Pt[t,r]*Vt[c,r];  fused sigmoid(g)*o   (async NT)
        gemm_tc<EPI_GSIG, false, __nv_bfloat16, __nv_bfloat16><<<dim3(1, 8, 16), 256>>>(
            pbf, vtb, nullptr, nullptr, kvgb + 2 * CH_, nullptr, obb,
            S_, CH_, S_, S_, S_, CH_, C3_,
            (long long)S2_, (long long)CH_ * S_, (long long)S_ * CH_,
            (long long)S_ * C3_);

        // attn_mm = (sig(g)*o) @ ao_w^T
        gemm_tc<EPI_PLAIN, false, float, float><<<dim3(12, 8, 1), 256>>>(
            obb, wbf + wo_ao[l], nullptr, nullptr, nullptr, nullptr, amm,
            S_, CA_, CA_, CA_, CA_, CA_, 0, 0, 0, 0, 0);

        // attn_out = sigmoid(s @ out_w^T + out_b) * attn_mm
        gemm_tc<EPI_OUTGATE, false, float, float><<<dim3(12, 8, 1), 256>>>(
            s_bf, wbf + wo_out[l], nullptr, out_b + (long long)l * CA_,
            amm, nullptr, aout,
            S_, CA_, CS_, CS_, CS_, CA_, CA_, 0, 0, 0, 0);

        // adaLN (transition) -> a3
        gemm_tc<EPI_ADALN, true, __nv_bfloat16, float><<<dim3(12, 8, 1), 256>>>(
            shatb, wbf + wo_trpb[l], wbf + wo_trpnb[l], tr_pb_b + (long long)l * CA_,
            an, nullptr, a2b,
            S_, CA_, CS_, CS_, CS_, CA_, CA_, 0, 0, 0, 0);

        // bb = silu(a3 @ W1^T) * (a3 @ W2^T)
        gemm_tc<EPI_GLU, true, __nv_bfloat16, float><<<dim3(24, 8, 1), 256>>>(
            a2b, wbf + wo_tra[l], wbf + wo_tra[l] + (long long)2 * CA_ * CA_, nullptr,
            nullptr, nullptr, bbb,
            S_, 2 * CA_, CA_, CA_, CA_, 2 * CA_, 0, 0, 0, 0, 0);

        // tmm = bb @ tr_b_w^T
        gemm_tc<EPI_PLAIN, false, float, float><<<dim3(12, 8, 1), 256>>>(
            bbb, wbf + wo_trb[l], nullptr, nullptr, nullptr, nullptr, tmm,
            S_, CA_, 2 * CA_, 2 * CA_, 2 * CA_, CA_, 0, 0, 0, 0, 0);

        // a_next = attn_out + sigmoid((s @ tr_s_w^T + tr_s_b) * tmm)
        gemm_tc<EPI_TRFIN, false, float, float><<<dim3(12, 8, 1), 256>>>(
            s_bf, wbf + wo_trs[l], nullptr, tr_s_b + (long long)l * CA_,
            tmm, aout, aoutp,
            S_, CA_, CS_, CS_, CS_, CA_, CA_, 0, 0, 0, 0);
    }
}

// round 12
// speedup vs baseline: 5.1144x; 1.1328x over previous
#include <cuda_runtime.h>
#include <cuda_bf16.h>
#include <math.h>
#include <stdint.h>

// Problem constants
#define S_   1024
#define CA_  768
#define CS_  384
#define CZ_  64
#define H_   16
#define CH_  48     // head dim
#define C3_  144    // 3*CH
#define S2_  (S_ * S_)

// ---------------------------------------------------------------------------
// Static scratch (device globals — no cudaMalloc allowed)
// ---------------------------------------------------------------------------
__device__ float g_an[S_ * CA_];           // LN(a) per layer (fp32 aux)
__device__ float g_aout[S_ * CA_];         // gated attention output
__device__ float g_anew[S_ * CA_];         // a after layer 0
__device__ float g_wbias[32];
__device__ float g_sg[S_ * 3072];          // [og l0 | tg l0 | og l1 | tg l1]
__device__ float g_adab[3072];             // stacked adaLN biases (2 layers)
__device__ float g_sgb[3072];              // stacked sgate biases

__device__ __align__(16) __nv_bfloat16 g_bb0[H_ * S2_];   // layer-0 bias [h][i][j]
__device__ __align__(16) __nv_bfloat16 g_bb1[H_ * S2_];   // layer-1 bias
__device__ __align__(16) __nv_bfloat16 g_wbf[16908288];   // all weights + s, bf16
__device__ __align__(16) __nv_bfloat16 g_shatb[S_ * CS_];
__device__ __align__(16) __nv_bfloat16 g_a23b[S_ * 1536]; // a2 | a3
__device__ __align__(16) __nv_bfloat16 g_qb[S_ * CA_];
__device__ __align__(16) __nv_bfloat16 g_kvgb[S_ * 3 * CA_];
__device__ __align__(16) __nv_bfloat16 g_obb[S_ * CA_];
__device__ __align__(16) __nv_bfloat16 g_bbb[S_ * 2 * CA_];
__device__ __align__(16) __nv_bfloat16 g_pbf[H_ * S2_];   // Pt (transposed, unnormalized)
__device__ __align__(16) __nv_bfloat16 g_vtb[H_ * CH_ * S_ + 64 * S_];  // Vt scaled (+pad)
__device__ __align__(16) __nv_bfloat16 g_wpbf[32 * 64];   // folded z-proj weights

// ---------------------------------------------------------------------------
// Helpers
// ---------------------------------------------------------------------------
__device__ __forceinline__ float sigf(float x) { return 1.0f / (1.0f + expf(-x)); }

__device__ __forceinline__ void mma_bf16(float* d, const uint32_t* a,
                                         uint32_t b0, uint32_t b1) {
    asm volatile(
        "mma.sync.aligned.m16n8k16.row.col.f32.bf16.bf16.f32 "
        "{%0,%1,%2,%3}, {%4,%5,%6,%7}, {%8,%9}, {%0,%1,%2,%3};"
        : "+f"(d[0]), "+f"(d[1]), "+f"(d[2]), "+f"(d[3])
        : "r"(a[0]), "r"(a[1]), "r"(a[2]), "r"(a[3]), "r"(b0), "r"(b1));
}

__device__ __forceinline__ void cp16(uint32_t smem, const void* g, int sbytes) {
    asm volatile("cp.async.cg.shared.global [%0], [%1], 16, %2;\n"
                 :: "r"(smem), "l"(g), "r"(sbytes));
}
#define CP_COMMIT() asm volatile("cp.async.commit_group;\n" ::)

__device__ __forceinline__ float toF(float v) { return v; }
__device__ __forceinline__ float toF(__nv_bfloat16 v) { return __bfloat162float(v); }
__device__ __forceinline__ void storeOut(float v, float* p) { *p = v; }
__device__ __forceinline__ void storeOut(float v, __nv_bfloat16* p) { *p = __float2bfloat16_rn(v); }

// ---------------------------------------------------------------------------
// Weight/act conversion fp32 -> bf16 (optionally scaling columns by scl[c])
// ---------------------------------------------------------------------------
struct CvtArgs {
    const float* src[24];
    const float* scl[24];
    __nv_bfloat16* dst[24];
    int len[24];
    int smod;
    int nseg;
};

__global__ void __launch_bounds__(256) cvt_kernel(CvtArgs a) {
    int s = blockIdx.y;
    if (s >= a.nseg) return;
    const float* src = a.src[s];
    const float* scl = a.scl[s];
    __nv_bfloat16* dst = a.dst[s];
    int n = a.len[s];
    for (long long i = (long long)(blockIdx.x * 256 + threadIdx.x) * 2; i < n;
         i += (long long)gridDim.x * 512) {
        float2 v = *(const float2*)&src[i];
        if (scl) { int c = (int)(i % a.smod); v.x *= scl[c]; v.y *= scl[c + 1]; }
        *(__nv_bfloat162*)&dst[i] = __floats2bfloat162_rn(v.x, v.y);
    }
}

// ---------------------------------------------------------------------------
// Stacked bias prep: adab = [attn_pb_b l0, tr_pb_b l0, attn_pb_b l1, tr_pb_b l1]
//                    sgb  = [out_b l0, tr_s_b l0, out_b l1, tr_s_b l1]
// ---------------------------------------------------------------------------
__global__ void bias_prep(const float* __restrict__ apb_b, const float* __restrict__ trpb_b,
                          const float* __restrict__ out_b, const float* __restrict__ tr_s_b,
                          float* __restrict__ adab, float* __restrict__ sgb) {
    int i = blockIdx.x * 256 + threadIdx.x;
    if (i < 3072) {
        int l = i / 1536, n = i % 1536;
        adab[i] = (n < CA_) ? apb_b[l * CA_ + n] : trpb_b[l * CA_ + n - CA_];
    } else if (i < 6144) {
        int j = i - 3072;
        int l = j / 1536, n = j % 1536;
        sgb[j] = (n < CA_) ? out_b[l * CA_ + n] : tr_s_b[l * CA_ + n - CA_];
    }
}

// ---------------------------------------------------------------------------
// LayerNorm (no affine): one WARP per row, 8 rows/block. W % 128 == 0, W<=768.
// ---------------------------------------------------------------------------
template <typename OutT>
__global__ void __launch_bounds__(256) ln_kernel(const float* __restrict__ x,
                                                 OutT* __restrict__ y, int W) {
    int warp = threadIdx.x >> 5, lane = threadIdx.x & 31;
    long long row = (long long)blockIdx.x * 8 + warp;
    const float4* xr = (const float4*)(x + row * W);
    int npl = W >> 7;
    float4 v[6];
    float s = 0.f;
    #pragma unroll 6
    for (int i = 0; i < npl; i++) {
        v[i] = xr[lane + i * 32];
        s += v[i].x + v[i].y + v[i].z + v[i].w;
    }
    #pragma unroll
    for (int o = 16; o; o >>= 1) s += __shfl_xor_sync(0xffffffffu, s, o);
    float mean = s / (float)W;
    float vs = 0.f;
    #pragma unroll 6
    for (int i = 0; i < npl; i++) {
        float a = v[i].x - mean, b = v[i].y - mean, c = v[i].z - mean, d = v[i].w - mean;
        vs += a * a + b * b + c * c + d * d;
    }
    #pragma unroll
    for (int o = 16; o; o >>= 1) vs += __shfl_xor_sync(0xffffffffu, vs, o);
    float rstd = rsqrtf(vs / (float)W + 1e-5f);
    #pragma unroll 6
    for (int i = 0; i < npl; i++) {
        float a = (v[i].x - mean) * rstd, b = (v[i].y - mean) * rstd;
        float c = (v[i].z - mean) * rstd, d = (v[i].w - mean) * rstd;
        if constexpr (sizeof(OutT) == 4) {
            ((float4*)(y + row * W))[lane + i * 32] = make_float4(a, b, c, d);
        } else {
            uint2 u;
            __nv_bfloat162 p0 = __floats2bfloat162_rn(a, b);
            __nv_bfloat162 p1 = __floats2bfloat162_rn(c, d);
            memcpy(&u.x, &p0, 4);
            memcpy(&u.y, &p1, 4);
            ((uint2*)(y + row * W))[lane + i * 32] = u;
        }
    }
}

// ---------------------------------------------------------------------------
// z projection prep
// ---------------------------------------------------------------------------
__global__ void zprep_kernel(const float* __restrict__ pw, const float* __restrict__ pb,
                             const float* __restrict__ bw, const float* __restrict__ bb,
                             __nv_bfloat16* __restrict__ Wp, float* __restrict__ Wbias) {
    int lh = threadIdx.x;
    if (lh >= 32) return;
    int l = lh >> 4;
    float bs = 0.f;
    for (int c = 0; c < 64; c++) {
        float w = bw[lh * 64 + c];
        Wp[lh * 64 + c] = __float2bfloat16_rn(pw[l * 64 + c] * w);
        bs += pb[l * 64 + c] * w;
    }
    Wbias[lh] = bs + bb[lh];
}

// ---------------------------------------------------------------------------
// z projection: coalesced load -> bf16 smem -> vectorized per-row LN ->
// mma (128x32x64) -> bf16 bias output [h][i*S+j] with coalesced stores.
// ---------------------------------------------------------------------------
__global__ void __launch_bounds__(256) zproj_kernel(const float* __restrict__ z,
                                                    const __nv_bfloat16* __restrict__ Wp,
                                                    const float* __restrict__ Wbias,
                                                    __nv_bfloat16* __restrict__ b0,
                                                    __nv_bfloat16* __restrict__ b1) {
    __shared__ __nv_bfloat16 zb[128][72];
    __shared__ __nv_bfloat16 wsm[32][72];
    __shared__ __nv_bfloat16 sOut[32][136];
    __shared__ float bsm[32];
    int tid = threadIdx.x;
    long long base = (long long)blockIdx.x * 8192;

    #pragma unroll
    for (int i = 0; i < 8; i++) {
        int idx = tid + i * 256;
        float4 t = *(const float4*)&z[base + (long long)idx * 4];
        int r = idx >> 4, c = (idx & 15) * 4;
        *(__nv_bfloat162*)&zb[r][c]     = __floats2bfloat162_rn(t.x, t.y);
        *(__nv_bfloat162*)&zb[r][c + 2] = __floats2bfloat162_rn(t.z, t.w);
    }
    #pragma unroll
    for (int i = 0; i < 8; i++) {
        int idx = tid + i * 256;
        wsm[idx >> 6][idx & 63] = Wp[idx];
    }
    if (tid < 32) bsm[tid] = Wbias[tid];
    __syncthreads();

    {
        int row = tid >> 1, half = tid & 1;
        uint4* zr = (uint4*)&zb[row][half * 32];
        uint4 u[4];
        float vv[32];
        float s = 0.f, s2 = 0.f;
        #pragma unroll
        for (int i = 0; i < 4; i++) {
            u[i] = zr[i];
            const __nv_bfloat162* p = (const __nv_bfloat162*)&u[i];
            #pragma unroll
            for (int w = 0; w < 4; w++) {
                float2 f = __bfloat1622float2(p[w]);
                vv[i * 8 + w * 2] = f.x; vv[i * 8 + w * 2 + 1] = f.y;
                s += f.x + f.y; s2 += f.x * f.x + f.y * f.y;
            }
        }
        s  += __shfl_xor_sync(0xffffffffu, s, 1);
        s2 += __shfl_xor_sync(0xffffffffu, s2, 1);
        float m = s * (1.f / 64.f);
        float rs = rsqrtf(s2 * (1.f / 64.f) - m * m + 1e-5f);
        #pragma unroll
        for (int i = 0; i < 4; i++) {
            __nv_bfloat162* p = (__nv_bfloat162*)&u[i];
            #pragma unroll
            for (int w = 0; w < 4; w++)
                p[w] = __floats2bfloat162_rn((vv[i * 8 + w * 2] - m) * rs,
                                             (vv[i * 8 + w * 2 + 1] - m) * rs);
            zr[i] = u[i];
        }
    }
    __syncthreads();

    int w = tid >> 5, lane = tid & 31, qr = lane >> 2, qc = lane & 3;
    float acc[4][4] = {};
    const uint32_t* zw = (const uint32_t*)&zb[0][0];
    const uint32_t* ww = (const uint32_t*)&wsm[0][0];
    #pragma unroll
    for (int kc = 0; kc < 4; kc++) {
        uint32_t af[4];
        int r = w * 16 + qr;
        af[0] = zw[r * 36 + kc * 8 + qc];
        af[1] = zw[(r + 8) * 36 + kc * 8 + qc];
        af[2] = zw[r * 36 + kc * 8 + 4 + qc];
        af[3] = zw[(r + 8) * 36 + kc * 8 + 4 + qc];
        #pragma unroll
        for (int j = 0; j < 4; j++) {
            int n = j * 8 + qr;
            mma_bf16(acc[j], af, ww[n * 36 + kc * 8 + qc], ww[n * 36 + kc * 8 + 4 + qc]);
        }
    }
    #pragma unroll
    for (int j = 0; j < 4; j++) {
        #pragma unroll
        for (int e = 0; e < 4; e++) {
            int mm = w * 16 + qr + ((e >= 2) ? 8 : 0);
            int n = j * 8 + 2 * qc + (e & 1);
            sOut[n][mm] = __float2bfloat16_rn(acc[j][e] + bsm[n]);
        }
    }
    __syncthreads();
    long long rg0 = (long long)blockIdx.x * 128;
    #pragma unroll
    for (int it = 0; it < 2; it++) {
        int lh = tid >> 3, part = (tid & 7) + it * 8;
        uint4 v = *(const uint4*)&sOut[lh][part * 8];
        __nv_bfloat16* dst = ((lh < 16) ? b0 : b1) +
                             (long long)(lh & 15) * S2_ + rg0 + part * 8;
        *(uint4*)dst = v;
    }
}

// ---------------------------------------------------------------------------
// Fused scores+softmax+Vt: per block = (head, 128 k-rows r) x all 1024 t.
// Pt[h][t][r] = exp(q[h,t]·k[h,r]/48 + bias)  (transposed, unnormalized)
// Vt[h][c][r] = v[h][r][c] / rowsum[r]        (transposed, scaled)
// ---------------------------------------------------------------------------
__global__ void __launch_bounds__(256) attn_sm_kernel(
    const __nv_bfloat16* __restrict__ kvg,
    const __nv_bfloat16* __restrict__ q,
    const __nv_bfloat16* __restrict__ bias,
    __nv_bfloat16* __restrict__ Pt,
    __nv_bfloat16* __restrict__ vt) {
    const int h = blockIdx.y;
    const int bm = blockIdx.x * 128;
    const int tid = threadIdx.x, lane = tid & 31, warp = tid >> 5;
    const int wm = warp >> 1, wn = warp & 1;
    const int qr = lane >> 2, qc = lane & 3;

    extern __shared__ char smraw[];
    __nv_bfloat16* Ks  = (__nv_bfloat16*)smraw;            // [128][56]
    __nv_bfloat16* Qs  = Ks + 128 * 56;                    // [2][64][56]
    __nv_bfloat16* Bsm = Qs + 2 * 64 * 56;                 // [2][128][72]
    __nv_bfloat16* sP  = Bsm + 2 * 128 * 72;               // [64][136]
    __shared__ float rs[128];

    const __nv_bfloat16* kbase = kvg + (long long)h * S_ * C3_;
    for (int id = tid; id < 128 * 24; id += 256) {
        int r = id / 24, c2 = id % 24;
        *(__nv_bfloat162*)&Ks[r * 56 + c2 * 2] =
            *(const __nv_bfloat162*)&kbase[(long long)(bm + r) * C3_ + c2 * 2];
    }
    if (tid < 128) rs[tid] = 0.f;

    const __nv_bfloat16* qbase = q + (long long)h * S_ * CH_;
    const __nv_bfloat16* bbase = bias + (long long)h * S2_;
    __nv_bfloat16* ptbase = Pt + (long long)h * S2_;
    uint32_t qS = (uint32_t)__cvta_generic_to_shared(Qs);
    uint32_t bS = (uint32_t)__cvta_generic_to_shared(Bsm);

    auto issue = [&](int st, int tc) {
        if (tid < 192) {
            int t = tid / 3, seg = tid % 3;
            cp16(qS + st * 64 * 112 + t * 112 + seg * 16,
                 qbase + (long long)(tc * 64 + t) * CH_ + seg * 8, 16);
        }
        #pragma unroll
        for (int i = 0; i < 4; i++) {
            int id = tid + i * 256;
            int r = id >> 3, seg = id & 7;
            cp16(bS + st * 128 * 144 + r * 144 + seg * 16,
                 bbase + (long long)(bm + r) * S_ + tc * 64 + seg * 8, 16);
        }
    };

    float rowacc[2][2] = {};
    issue(0, 0);
    CP_COMMIT();

    for (int tc = 0; tc < 16; tc++) {
        asm volatile("cp.async.wait_group 0;\n" ::);
        __syncthreads();
        if (tc + 1 < 16) issue((tc + 1) & 1, tc + 1);
        CP_COMMIT();
        int st = tc & 1;
        float acc[2][4][4] = {};
        #pragma unroll
        for (int ks = 0; ks < 3; ks++) {
            uint32_t af[2][4];
            #pragma unroll
            for (int i = 0; i < 2; i++) {
                int r = wm * 32 + i * 16 + qr;
                const uint32_t* a0 = (const uint32_t*)&Ks[r * 56];
                const uint32_t* a8 = (const uint32_t*)&Ks[(r + 8) * 56];
                af[i][0] = a0[ks * 8 + qc];
                af[i][1] = a8[ks * 8 + qc];
                af[i][2] = a0[ks * 8 + 4 + qc];
                af[i][3] = a8[ks * 8 + 4 + qc];
            }
            #pragma unroll
            for (int j = 0; j < 4; j++) {
                int n = wn * 32 + j * 8 + qr;
                const uint32_t* br = (const uint32_t*)&Qs[st * 64 * 56 + n * 56];
                uint32_t b0 = br[ks * 8 + qc];
                uint32_t b1 = br[ks * 8 + 4 + qc];
                #pragma unroll
                for (int i = 0; i < 2; i++) mma_bf16(acc[i][j], af[i], b0, b1);
            }
        }
        #pragma unroll
        for (int i = 0; i < 2; i++) {
            #pragma unroll
            for (int eh = 0; eh < 2; eh++) {
                int ml = wm * 32 + i * 16 + qr + eh * 8;
                const __nv_bfloat16* brow = &Bsm[st * 128 * 72 + ml * 72];
                float part = 0.f;
                #pragma unroll
                for (int j = 0; j < 4; j++) {
                    int nl = wn * 32 + j * 8 + 2 * qc;
                    __nv_bfloat162 bb = *(const __nv_bfloat162*)&brow[nl];
                    float v0 = acc[i][j][eh * 2 + 0] * (1.f / 48.f) + toF(bb.x);
                    float v1 = acc[i][j][eh * 2 + 1] * (1.f / 48.f) + toF(bb.y);
                    float e0 = __expf(v0), e1 = __expf(v1);
                    sP[nl * 136 + ml]       = __float2bfloat16_rn(e0);
                    sP[(nl + 1) * 136 + ml] = __float2bfloat16_rn(e1);
                    part += e0 + e1;
                }
                rowacc[i][eh] += part;
            }
        }
        __syncthreads();
        #pragma unroll
        for (int it = 0; it < 4; it++) {
            int id = tid + it * 256;
            int trow = id >> 4, chunk = id & 15;
            uint4 v = *(const uint4*)&sP[trow * 136 + chunk * 8];
            *(uint4*)&ptbase[(long long)(tc * 64 + trow) * S_ + bm + chunk * 8] = v;
        }
    }
    #pragma unroll
    for (int i = 0; i < 2; i++) {
        #pragma unroll
        for (int eh = 0; eh < 2; eh++) {
            float v = rowacc[i][eh];
            v += __shfl_xor_sync(0xffffffffu, v, 1);
            v += __shfl_xor_sync(0xffffffffu, v, 2);
            if (qc == 0) atomicAdd(&rs[wm * 32 + i * 16 + qr + eh * 8], v);
        }
    }
    __syncthreads();

    // ---- fused Vt: scale V rows by 1/rowsum, transpose, store ----
    {
        __nv_bfloat16* sv = sP;   // reuse staging (48x136 <= 64x136)
        const __nv_bfloat16* vbase = kvg + (long long)h * S_ * C3_ + CH_;
        for (int id = tid; id < 128 * 24; id += 256) {
            int r = id / 24, c2 = id % 24;
            __nv_bfloat162 v = *(const __nv_bfloat162*)&vbase[(long long)(bm + r) * C3_ + 2 * c2];
            float sc = 1.0f / rs[r];
            sv[(2 * c2) * 136 + r]     = __float2bfloat16_rn(toF(v.x) * sc);
            sv[(2 * c2 + 1) * 136 + r] = __float2bfloat16_rn(toF(v.y) * sc);
        }
        __syncthreads();
        for (int id = tid; id < 48 * 16; id += 256) {
            int c = id >> 4, chunk = id & 15;
            *(uint4*)&vt[(long long)h * CH_ * S_ + (long long)c * S_ + bm + chunk * 8] =
                *(const uint4*)&sv[c * 136 + chunk * 8];
        }
    }
}

// ---------------------------------------------------------------------------
// Tensor-core bf16 GEMM (NT):  C[m,n] = sum_k A[m,k] * B[n,k]
// cp.async multi-stage ring, one sync per k-chunk.
// Block tile 128x64, BK=32, 256 threads (8 warps, 4x2), warp tile 32x32.
// ---------------------------------------------------------------------------
enum { EPI_PLAIN = 0, EPI_GSIG = 2, EPI_ADALN = 5, EPI_GLU = 6,
       EPI_SPLIT = 7, EPI_SGATE = 8, EPI_MULT = 9, EPI_TRF2 = 10 };

template <int EPI, bool DUAL, typename OutT, typename AuxT>
__global__ void __launch_bounds__(256) gemm_tc(
    const __nv_bfloat16* __restrict__ A, const __nv_bfloat16* __restrict__ B1,
    const __nv_bfloat16* __restrict__ B2, const float* __restrict__ bias,
    const AuxT* __restrict__ aux, const float* __restrict__ aux2,
    OutT* __restrict__ Cp, OutT* __restrict__ Cp2,
    int M, int N, int K, int lda, int ldb, int ldc, int ldc2, int nsplit, int aux_ld,
    long long sA, long long sB, long long sC, long long sAux) {
    constexpr int NST = DUAL ? 2 : 3;
    const int tid = threadIdx.x;
    const int lane = tid & 31, warp = tid >> 5;
    const int wm = warp >> 1, wn = warp & 1;
    const int bm = blockIdx.y * 128, bn = blockIdx.x * 64;
    const int bz = blockIdx.z;
    A += bz * sA;
    B1 += bz * sB;
    if constexpr (DUAL) B2 += bz * sB;
    Cp += bz * sC;
    if (aux) aux += bz * sAux;

    __shared__ __nv_bfloat16 As[NST][128][40];
    __shared__ __nv_bfloat16 Bs1[NST][64][40];
    __shared__ __nv_bfloat16 Bs2[DUAL ? NST : 1][64][40];

    float acc1[2][4][4] = {};
    float acc2[2][4][4] = {};
    const int qr = lane >> 2, qc = lane & 3;
    const int nk = (K + 31) / 32;

    auto do_mma = [&](int st) {
        #pragma unroll
        for (int ks = 0; ks < 2; ks++) {
            uint32_t af[2][4];
            #pragma unroll
            for (int i = 0; i < 2; i++) {
                int r = wm * 32 + i * 16 + qr;
                const uint32_t* arow  = (const uint32_t*)&As[st][r][0];
                const uint32_t* arow8 = (const uint32_t*)&As[st][r + 8][0];
                af[i][0] = arow[ks * 8 + qc];
                af[i][1] = arow8[ks * 8 + qc];
                af[i][2] = arow[ks * 8 + 4 + qc];
                af[i][3] = arow8[ks * 8 + 4 + qc];
            }
            #pragma unroll
            for (int j = 0; j < 4; j++) {
                int n = wn * 32 + j * 8 + qr;
                const uint32_t* brow = (const uint32_t*)&Bs1[st][n][0];
                uint32_t b0 = brow[ks * 8 + qc];
                uint32_t b1 = brow[ks * 8 + 4 + qc];
                #pragma unroll
                for (int i = 0; i < 2; i++) mma_bf16(acc1[i][j], af[i], b0, b1);
                if constexpr (DUAL) {
                    const uint32_t* brow2 = (const uint32_t*)&Bs2[st][n][0];
                    uint32_t c0 = brow2[ks * 8 + qc];
                    uint32_t c1 = brow2[ks * 8 + 4 + qc];
                    #pragma unroll
                    for (int i = 0; i < 2; i++) mma_bf16(acc2[i][j], af[i], c0, c1);
                }
            }
        }
    };

    uint32_t aBase = (uint32_t)__cvta_generic_to_shared(&As[0][0][0]);
    uint32_t bBase = (uint32_t)__cvta_generic_to_shared(&Bs1[0][0][0]);
    uint32_t b2Base = 0;
    if constexpr (DUAL) b2Base = (uint32_t)__cvta_generic_to_shared(&Bs2[0][0][0]);

    auto issue = [&](int st, int k0) {
        #pragma unroll
        for (int i = 0; i < 2; i++) {
            int id = tid + i * 256;
            int r = id >> 2, cp4 = id & 3;
            int kk = k0 + cp4 * 8;
            const __nv_bfloat16* src = A + (long long)(bm + r) * lda + kk;
            int sb = (kk < K) ? 16 : 0;
            if (!sb) src = A;
            cp16(aBase + st * 128 * 80 + r * 80 + cp4 * 16, src, sb);
        }
        {
            int r = tid >> 2, cp4 = tid & 3;
            int kk = k0 + cp4 * 8;
            int sb = (kk < K) ? 16 : 0;
            const __nv_bfloat16* src = B1 + (long long)(bn + r) * ldb + kk;
            if (!sb) src = B1;
            cp16(bBase + st * 64 * 80 + r * 80 + cp4 * 16, src, sb);
            if constexpr (DUAL) {
                const __nv_bfloat16* src2 = B2 + (long long)(bn + r) * ldb + kk;
                if (!sb) src2 = B2;
                cp16(b2Base + st * 64 * 80 + r * 80 + cp4 * 16, src2, sb);
            }
        }
    };

    #pragma unroll
    for (int p = 0; p < NST - 1; p++) {
        if (p < nk) issue(p, p * 32);
        CP_COMMIT();
    }
    for (int ic = 0; ic < nk; ic++) {
        if constexpr (NST == 3) asm volatile("cp.async.wait_group 1;\n" ::);
        else                    asm volatile("cp.async.wait_group 0;\n" ::);
        __syncthreads();
        int pn = ic + NST - 1;
        if (pn < nk) issue(pn % NST, pn * 32);
        CP_COMMIT();
        do_mma(ic % NST);
    }

    // ---- epilogue ----
    #pragma unroll
    for (int i = 0; i < 2; i++) {
        #pragma unroll
        for (int j = 0; j < 4; j++) {
            int m0 = bm + wm * 32 + i * 16 + qr;
            int n0 = bn + wn * 32 + j * 8 + 2 * qc;
            #pragma unroll
            for (int e = 0; e < 4; e++) {
                int m = m0 + ((e >= 2) ? 8 : 0);
                int n = n0 + (e & 1);
                if (n >= N) continue;
                float v = acc1[i][j][e];
                if constexpr (EPI == EPI_PLAIN) {
                    storeOut(v + (bias ? bias[n] : 0.f), &Cp[(long long)m * ldc + n]);
                } else if constexpr (EPI == EPI_GSIG) {
                    storeOut(sigf(toF(aux[(long long)m * aux_ld + n])) * v,
                             &Cp[(long long)m * ldc + n]);
                } else if constexpr (EPI == EPI_ADALN) {
                    int na = (n >= CA_) ? n - CA_ : n;
                    storeOut(sigf((v + bias[n]) * toF(aux[(long long)m * aux_ld + na]) +
                                  acc2[i][j][e]),
                             &Cp[(long long)m * ldc + n]);
                } else if constexpr (EPI == EPI_GLU) {
                    storeOut(v * sigf(v) * acc2[i][j][e], &Cp[(long long)m * ldc + n]);
                } else if constexpr (EPI == EPI_SPLIT) {
                    float out = v + ((n < nsplit) ? bias[n] : 0.f);
                    if (n < nsplit) storeOut(out, &Cp[(long long)m * ldc + n]);
                    else            storeOut(out, &Cp2[(long long)m * ldc2 + (n - nsplit)]);
                } else if constexpr (EPI == EPI_SGATE) {
                    bool sg = (((bn / 768) & 1) == 0);
                    float out = v + bias[n];
                    storeOut(sg ? sigf(out) : out, &Cp[(long long)m * ldc + n]);
                } else if constexpr (EPI == EPI_MULT) {
                    storeOut(toF(aux[(long long)m * aux_ld + n]) * v,
                             &Cp[(long long)m * ldc + n]);
                } else {  // EPI_TRF2
                    storeOut(aux2[(long long)m * CA_ + n] +
                             sigf(toF(aux[(long long)m * aux_ld + n]) * v),
                             &Cp[(long long)m * ldc + n]);
                }
            }
        }
    }
}

// ---------------------------------------------------------------------------
// Host orchestration
// ---------------------------------------------------------------------------
extern "C" void kernel_launch(void* const* d_in, const int* in_sizes, int n_in,
                              void* d_out, int out_size) {
    const float* A0        = (const float*)d_in[0];
    const float* Sm        = (const float*)d_in[1];
    const float* Z         = (const float*)d_in[2];
    const float* attn_sn_w = (const float*)d_in[3];
    const float* attn_pb_w = (const float*)d_in[4];
    const float* attn_pb_b = (const float*)d_in[5];
    const float* attn_pnb_w= (const float*)d_in[6];
    const float* pair_w    = (const float*)d_in[7];
    const float* pair_b    = (const float*)d_in[8];
    const float* q_w       = (const float*)d_in[9];
    const float* q_b       = (const float*)d_in[10];
    const float* kvg_w     = (const float*)d_in[11];
    const float* bias_w    = (const float*)d_in[12];
    const float* bias_b    = (const float*)d_in[13];
    const float* ao_w      = (const float*)d_in[14];
    const float* out_w     = (const float*)d_in[15];
    const float* out_b     = (const float*)d_in[16];
    const float* tr_sn_w   = (const float*)d_in[17];
    const float* tr_pb_w   = (const float*)d_in[18];
    const float* tr_pb_b   = (const float*)d_in[19];
    const float* tr_pnb_w  = (const float*)d_in[20];
    const float* tr_a_w    = (const float*)d_in[21];
    const float* tr_s_w    = (const float*)d_in[22];
    const float* tr_s_b    = (const float*)d_in[23];
    const float* tr_b_w    = (const float*)d_in[24];
    float* OUT = (float*)d_out;

    float *an, *aout, *anew, *wbias, *sg, *adab, *sgb;
    __nv_bfloat16 *bb0, *bb1, *wbf, *shatb, *a23b, *qb, *kvgb, *obb, *bbb, *pbf, *vtb, *wpbf;
    cudaGetSymbolAddress((void**)&an, g_an);
    cudaGetSymbolAddress((void**)&aout, g_aout);
    cudaGetSymbolAddress((void**)&anew, g_anew);
    cudaGetSymbolAddress((void**)&wbias, g_wbias);
    cudaGetSymbolAddress((void**)&sg, g_sg);
    cudaGetSymbolAddress((void**)&adab, g_adab);
    cudaGetSymbolAddress((void**)&sgb, g_sgb);
    cudaGetSymbolAddress((void**)&bb0, g_bb0);
    cudaGetSymbolAddress((void**)&bb1, g_bb1);
    cudaGetSymbolAddress((void**)&wbf, g_wbf);
    cudaGetSymbolAddress((void**)&shatb, g_shatb);
    cudaGetSymbolAddress((void**)&a23b, g_a23b);
    cudaGetSymbolAddress((void**)&qb, g_qb);
    cudaGetSymbolAddress((void**)&kvgb, g_kvgb);
    cudaGetSymbolAddress((void**)&obb, g_obb);
    cudaGetSymbolAddress((void**)&bbb, g_bbb);
    cudaGetSymbolAddress((void**)&pbf, g_pbf);
    cudaGetSymbolAddress((void**)&vtb, g_vtb);
    cudaGetSymbolAddress((void**)&wpbf, g_wpbf);

    cudaFuncSetAttribute(attn_sm_kernel, cudaFuncAttributeMaxDynamicSharedMemorySize, 82944);

    // ---- conversion table; contiguity groups: [pb|tr_pb], [pnb|tr_pnb],
    //      [q|kvg], [out_w0|tr_s0|out_w1|tr_s1] ----
    CvtArgs ca;
    long long off = 0;
    int ns = 0;
    long long wo_ada1[2], wo_ada2[2], wo_q[2], wo_ao[2], wo_tra[2], wo_trb[2], wo_sg, wo_s;
    auto seg = [&](const float* s, int len, const float* sc) -> long long {
        ca.src[ns] = s; ca.scl[ns] = sc; ca.dst[ns] = wbf + off; ca.len[ns] = len;
        long long o = off; off += len; ns++; return o;
    };
    for (int l = 0; l < 2; l++) {
        wo_ada1[l] = seg(attn_pb_w  + (long long)l * CA_ * CS_, CA_ * CS_, attn_sn_w + l * CS_);
                     seg(tr_pb_w   + (long long)l * CA_ * CS_, CA_ * CS_, tr_sn_w + l * CS_);
        wo_ada2[l] = seg(attn_pnb_w + (long long)l * CA_ * CS_, CA_ * CS_, attn_sn_w + l * CS_);
                     seg(tr_pnb_w  + (long long)l * CA_ * CS_, CA_ * CS_, tr_sn_w + l * CS_);
        wo_q[l]    = seg(q_w   + (long long)l * CA_ * CA_, CA_ * CA_, nullptr);
                     seg(kvg_w + (long long)l * 3 * CA_ * CA_, 3 * CA_ * CA_, nullptr);
        wo_ao[l]   = seg(ao_w  + (long long)l * CA_ * CA_, CA_ * CA_, nullptr);
        wo_tra[l]  = seg(tr_a_w + (long long)l * 4 * CA_ * CA_, 4 * CA_ * CA_, nullptr);
        wo_trb[l]  = seg(tr_b_w + (long long)l * 2 * CA_ * CA_, 2 * CA_ * CA_, nullptr);
    }
    wo_sg = seg(out_w, CA_ * CS_, nullptr);
            seg(tr_s_w, CA_ * CS_, nullptr);
            seg(out_w + (long long)CA_ * CS_, CA_ * CS_, nullptr);
            seg(tr_s_w + (long long)CA_ * CS_, CA_ * CS_, nullptr);
    wo_s = seg(Sm, S_ * CS_, nullptr);
    ca.smod = CS_;
    ca.nseg = ns;

    cvt_kernel<<<dim3(128, ns), 256>>>(ca);
    bias_prep<<<24, 256>>>(attn_pb_b, tr_pb_b, out_b, tr_s_b, adab, sgb);
    ln_kernel<__nv_bfloat16><<<S_ / 8, 256>>>(Sm, shatb, CS_);
    zprep_kernel<<<1, 32>>>(pair_w, pair_b, bias_w, bias_b, wpbf, wbias);
    zproj_kernel<<<(S_ * S_) / 128, 256>>>(Z, wpbf, wbias, bb0, bb1);

    const __nv_bfloat16* s_bf = wbf + wo_s;

    // sgate: [og l0 | tg l0 | og l1 | tg l1]  (layer-independent)
    gemm_tc<EPI_SGATE, false, float, float><<<dim3(48, 8, 1), 256>>>(
        s_bf, wbf + wo_sg, nullptr, sgb, nullptr, nullptr, sg, nullptr,
        S_, 3072, CS_, CS_, CS_, 3072, 0, 0, 0, 0, 0, 0, 0);

    for (int l = 0; l < 2; l++) {
        const float* ain = l ? anew : A0;
        float* aoutp = l ? OUT : anew;
        const __nv_bfloat16* bbl = l ? bb1 : bb0;

        ln_kernel<float><<<S_ / 8, 256>>>(ain, an, CA_);

        // combined adaLN: a2|a3 = sigmoid((pb·sn+b)*an + pnb·sn), N=1536
        gemm_tc<EPI_ADALN, true, __nv_bfloat16, float><<<dim3(24, 8, 1), 256>>>(
            shatb, wbf + wo_ada1[l], wbf + wo_ada2[l], adab + (long long)l * 1536,
            an, nullptr, a23b, nullptr,
            S_, 1536, CS_, CS_, CS_, 1536, 0, 0, CA_, 0, 0, 0, 0);

        // combined q+kvg: N=3072, split epilogue -> qb / kvgb
        gemm_tc<EPI_SPLIT, false, __nv_bfloat16, float><<<dim3(48, 8, 1), 256>>>(
            a23b, wbf + wo_q[l], nullptr, q_b + (long long)l * CA_,
            nullptr, nullptr, qb, kvgb,
            S_, 3072, CA_, 1536, CA_, CA_, 3 * CA_, CA_, 0, 0, 0, 0, 0);

        // fused scores + softmax + Vt
        attn_sm_kernel<<<dim3(8, 16), 256, 82944>>>(kvgb, qb, bbl, pbf, vtb);

        // o[t,c] = sum_r Pt[t,r]*Vt[c,r];  fused sigmoid(g)*o
        gemm_tc<EPI_GSIG, false, __nv_bfloat16, __nv_bfloat16><<<dim3(1, 8, 16), 256>>>(
            pbf, vtb, nullptr, nullptr, kvgb + 2 * CH_, nullptr, obb, nullptr,
            S_, CH_, S_, S_, S_, CH_, 0, 0, C3_,
            (long long)S2_, (long long)CH_ * S_, (long long)S_ * CH_,
            (long long)S_ * C3_);

        // aout = og * ((sig(g)*o) @ ao_w^T)
        gemm_tc<EPI_MULT, false, float, float><<<dim3(12, 8, 1), 256>>>(
            obb, wbf + wo_ao[l], nullptr, nullptr, sg + (long long)l * 1536, nullptr,
            aout, nullptr,
            S_, CA_, CA_, CA_, CA_, CA_, 0, 0, 3072, 0, 0, 0, 0);

        // bb = silu(a3 @ W1^T) * (a3 @ W2^T)
        gemm_tc<EPI_GLU, true, __nv_bfloat16, float><<<dim3(24, 8, 1), 256>>>(
            a23b + CA_, wbf + wo_tra[l], wbf + wo_tra[l] + (long long)2 * CA_ * CA_, nullptr,
            nullptr, nullptr, bbb, nullptr,
            S_, 2 * CA_, CA_, 1536, CA_, 2 * CA_, 0, 0, 0, 0, 0, 0, 0);

        // a_next = aout + sigmoid(tg * (bb @ tr_b_w^T))
        gemm_tc<EPI_TRF2, false, float, float><<<dim3(12, 8, 1), 256>>>(
            bbb, wbf + wo_trb[l], nullptr, nullptr,
            sg + (long long)l * 1536 + CA_, aout, aoutp, nullptr,
            S_, CA_, 2 * CA_, 2 * CA_, 2 * CA_, CA_, 0, 0, 3072, 0, 0, 0, 0);
    }
}